// round 1
// baseline (speedup 1.0000x reference)
#include <cuda_runtime.h>
#include <math.h>

// ---------------- problem constants ----------------
#define BB    16
#define NN    1024
#define CC    512
#define LL    77
#define KVLEN 1101
#define NHH   8
#define HDD   64
#define CPG   16          // channels per group (512/32)
#define EPSV  1e-6f
#define NEGV  -1e10f

// ---------------- scratch (float offsets) ----------------
#define OFF_XQ   ((size_t)0)
#define OFF_XKV  ((size_t)8388608)
#define OFF_Q    ((size_t)16777216)
#define OFF_ATTN ((size_t)25165824)
#define OFF_T    ((size_t)33554432)
#define OFF_K    ((size_t)34185216)
#define OFF_V    ((size_t)43204608)
#define SCRATCH_FLOATS ((size_t)52224000)
__device__ float g_scratch[SCRATCH_FLOATS];

// =====================================================================
// GroupNorm over image x: one block per (b, g). Stats over 1024*16 elems,
// then writes BOTH x_q and x_kv normalized outputs (shared stats).
// =====================================================================
__global__ void gn_img_kernel(const float* __restrict__ x,
                              const float* __restrict__ qsc, const float* __restrict__ qbi,
                              const float* __restrict__ ksc, const float* __restrict__ kbi,
                              float* __restrict__ oq, float* __restrict__ okv)
{
    int b = blockIdx.x >> 5, g = blockIdx.x & 31;
    const float* xb = x + (size_t)b * NN * CC + g * CPG;
    int tid = threadIdx.x;

    float s = 0.f, s2 = 0.f;
    for (int e = tid; e < NN * 4; e += 256) {
        int n = e >> 2, c4 = (e & 3) << 2;
        float4 v = *(const float4*)(xb + (size_t)n * CC + c4);
        s  += v.x + v.y + v.z + v.w;
        s2 += v.x * v.x + v.y * v.y + v.z * v.z + v.w * v.w;
    }
    #pragma unroll
    for (int o2 = 16; o2; o2 >>= 1) {
        s  += __shfl_xor_sync(0xffffffffu, s,  o2);
        s2 += __shfl_xor_sync(0xffffffffu, s2, o2);
    }
    __shared__ float sh[8], sh2[8];
    int w = tid >> 5, lane = tid & 31;
    if (lane == 0) { sh[w] = s; sh2[w] = s2; }
    __syncthreads();

    __shared__ float cq[2][CPG], ck[2][CPG];
    if (tid < CPG) {
        float ts = 0.f, ts2 = 0.f;
        #pragma unroll
        for (int i = 0; i < 8; i++) { ts += sh[i]; ts2 += sh2[i]; }
        const float cnt = (float)(NN * CPG);
        float mu  = ts / cnt;
        float var = ts2 / cnt - mu * mu;
        float inv = rsqrtf(var + EPSV);
        int c = g * CPG + tid;
        float aq = inv * qsc[c];
        cq[0][tid] = aq;  cq[1][tid] = qbi[c] - mu * aq;
        float ak = inv * ksc[c];
        ck[0][tid] = ak;  ck[1][tid] = kbi[c] - mu * ak;
    }
    __syncthreads();

    float* oqb  = oq  + (size_t)b * NN * CC + g * CPG;
    float* okvb = okv + (size_t)b * NN * CC + g * CPG;
    for (int e = tid; e < NN * 4; e += 256) {
        int n = e >> 2, c4 = (e & 3) << 2;
        float4 v = *(const float4*)(xb + (size_t)n * CC + c4);
        float4 r;
        r.x = v.x * cq[0][c4+0] + cq[1][c4+0];
        r.y = v.y * cq[0][c4+1] + cq[1][c4+1];
        r.z = v.z * cq[0][c4+2] + cq[1][c4+2];
        r.w = v.w * cq[0][c4+3] + cq[1][c4+3];
        *(float4*)(oqb + (size_t)n * CC + c4) = r;
        r.x = v.x * ck[0][c4+0] + ck[1][c4+0];
        r.y = v.y * ck[0][c4+1] + ck[1][c4+1];
        r.z = v.z * ck[0][c4+2] + ck[1][c4+2];
        r.w = v.w * ck[0][c4+3] + ck[1][c4+3];
        *(float4*)(okvb + (size_t)n * CC + c4) = r;
    }
}

// =====================================================================
// GroupNorm over text: one block per (b, g), 128 threads, 77*16 elems.
// =====================================================================
__global__ void gn_txt_kernel(const float* __restrict__ t,
                              const float* __restrict__ tsc, const float* __restrict__ tbi,
                              float* __restrict__ ot)
{
    int b = blockIdx.x >> 5, g = blockIdx.x & 31;
    const float* xb = t + (size_t)b * LL * CC + g * CPG;
    int tid = threadIdx.x;

    float s = 0.f, s2 = 0.f;
    for (int e = tid; e < LL * 4; e += 128) {
        int n = e >> 2, c4 = (e & 3) << 2;
        float4 v = *(const float4*)(xb + (size_t)n * CC + c4);
        s  += v.x + v.y + v.z + v.w;
        s2 += v.x * v.x + v.y * v.y + v.z * v.z + v.w * v.w;
    }
    #pragma unroll
    for (int o2 = 16; o2; o2 >>= 1) {
        s  += __shfl_xor_sync(0xffffffffu, s,  o2);
        s2 += __shfl_xor_sync(0xffffffffu, s2, o2);
    }
    __shared__ float sh[4], sh2[4];
    int w = tid >> 5, lane = tid & 31;
    if (lane == 0) { sh[w] = s; sh2[w] = s2; }
    __syncthreads();

    __shared__ float ct[2][CPG];
    if (tid < CPG) {
        float ts = 0.f, ts2 = 0.f;
        #pragma unroll
        for (int i = 0; i < 4; i++) { ts += sh[i]; ts2 += sh2[i]; }
        const float cnt = (float)(LL * CPG);
        float mu  = ts / cnt;
        float var = ts2 / cnt - mu * mu;
        float inv = rsqrtf(var + EPSV);
        int c = g * CPG + tid;
        float a = inv * tsc[c];
        ct[0][tid] = a;  ct[1][tid] = tbi[c] - mu * a;
    }
    __syncthreads();

    float* ob = ot + (size_t)b * LL * CC + g * CPG;
    for (int e = tid; e < LL * 4; e += 128) {
        int n = e >> 2, c4 = (e & 3) << 2;
        float4 v = *(const float4*)(xb + (size_t)n * CC + c4);
        float4 r;
        r.x = v.x * ct[0][c4+0] + ct[1][c4+0];
        r.y = v.y * ct[0][c4+1] + ct[1][c4+1];
        r.z = v.z * ct[0][c4+2] + ct[1][c4+2];
        r.w = v.w * ct[0][c4+3] + ct[1][c4+3];
        *(float4*)(ob + (size_t)n * CC + c4) = r;
    }
}

// =====================================================================
// Generic SGEMM: Out[row-remapped] = alpha * A[M,512] @ W[512,512] (+Res)
// 64x64 block tile, 256 threads, 4x4 register tile, BK=16.
// Row remap: gm -> b*out_rows_per_b + out_off + (gm % rows_per_b)
// =====================================================================
__global__ void gemm512(const float* __restrict__ A, const float* __restrict__ W,
                        float* __restrict__ Out, const float* __restrict__ Res,
                        int M, int rows_per_b, int out_rows_per_b, int out_off,
                        float alpha)
{
    __shared__ float As[64][20];
    __shared__ float Bs[16][68];
    int tid = threadIdx.x;
    int tx = tid & 15, ty = tid >> 4;
    int m0 = blockIdx.x * 64, n0 = blockIdx.y * 64;

    float acc[4][4];
    #pragma unroll
    for (int mm = 0; mm < 4; mm++)
        #pragma unroll
        for (int nn = 0; nn < 4; nn++) acc[mm][nn] = 0.f;

    int ra = tid >> 2,  ka = (tid & 3) << 2;
    int kb = tid >> 4,  nb = (tid & 15) << 2;
    bool aok = (m0 + ra) < M;
    const float* Ap = A + (size_t)(m0 + ra) * 512 + ka;
    const float* Wp = W + (size_t)kb * 512 + n0 + nb;

    for (int k0 = 0; k0 < 512; k0 += 16) {
        float4 av = aok ? *(const float4*)(Ap + k0) : make_float4(0, 0, 0, 0);
        *(float4*)(&As[ra][ka]) = av;
        *(float4*)(&Bs[kb][nb]) = *(const float4*)(Wp + (size_t)k0 * 512);
        __syncthreads();
        #pragma unroll
        for (int k4 = 0; k4 < 16; k4 += 4) {
            float a_[4][4], b_[4][4];
            #pragma unroll
            for (int mm = 0; mm < 4; mm++)
                *(float4*)a_[mm] = *(const float4*)(&As[4 * ty + mm][k4]);
            #pragma unroll
            for (int kk = 0; kk < 4; kk++)
                *(float4*)b_[kk] = *(const float4*)(&Bs[k4 + kk][4 * tx]);
            #pragma unroll
            for (int mm = 0; mm < 4; mm++)
                #pragma unroll
                for (int nn = 0; nn < 4; nn++)
                    #pragma unroll
                    for (int kk = 0; kk < 4; kk++)
                        acc[mm][nn] += a_[mm][kk] * b_[kk][nn];
        }
        __syncthreads();
    }

    #pragma unroll
    for (int mm = 0; mm < 4; mm++) {
        int gm = m0 + 4 * ty + mm;
        if (gm < M) {
            int bbi = gm / rows_per_b;
            int rr  = gm - bbi * rows_per_b;
            size_t orow = (size_t)bbi * out_rows_per_b + out_off + rr;
            float4 r = make_float4(0, 0, 0, 0);
            if (Res) r = *(const float4*)(Res + orow * 512 + n0 + 4 * tx);
            float4 ov;
            ov.x = acc[mm][0] * alpha + r.x;
            ov.y = acc[mm][1] * alpha + r.y;
            ov.z = acc[mm][2] * alpha + r.z;
            ov.w = acc[mm][3] * alpha + r.w;
            *(float4*)(Out + orow * 512 + n0 + 4 * tx) = ov;
        }
    }
}

// =====================================================================
// Flash attention: one block per (q-tile of 64, head, batch).
// Q resident in smem; loop over 18 KV tiles of 64; online softmax.
// smem arrays row-major with stride 68 (float4-aligned, conflict-light).
// =====================================================================
#define AP 68
#define ATT_SMEM_BYTES ((4 * 64 * AP + 64) * 4)

__global__ void attn_kernel(const int* __restrict__ tmask,
                            const float* __restrict__ Qg,
                            const float* __restrict__ Kg,
                            const float* __restrict__ Vg,
                            float* __restrict__ Og)
{
    extern __shared__ float sm[];
    float* Qs = sm;
    float* Ks = Qs + 64 * AP;
    float* Vs = Ks + 64 * AP;
    float* Ps = Vs + 64 * AP;
    float* kmask = Ps + 64 * AP;

    int qt = blockIdx.x, h = blockIdx.y, b = blockIdx.z;
    int tid = threadIdx.x;
    int tx = tid & 15, ty = tid >> 4;

    const float* qb = Qg + (size_t)(b * NN + qt * 64) * CC + h * HDD;
    for (int e = tid; e < 64 * 16; e += 256) {
        int r = e >> 4, c4 = (e & 15) << 2;
        *(float4*)(Qs + r * AP + c4) = *(const float4*)(qb + (size_t)r * CC + c4);
    }
    float m_i[4], l_i[4], o[4][4];
    #pragma unroll
    for (int mm = 0; mm < 4; mm++) {
        m_i[mm] = -1e30f; l_i[mm] = 0.f;
        #pragma unroll
        for (int nn = 0; nn < 4; nn++) o[mm][nn] = 0.f;
    }
    const float* kb = Kg + (size_t)b * KVLEN * CC + h * HDD;
    const float* vb = Vg + (size_t)b * KVLEN * CC + h * HDD;
    const int* tm = tmask + b * LL;
    __syncthreads();

    for (int kv0 = 0; kv0 < KVLEN; kv0 += 64) {
        for (int e = tid; e < 64 * 16; e += 256) {
            int r = e >> 4, c4 = (e & 15) << 2;
            int kg = kv0 + r;
            float4 kv = make_float4(0, 0, 0, 0), vv = make_float4(0, 0, 0, 0);
            if (kg < KVLEN) {
                kv = *(const float4*)(kb + (size_t)kg * CC + c4);
                vv = *(const float4*)(vb + (size_t)kg * CC + c4);
            }
            *(float4*)(Ks + r * AP + c4) = kv;
            *(float4*)(Vs + r * AP + c4) = vv;
        }
        if (tid < 64) {
            int kg = kv0 + tid;
            float madd = 0.f;
            if (kg >= KVLEN) madd = NEGV;
            else if (kg >= NN && tm[kg - NN] == 0) madd = NEGV;
            kmask[tid] = madd;
        }
        __syncthreads();

        // S = Q K^T  (64x64)
        float s[4][4];
        #pragma unroll
        for (int mm = 0; mm < 4; mm++)
            #pragma unroll
            for (int nn = 0; nn < 4; nn++) s[mm][nn] = 0.f;
        #pragma unroll
        for (int d4 = 0; d4 < 64; d4 += 4) {
            float qa[4][4], kk_[4][4];
            #pragma unroll
            for (int mm = 0; mm < 4; mm++)
                *(float4*)qa[mm] = *(const float4*)(Qs + (4 * ty + mm) * AP + d4);
            #pragma unroll
            for (int nn = 0; nn < 4; nn++)
                *(float4*)kk_[nn] = *(const float4*)(Ks + (4 * tx + nn) * AP + d4);
            #pragma unroll
            for (int mm = 0; mm < 4; mm++)
                #pragma unroll
                for (int nn = 0; nn < 4; nn++)
                    #pragma unroll
                    for (int kk = 0; kk < 4; kk++)
                        s[mm][nn] += qa[mm][kk] * kk_[nn][kk];
        }

        // mask + online softmax (row reductions across tx = lane bits 0..3)
        #pragma unroll
        for (int mm = 0; mm < 4; mm++) {
            #pragma unroll
            for (int nn = 0; nn < 4; nn++) s[mm][nn] += kmask[4 * tx + nn];
            float t = fmaxf(fmaxf(s[mm][0], s[mm][1]), fmaxf(s[mm][2], s[mm][3]));
            #pragma unroll
            for (int off = 1; off < 16; off <<= 1)
                t = fmaxf(t, __shfl_xor_sync(0xffffffffu, t, off));
            float mnew  = fmaxf(m_i[mm], t);
            float alpha = __expf(m_i[mm] - mnew);
            m_i[mm] = mnew;
            float rs = 0.f;
            #pragma unroll
            for (int nn = 0; nn < 4; nn++) {
                s[mm][nn] = __expf(s[mm][nn] - mnew);
                rs += s[mm][nn];
            }
            #pragma unroll
            for (int off = 1; off < 16; off <<= 1)
                rs += __shfl_xor_sync(0xffffffffu, rs, off);
            l_i[mm] = l_i[mm] * alpha + rs;
            #pragma unroll
            for (int nn = 0; nn < 4; nn++) o[mm][nn] *= alpha;
        }
        #pragma unroll
        for (int mm = 0; mm < 4; mm++)
            *(float4*)(Ps + (4 * ty + mm) * AP + 4 * tx) =
                make_float4(s[mm][0], s[mm][1], s[mm][2], s[mm][3]);
        __syncthreads();

        // O += P V
        #pragma unroll
        for (int j4 = 0; j4 < 64; j4 += 4) {
            float pa[4][4], va[4][4];
            #pragma unroll
            for (int mm = 0; mm < 4; mm++)
                *(float4*)pa[mm] = *(const float4*)(Ps + (4 * ty + mm) * AP + j4);
            #pragma unroll
            for (int kk = 0; kk < 4; kk++)
                *(float4*)va[kk] = *(const float4*)(Vs + (j4 + kk) * AP + 4 * tx);
            #pragma unroll
            for (int mm = 0; mm < 4; mm++)
                #pragma unroll
                for (int nn = 0; nn < 4; nn++)
                    #pragma unroll
                    for (int kk = 0; kk < 4; kk++)
                        o[mm][nn] += pa[mm][kk] * va[kk][nn];
        }
        __syncthreads();
    }

    float* ob = Og + (size_t)(b * NN + qt * 64) * CC + h * HDD;
    #pragma unroll
    for (int mm = 0; mm < 4; mm++) {
        float inv = 1.f / l_i[mm];
        *(float4*)(ob + (size_t)(4 * ty + mm) * CC + 4 * tx) =
            make_float4(o[mm][0] * inv, o[mm][1] * inv, o[mm][2] * inv, o[mm][3] * inv);
    }
}

// =====================================================================
// launch
// =====================================================================
extern "C" void kernel_launch(void* const* d_in, const int* in_sizes, int n_in,
                              void* d_out, int out_size)
{
    const float* x    = (const float*)d_in[0];
    const float* te   = (const float*)d_in[1];
    const int*   tmk  = (const int*)  d_in[2];
    const float* gqs  = (const float*)d_in[3];
    const float* gqb  = (const float*)d_in[4];
    const float* gks  = (const float*)d_in[5];
    const float* gkb  = (const float*)d_in[6];
    const float* gts  = (const float*)d_in[7];
    const float* gtb  = (const float*)d_in[8];
    const float* Wq   = (const float*)d_in[9];
    const float* Wks  = (const float*)d_in[10];
    const float* Wvs  = (const float*)d_in[11];
    const float* Wkc  = (const float*)d_in[12];
    const float* Wvc  = (const float*)d_in[13];
    const float* Wout = (const float*)d_in[14];
    float* out = (float*)d_out;

    float* scratch = nullptr;
    cudaGetSymbolAddress((void**)&scratch, g_scratch);
    float* XQ   = scratch + OFF_XQ;
    float* XKV  = scratch + OFF_XKV;
    float* Qb   = scratch + OFF_Q;
    float* ATTb = scratch + OFF_ATTN;
    float* Tb   = scratch + OFF_T;
    float* Kb   = scratch + OFF_K;
    float* Vb   = scratch + OFF_V;

    gn_img_kernel<<<512, 256>>>(x, gqs, gqb, gks, gkb, XQ, XKV);
    gn_txt_kernel<<<512, 128>>>(te, gts, gtb, Tb);

    // projections (self parts write into concat positions of K/V)
    gemm512<<<dim3(256, 8), 256>>>(XQ,  Wq,  Qb, nullptr, 16384, 1024, 1024,  0, 0.125f);
    gemm512<<<dim3(256, 8), 256>>>(XKV, Wks, Kb, nullptr, 16384, 1024, KVLEN, 0, 1.f);
    gemm512<<<dim3(256, 8), 256>>>(XKV, Wvs, Vb, nullptr, 16384, 1024, KVLEN, 0, 1.f);
    gemm512<<<dim3(20, 8),  256>>>(Tb,  Wkc, Kb, nullptr, 1232,  77,   KVLEN, 1024, 1.f);
    gemm512<<<dim3(20, 8),  256>>>(Tb,  Wvc, Vb, nullptr, 1232,  77,   KVLEN, 1024, 1.f);

    cudaFuncSetAttribute(attn_kernel, cudaFuncAttributeMaxDynamicSharedMemorySize,
                         ATT_SMEM_BYTES);
    attn_kernel<<<dim3(16, NHH, BB), 256, ATT_SMEM_BYTES>>>(tmk, Qb, Kb, Vb, ATTb);

    // output projection + residual
    gemm512<<<dim3(256, 8), 256>>>(ATTb, Wout, out, x, 16384, 1024, 1024, 0, 1.f);
}

// round 2
// speedup vs baseline: 3.2759x; 3.2759x over previous
#include <cuda_runtime.h>
#include <math.h>

// ---------------- problem constants ----------------
#define BB    16
#define NN    1024
#define CC    512
#define LL    77
#define KVLEN 1101
#define NHH   8
#define HDD   64
#define CPG   16
#define EPSV  1e-6f
#define NEGV  -1e10f

// ---------------- scratch (float offsets) ----------------
#define OFF_XQ   ((size_t)0)
#define OFF_XKV  ((size_t)8388608)
#define OFF_Q    ((size_t)16777216)
#define OFF_ATTN ((size_t)25165824)
#define OFF_T    ((size_t)33554432)
#define OFF_K    ((size_t)34185216)
#define OFF_V    ((size_t)43204608)
#define SCRATCH_FLOATS ((size_t)52224000)
__device__ float g_scratch[SCRATCH_FLOATS];

// ---------------- tf32 helpers ----------------
__device__ __forceinline__ unsigned f2tf(float x) {
    unsigned r; asm("cvt.rna.tf32.f32 %0, %1;" : "=r"(r) : "f"(x)); return r;
}
__device__ __forceinline__ uint4 f2tf4(float4 v) {
    uint4 r; r.x = f2tf(v.x); r.y = f2tf(v.y); r.z = f2tf(v.z); r.w = f2tf(v.w); return r;
}
__device__ __forceinline__ void mma8(float* c, const unsigned* a, const unsigned* b) {
    asm volatile(
        "mma.sync.aligned.m16n8k8.row.col.f32.tf32.tf32.f32 "
        "{%0,%1,%2,%3},{%4,%5,%6,%7},{%8,%9},{%0,%1,%2,%3};\n"
        : "+f"(c[0]), "+f"(c[1]), "+f"(c[2]), "+f"(c[3])
        : "r"(a[0]), "r"(a[1]), "r"(a[2]), "r"(a[3]), "r"(b[0]), "r"(b[1]));
}

// =====================================================================
// GroupNorm over image: one block per (b, g); writes both x_q and x_kv.
// =====================================================================
__global__ void gn_img_kernel(const float* __restrict__ x,
                              const float* __restrict__ qsc, const float* __restrict__ qbi,
                              const float* __restrict__ ksc, const float* __restrict__ kbi,
                              float* __restrict__ oq, float* __restrict__ okv)
{
    int b = blockIdx.x >> 5, g = blockIdx.x & 31;
    const float* xb = x + (size_t)b * NN * CC + g * CPG;
    int tid = threadIdx.x;

    float s = 0.f, s2 = 0.f;
    for (int e = tid; e < NN * 4; e += 256) {
        int n = e >> 2, c4 = (e & 3) << 2;
        float4 v = *(const float4*)(xb + (size_t)n * CC + c4);
        s  += v.x + v.y + v.z + v.w;
        s2 += v.x * v.x + v.y * v.y + v.z * v.z + v.w * v.w;
    }
    #pragma unroll
    for (int o2 = 16; o2; o2 >>= 1) {
        s  += __shfl_xor_sync(0xffffffffu, s,  o2);
        s2 += __shfl_xor_sync(0xffffffffu, s2, o2);
    }
    __shared__ float sh[8], sh2[8];
    int w = tid >> 5, lane = tid & 31;
    if (lane == 0) { sh[w] = s; sh2[w] = s2; }
    __syncthreads();

    __shared__ float cq[2][CPG], ck[2][CPG];
    if (tid < CPG) {
        float ts = 0.f, ts2 = 0.f;
        #pragma unroll
        for (int i = 0; i < 8; i++) { ts += sh[i]; ts2 += sh2[i]; }
        const float cnt = (float)(NN * CPG);
        float mu  = ts / cnt;
        float var = ts2 / cnt - mu * mu;
        float inv = rsqrtf(var + EPSV);
        int c = g * CPG + tid;
        float aq = inv * qsc[c];
        cq[0][tid] = aq;  cq[1][tid] = qbi[c] - mu * aq;
        float ak = inv * ksc[c];
        ck[0][tid] = ak;  ck[1][tid] = kbi[c] - mu * ak;
    }
    __syncthreads();

    float* oqb  = oq  + (size_t)b * NN * CC + g * CPG;
    float* okvb = okv + (size_t)b * NN * CC + g * CPG;
    for (int e = tid; e < NN * 4; e += 256) {
        int n = e >> 2, c4 = (e & 3) << 2;
        float4 v = *(const float4*)(xb + (size_t)n * CC + c4);
        float4 r;
        r.x = v.x * cq[0][c4+0] + cq[1][c4+0];
        r.y = v.y * cq[0][c4+1] + cq[1][c4+1];
        r.z = v.z * cq[0][c4+2] + cq[1][c4+2];
        r.w = v.w * cq[0][c4+3] + cq[1][c4+3];
        *(float4*)(oqb + (size_t)n * CC + c4) = r;
        r.x = v.x * ck[0][c4+0] + ck[1][c4+0];
        r.y = v.y * ck[0][c4+1] + ck[1][c4+1];
        r.z = v.z * ck[0][c4+2] + ck[1][c4+2];
        r.w = v.w * ck[0][c4+3] + ck[1][c4+3];
        *(float4*)(okvb + (size_t)n * CC + c4) = r;
    }
}

// =====================================================================
// GroupNorm over text
// =====================================================================
__global__ void gn_txt_kernel(const float* __restrict__ t,
                              const float* __restrict__ tsc, const float* __restrict__ tbi,
                              float* __restrict__ ot)
{
    int b = blockIdx.x >> 5, g = blockIdx.x & 31;
    const float* xb = t + (size_t)b * LL * CC + g * CPG;
    int tid = threadIdx.x;

    float s = 0.f, s2 = 0.f;
    for (int e = tid; e < LL * 4; e += 128) {
        int n = e >> 2, c4 = (e & 3) << 2;
        float4 v = *(const float4*)(xb + (size_t)n * CC + c4);
        s  += v.x + v.y + v.z + v.w;
        s2 += v.x * v.x + v.y * v.y + v.z * v.z + v.w * v.w;
    }
    #pragma unroll
    for (int o2 = 16; o2; o2 >>= 1) {
        s  += __shfl_xor_sync(0xffffffffu, s,  o2);
        s2 += __shfl_xor_sync(0xffffffffu, s2, o2);
    }
    __shared__ float sh[4], sh2[4];
    int w = tid >> 5, lane = tid & 31;
    if (lane == 0) { sh[w] = s; sh2[w] = s2; }
    __syncthreads();

    __shared__ float ct[2][CPG];
    if (tid < CPG) {
        float ts = 0.f, ts2 = 0.f;
        #pragma unroll
        for (int i = 0; i < 4; i++) { ts += sh[i]; ts2 += sh2[i]; }
        const float cnt = (float)(LL * CPG);
        float mu  = ts / cnt;
        float var = ts2 / cnt - mu * mu;
        float inv = rsqrtf(var + EPSV);
        int c = g * CPG + tid;
        float a = inv * tsc[c];
        ct[0][tid] = a;  ct[1][tid] = tbi[c] - mu * a;
    }
    __syncthreads();

    float* ob = ot + (size_t)b * LL * CC + g * CPG;
    for (int e = tid; e < LL * 4; e += 128) {
        int n = e >> 2, c4 = (e & 3) << 2;
        float4 v = *(const float4*)(xb + (size_t)n * CC + c4);
        float4 r;
        r.x = v.x * ct[0][c4+0] + ct[1][c4+0];
        r.y = v.y * ct[0][c4+1] + ct[1][c4+1];
        r.z = v.z * ct[0][c4+2] + ct[1][c4+2];
        r.w = v.w * ct[0][c4+3] + ct[1][c4+3];
        *(float4*)(ob + (size_t)n * CC + c4) = r;
    }
}

// =====================================================================
// TF32 tensor-core GEMM: Out[remap(rows)] = alpha * A[M,512] @ W[512,512] (+Res)
// Block tile 128x128, BK=16, 256 threads (8 warps, 64x32 warp tiles).
// =====================================================================
__global__ void gemm512_tc(const float* __restrict__ A, const float* __restrict__ W,
                           float* __restrict__ Out, const float* __restrict__ Res,
                           int M, int rows_per_b, int out_rows_per_b, int out_off,
                           float alpha)
{
    __shared__ unsigned As[128][20];   // [m][k], stride 20: conflict-free frag reads
    __shared__ unsigned Bs[16][132];   // [k][n], stride 132: coalesced fills

    int tid = threadIdx.x;
    int warp = tid >> 5, lane = tid & 31;
    int g = lane >> 2, tg = lane & 3;
    int wm = (warp >> 2) * 64, wn = (warp & 3) * 32;
    int m0 = blockIdx.x * 128, n0 = blockIdx.y * 128;

    float acc[4][4][4];
    #pragma unroll
    for (int i = 0; i < 4; i++)
        #pragma unroll
        for (int j = 0; j < 4; j++)
            #pragma unroll
            for (int q = 0; q < 4; q++) acc[i][j][q] = 0.f;

    int ar = tid >> 2, ak4 = (tid & 3) << 2;           // A fill: rows ar, ar+64
    int bk = tid >> 5, bn4 = (tid & 31) << 2;          // B fill: rows bk, bk+8
    bool aok0 = (m0 + ar) < M;
    bool aok1 = (m0 + 64 + ar) < M;
    const float* Ap0 = A + (size_t)(m0 + ar) * 512 + ak4;
    const float* Ap1 = A + (size_t)(m0 + 64 + ar) * 512 + ak4;
    const float* Wp0 = W + (size_t)bk * 512 + n0 + bn4;
    const float* Wp1 = W + (size_t)(bk + 8) * 512 + n0 + bn4;

    for (int k0 = 0; k0 < 512; k0 += 16) {
        float4 a0 = aok0 ? *(const float4*)(Ap0 + k0) : make_float4(0, 0, 0, 0);
        float4 a1 = aok1 ? *(const float4*)(Ap1 + k0) : make_float4(0, 0, 0, 0);
        float4 b0 = *(const float4*)(Wp0 + (size_t)k0 * 512);
        float4 b1 = *(const float4*)(Wp1 + (size_t)k0 * 512);
        __syncthreads();
        *(uint4*)(&As[ar][ak4])      = f2tf4(a0);
        *(uint4*)(&As[ar + 64][ak4]) = f2tf4(a1);
        *(uint4*)(&Bs[bk][bn4])      = f2tf4(b0);
        *(uint4*)(&Bs[bk + 8][bn4])  = f2tf4(b1);
        __syncthreads();

        #pragma unroll
        for (int ks = 0; ks < 16; ks += 8) {
            unsigned af[4][4], bf[4][2];
            #pragma unroll
            for (int i = 0; i < 4; i++) {
                int r = wm + i * 16 + g;
                af[i][0] = As[r][ks + tg];
                af[i][1] = As[r + 8][ks + tg];
                af[i][2] = As[r][ks + tg + 4];
                af[i][3] = As[r + 8][ks + tg + 4];
            }
            #pragma unroll
            for (int j = 0; j < 4; j++) {
                bf[j][0] = Bs[ks + tg][wn + j * 8 + g];
                bf[j][1] = Bs[ks + tg + 4][wn + j * 8 + g];
            }
            #pragma unroll
            for (int i = 0; i < 4; i++)
                #pragma unroll
                for (int j = 0; j < 4; j++)
                    mma8(acc[i][j], af[i], bf[j]);
        }
    }

    // epilogue
    #pragma unroll
    for (int i = 0; i < 4; i++) {
        #pragma unroll
        for (int rsel = 0; rsel < 2; rsel++) {
            int gm = m0 + wm + i * 16 + g + rsel * 8;
            if (gm >= M) continue;
            int bbi = gm / rows_per_b;
            int rr  = gm - bbi * rows_per_b;
            size_t orow = (size_t)bbi * out_rows_per_b + out_off + rr;
            #pragma unroll
            for (int j = 0; j < 4; j++) {
                int col = n0 + wn + j * 8 + 2 * tg;
                float v0 = acc[i][j][rsel * 2 + 0] * alpha;
                float v1 = acc[i][j][rsel * 2 + 1] * alpha;
                if (Res) {
                    float2 r = *(const float2*)(Res + orow * 512 + col);
                    v0 += r.x; v1 += r.y;
                }
                *(float2*)(Out + orow * 512 + col) = make_float2(v0, v1);
            }
        }
    }
}

// =====================================================================
// TF32 tensor-core flash attention: block = (128-q-tile, head, batch),
// 4 warps x 32 q-rows. KV tiles of 64, online softmax on mma fragments.
// =====================================================================
#define ATS 68
#define ATT_SMEM_BYTES ((384 * ATS) * 4 + 64 * 4)

__global__ void attn_tc(const int* __restrict__ tmask,
                        const float* __restrict__ Qg,
                        const float* __restrict__ Kg,
                        const float* __restrict__ Vg,
                        float* __restrict__ Og)
{
    extern __shared__ unsigned smb[];
    unsigned* Qs = smb;               // [128][ATS]
    unsigned* Ks = Qs + 128 * ATS;    // [64][ATS]
    unsigned* Vs = Ks + 64 * ATS;     // [64][ATS]
    unsigned* Ps = Vs + 64 * ATS;     // [128][ATS]
    float* kmask = (float*)(Ps + 128 * ATS);

    int qt = blockIdx.x, h = blockIdx.y, b = blockIdx.z;
    int tid = threadIdx.x, warp = tid >> 5, lane = tid & 31;
    int g = lane >> 2, tg = lane & 3;
    int wm = warp * 32;

    // load Q tile (128 x 64), convert to tf32
    const float* qb = Qg + (size_t)(b * NN + qt * 128) * CC + h * HDD;
    #pragma unroll
    for (int i = 0; i < 16; i++) {
        int idx = tid + i * 128;
        int r = idx >> 4, c4 = (idx & 15) << 2;
        float4 v = *(const float4*)(qb + (size_t)r * CC + c4);
        *(uint4*)(Qs + r * ATS + c4) = f2tf4(v);
    }

    float m_i[4], l_i[4], o[2][8][4];
    #pragma unroll
    for (int q = 0; q < 4; q++) { m_i[q] = -1e30f; l_i[q] = 0.f; }
    #pragma unroll
    for (int mt = 0; mt < 2; mt++)
        #pragma unroll
        for (int j = 0; j < 8; j++)
            #pragma unroll
            for (int q = 0; q < 4; q++) o[mt][j][q] = 0.f;

    const float* kb = Kg + (size_t)b * KVLEN * CC + h * HDD;
    const float* vb = Vg + (size_t)b * KVLEN * CC + h * HDD;
    const int* tm = tmask + b * LL;

    for (int kv0 = 0; kv0 < KVLEN; kv0 += 64) {
        __syncthreads();   // protect Ks/Vs (and initial Qs) across iterations
        #pragma unroll
        for (int i = 0; i < 8; i++) {
            int idx = tid + i * 128;
            int r = idx >> 4, c4 = (idx & 15) << 2;
            int kg = kv0 + r;
            float4 kv = make_float4(0, 0, 0, 0), vv = make_float4(0, 0, 0, 0);
            if (kg < KVLEN) {
                kv = *(const float4*)(kb + (size_t)kg * CC + c4);
                vv = *(const float4*)(vb + (size_t)kg * CC + c4);
            }
            *(uint4*)(Ks + r * ATS + c4) = f2tf4(kv);
            *(uint4*)(Vs + r * ATS + c4) = f2tf4(vv);
        }
        if (tid < 64) {
            int kg = kv0 + tid;
            float madd = 0.f;
            if (kg >= KVLEN) madd = NEGV;
            else if (kg >= NN && tm[kg - NN] == 0) madd = NEGV;
            kmask[tid] = madd;
        }
        __syncthreads();

        // ---- S = Q K^T ----
        float s[2][8][4];
        #pragma unroll
        for (int mt = 0; mt < 2; mt++)
            #pragma unroll
            for (int j = 0; j < 8; j++)
                #pragma unroll
                for (int q = 0; q < 4; q++) s[mt][j][q] = 0.f;

        #pragma unroll
        for (int d0 = 0; d0 < 64; d0 += 8) {
            unsigned aq[2][4];
            #pragma unroll
            for (int mt = 0; mt < 2; mt++) {
                int r = wm + mt * 16 + g;
                aq[mt][0] = Qs[r * ATS + d0 + tg];
                aq[mt][1] = Qs[(r + 8) * ATS + d0 + tg];
                aq[mt][2] = Qs[r * ATS + d0 + tg + 4];
                aq[mt][3] = Qs[(r + 8) * ATS + d0 + tg + 4];
            }
            #pragma unroll
            for (int j = 0; j < 8; j++) {
                unsigned bk[2];
                bk[0] = Ks[(j * 8 + g) * ATS + d0 + tg];
                bk[1] = Ks[(j * 8 + g) * ATS + d0 + tg + 4];
                mma8(s[0][j], aq[0], bk);
                mma8(s[1][j], aq[1], bk);
            }
        }

        // ---- mask + online softmax on fragments ----
        #pragma unroll
        for (int mt = 0; mt < 2; mt++) {
            #pragma unroll
            for (int j = 0; j < 8; j++) {
                float km0 = kmask[j * 8 + 2 * tg];
                float km1 = kmask[j * 8 + 2 * tg + 1];
                s[mt][j][0] += km0; s[mt][j][1] += km1;
                s[mt][j][2] += km0; s[mt][j][3] += km1;
            }
            float mx0 = -1e30f, mx1 = -1e30f;
            #pragma unroll
            for (int j = 0; j < 8; j++) {
                mx0 = fmaxf(mx0, fmaxf(s[mt][j][0], s[mt][j][1]));
                mx1 = fmaxf(mx1, fmaxf(s[mt][j][2], s[mt][j][3]));
            }
            mx0 = fmaxf(mx0, __shfl_xor_sync(0xffffffffu, mx0, 1));
            mx0 = fmaxf(mx0, __shfl_xor_sync(0xffffffffu, mx0, 2));
            mx1 = fmaxf(mx1, __shfl_xor_sync(0xffffffffu, mx1, 1));
            mx1 = fmaxf(mx1, __shfl_xor_sync(0xffffffffu, mx1, 2));
            int i0 = mt * 2, i1 = mt * 2 + 1;
            float mn0 = fmaxf(m_i[i0], mx0), mn1 = fmaxf(m_i[i1], mx1);
            float al0 = __expf(m_i[i0] - mn0), al1 = __expf(m_i[i1] - mn1);
            m_i[i0] = mn0; m_i[i1] = mn1;
            float sum0 = 0.f, sum1 = 0.f;
            int r = wm + mt * 16 + g;
            #pragma unroll
            for (int j = 0; j < 8; j++) {
                float p0 = __expf(s[mt][j][0] - mn0);
                float p1 = __expf(s[mt][j][1] - mn0);
                float p2 = __expf(s[mt][j][2] - mn1);
                float p3 = __expf(s[mt][j][3] - mn1);
                sum0 += p0 + p1; sum1 += p2 + p3;
                uint2 u0; u0.x = f2tf(p0); u0.y = f2tf(p1);
                uint2 u1; u1.x = f2tf(p2); u1.y = f2tf(p3);
                *(uint2*)(Ps + r * ATS + j * 8 + 2 * tg) = u0;
                *(uint2*)(Ps + (r + 8) * ATS + j * 8 + 2 * tg) = u1;
            }
            sum0 += __shfl_xor_sync(0xffffffffu, sum0, 1);
            sum0 += __shfl_xor_sync(0xffffffffu, sum0, 2);
            sum1 += __shfl_xor_sync(0xffffffffu, sum1, 1);
            sum1 += __shfl_xor_sync(0xffffffffu, sum1, 2);
            l_i[i0] = l_i[i0] * al0 + sum0;
            l_i[i1] = l_i[i1] * al1 + sum1;
            #pragma unroll
            for (int j = 0; j < 8; j++) {
                o[mt][j][0] *= al0; o[mt][j][1] *= al0;
                o[mt][j][2] *= al1; o[mt][j][3] *= al1;
            }
        }
        __syncwarp();

        // ---- O += P V ----
        #pragma unroll
        for (int k0 = 0; k0 < 64; k0 += 8) {
            unsigned ap[2][4];
            #pragma unroll
            for (int mt = 0; mt < 2; mt++) {
                int r = wm + mt * 16 + g;
                ap[mt][0] = Ps[r * ATS + k0 + tg];
                ap[mt][1] = Ps[(r + 8) * ATS + k0 + tg];
                ap[mt][2] = Ps[r * ATS + k0 + tg + 4];
                ap[mt][3] = Ps[(r + 8) * ATS + k0 + tg + 4];
            }
            #pragma unroll
            for (int j = 0; j < 8; j++) {
                unsigned bv[2];
                bv[0] = Vs[(k0 + tg) * ATS + j * 8 + g];
                bv[1] = Vs[(k0 + tg + 4) * ATS + j * 8 + g];
                mma8(o[0][j], ap[0], bv);
                mma8(o[1][j], ap[1], bv);
            }
        }
    }

    // ---- write O / l ----
    float* ob = Og + (size_t)(b * NN + qt * 128) * CC + h * HDD;
    #pragma unroll
    for (int mt = 0; mt < 2; mt++) {
        #pragma unroll
        for (int rsel = 0; rsel < 2; rsel++) {
            int r = wm + mt * 16 + g + rsel * 8;
            float inv = 1.f / l_i[mt * 2 + rsel];
            #pragma unroll
            for (int j = 0; j < 8; j++) {
                int col = j * 8 + 2 * tg;
                float v0 = o[mt][j][rsel * 2 + 0] * inv;
                float v1 = o[mt][j][rsel * 2 + 1] * inv;
                *(float2*)(ob + (size_t)r * CC + col) = make_float2(v0, v1);
            }
        }
    }
}

// =====================================================================
// launch
// =====================================================================
extern "C" void kernel_launch(void* const* d_in, const int* in_sizes, int n_in,
                              void* d_out, int out_size)
{
    const float* x    = (const float*)d_in[0];
    const float* te   = (const float*)d_in[1];
    const int*   tmk  = (const int*)  d_in[2];
    const float* gqs  = (const float*)d_in[3];
    const float* gqb  = (const float*)d_in[4];
    const float* gks  = (const float*)d_in[5];
    const float* gkb  = (const float*)d_in[6];
    const float* gts  = (const float*)d_in[7];
    const float* gtb  = (const float*)d_in[8];
    const float* Wq   = (const float*)d_in[9];
    const float* Wks  = (const float*)d_in[10];
    const float* Wvs  = (const float*)d_in[11];
    const float* Wkc  = (const float*)d_in[12];
    const float* Wvc  = (const float*)d_in[13];
    const float* Wout = (const float*)d_in[14];
    float* out = (float*)d_out;

    float* scratch = nullptr;
    cudaGetSymbolAddress((void**)&scratch, g_scratch);
    float* XQ   = scratch + OFF_XQ;
    float* XKV  = scratch + OFF_XKV;
    float* Qb   = scratch + OFF_Q;
    float* ATTb = scratch + OFF_ATTN;
    float* Tb   = scratch + OFF_T;
    float* Kb   = scratch + OFF_K;
    float* Vb   = scratch + OFF_V;

    gn_img_kernel<<<512, 256>>>(x, gqs, gqb, gks, gkb, XQ, XKV);
    gn_txt_kernel<<<512, 128>>>(te, gts, gtb, Tb);

    // projections (tensor cores); self parts write into concat positions of K/V
    gemm512_tc<<<dim3(128, 4), 256>>>(XQ,  Wq,  Qb, nullptr, 16384, 1024, 1024,  0, 0.125f);
    gemm512_tc<<<dim3(128, 4), 256>>>(XKV, Wks, Kb, nullptr, 16384, 1024, KVLEN, 0, 1.f);
    gemm512_tc<<<dim3(128, 4), 256>>>(XKV, Wvs, Vb, nullptr, 16384, 1024, KVLEN, 0, 1.f);
    gemm512_tc<<<dim3(10, 4),  256>>>(Tb,  Wkc, Kb, nullptr, 1232,  77,   KVLEN, 1024, 1.f);
    gemm512_tc<<<dim3(10, 4),  256>>>(Tb,  Wvc, Vb, nullptr, 1232,  77,   KVLEN, 1024, 1.f);

    cudaFuncSetAttribute(attn_tc, cudaFuncAttributeMaxDynamicSharedMemorySize,
                         ATT_SMEM_BYTES);
    attn_tc<<<dim3(8, NHH, BB), 128, ATT_SMEM_BYTES>>>(tmk, Qb, Kb, Vb, ATTb);

    // output projection + residual (fp32 residual add keeps overall error tiny)
    gemm512_tc<<<dim3(128, 4), 256>>>(ATTb, Wout, out, x, 16384, 1024, 1024, 0, 1.f);
}

// round 3
// speedup vs baseline: 3.8370x; 1.1713x over previous
#include <cuda_runtime.h>
#include <math.h>

// ---------------- problem constants ----------------
#define BB    16
#define NN    1024
#define CC    512
#define LL    77
#define KVLEN 1101
#define NHH   8
#define HDD   64
#define CPG   16
#define EPSV  1e-6f
#define NEGV  -1e10f

// ---------------- scratch (float offsets) ----------------
#define OFF_XQ   ((size_t)0)
#define OFF_XKV  ((size_t)8388608)
#define OFF_Q    ((size_t)16777216)
#define OFF_ATTN ((size_t)25165824)
#define OFF_T    ((size_t)33554432)
#define OFF_K    ((size_t)34185216)
#define OFF_V    ((size_t)43204608)
#define SCRATCH_FLOATS ((size_t)52224000)
__device__ float g_scratch[SCRATCH_FLOATS];

// ---------------- mma / cp.async helpers ----------------
// NOTE: fp32 bits fed directly to tf32 mma (HW truncates low mantissa bits).
__device__ __forceinline__ void mma8(float* c, const unsigned* a, const unsigned* b) {
    asm volatile(
        "mma.sync.aligned.m16n8k8.row.col.f32.tf32.tf32.f32 "
        "{%0,%1,%2,%3},{%4,%5,%6,%7},{%8,%9},{%0,%1,%2,%3};\n"
        : "+f"(c[0]), "+f"(c[1]), "+f"(c[2]), "+f"(c[3])
        : "r"(a[0]), "r"(a[1]), "r"(a[2]), "r"(a[3]), "r"(b[0]), "r"(b[1]));
}
__device__ __forceinline__ void cpa16(unsigned dst, const void* src, bool p) {
    int sz = p ? 16 : 0;
    asm volatile("cp.async.cg.shared.global [%0], [%1], 16, %2;\n"
                 :: "r"(dst), "l"(src), "r"(sz));
}
__device__ __forceinline__ void cpa_commit() {
    asm volatile("cp.async.commit_group;\n");
}
template<int N> __device__ __forceinline__ void cpa_wait() {
    asm volatile("cp.async.wait_group %0;\n" :: "n"(N));
}

// =====================================================================
// GroupNorm over image: one block per (b, g); writes both x_q and x_kv.
// =====================================================================
__global__ void gn_img_kernel(const float* __restrict__ x,
                              const float* __restrict__ qsc, const float* __restrict__ qbi,
                              const float* __restrict__ ksc, const float* __restrict__ kbi,
                              float* __restrict__ oq, float* __restrict__ okv)
{
    int b = blockIdx.x >> 5, g = blockIdx.x & 31;
    const float* xb = x + (size_t)b * NN * CC + g * CPG;
    int tid = threadIdx.x;

    float s = 0.f, s2 = 0.f;
    for (int e = tid; e < NN * 4; e += 256) {
        int n = e >> 2, c4 = (e & 3) << 2;
        float4 v = *(const float4*)(xb + (size_t)n * CC + c4);
        s  += v.x + v.y + v.z + v.w;
        s2 += v.x * v.x + v.y * v.y + v.z * v.z + v.w * v.w;
    }
    #pragma unroll
    for (int o2 = 16; o2; o2 >>= 1) {
        s  += __shfl_xor_sync(0xffffffffu, s,  o2);
        s2 += __shfl_xor_sync(0xffffffffu, s2, o2);
    }
    __shared__ float sh[8], sh2[8];
    int w = tid >> 5, lane = tid & 31;
    if (lane == 0) { sh[w] = s; sh2[w] = s2; }
    __syncthreads();

    __shared__ float cq[2][CPG], ck[2][CPG];
    if (tid < CPG) {
        float ts = 0.f, ts2 = 0.f;
        #pragma unroll
        for (int i = 0; i < 8; i++) { ts += sh[i]; ts2 += sh2[i]; }
        const float cnt = (float)(NN * CPG);
        float mu  = ts / cnt;
        float var = ts2 / cnt - mu * mu;
        float inv = rsqrtf(var + EPSV);
        int c = g * CPG + tid;
        float aq = inv * qsc[c];
        cq[0][tid] = aq;  cq[1][tid] = qbi[c] - mu * aq;
        float ak = inv * ksc[c];
        ck[0][tid] = ak;  ck[1][tid] = kbi[c] - mu * ak;
    }
    __syncthreads();

    float* oqb  = oq  + (size_t)b * NN * CC + g * CPG;
    float* okvb = okv + (size_t)b * NN * CC + g * CPG;
    for (int e = tid; e < NN * 4; e += 256) {
        int n = e >> 2, c4 = (e & 3) << 2;
        float4 v = *(const float4*)(xb + (size_t)n * CC + c4);
        float4 r;
        r.x = v.x * cq[0][c4+0] + cq[1][c4+0];
        r.y = v.y * cq[0][c4+1] + cq[1][c4+1];
        r.z = v.z * cq[0][c4+2] + cq[1][c4+2];
        r.w = v.w * cq[0][c4+3] + cq[1][c4+3];
        *(float4*)(oqb + (size_t)n * CC + c4) = r;
        r.x = v.x * ck[0][c4+0] + ck[1][c4+0];
        r.y = v.y * ck[0][c4+1] + ck[1][c4+1];
        r.z = v.z * ck[0][c4+2] + ck[1][c4+2];
        r.w = v.w * ck[0][c4+3] + ck[1][c4+3];
        *(float4*)(okvb + (size_t)n * CC + c4) = r;
    }
}

// =====================================================================
// GroupNorm over text
// =====================================================================
__global__ void gn_txt_kernel(const float* __restrict__ t,
                              const float* __restrict__ tsc, const float* __restrict__ tbi,
                              float* __restrict__ ot)
{
    int b = blockIdx.x >> 5, g = blockIdx.x & 31;
    const float* xb = t + (size_t)b * LL * CC + g * CPG;
    int tid = threadIdx.x;

    float s = 0.f, s2 = 0.f;
    for (int e = tid; e < LL * 4; e += 128) {
        int n = e >> 2, c4 = (e & 3) << 2;
        float4 v = *(const float4*)(xb + (size_t)n * CC + c4);
        s  += v.x + v.y + v.z + v.w;
        s2 += v.x * v.x + v.y * v.y + v.z * v.z + v.w * v.w;
    }
    #pragma unroll
    for (int o2 = 16; o2; o2 >>= 1) {
        s  += __shfl_xor_sync(0xffffffffu, s,  o2);
        s2 += __shfl_xor_sync(0xffffffffu, s2, o2);
    }
    __shared__ float sh[4], sh2[4];
    int w = tid >> 5, lane = tid & 31;
    if (lane == 0) { sh[w] = s; sh2[w] = s2; }
    __syncthreads();

    __shared__ float ct[2][CPG];
    if (tid < CPG) {
        float ts = 0.f, ts2 = 0.f;
        #pragma unroll
        for (int i = 0; i < 4; i++) { ts += sh[i]; ts2 += sh2[i]; }
        const float cnt = (float)(LL * CPG);
        float mu  = ts / cnt;
        float var = ts2 / cnt - mu * mu;
        float inv = rsqrtf(var + EPSV);
        int c = g * CPG + tid;
        float a = inv * tsc[c];
        ct[0][tid] = a;  ct[1][tid] = tbi[c] - mu * a;
    }
    __syncthreads();

    float* ob = ot + (size_t)b * LL * CC + g * CPG;
    for (int e = tid; e < LL * 4; e += 128) {
        int n = e >> 2, c4 = (e & 3) << 2;
        float4 v = *(const float4*)(xb + (size_t)n * CC + c4);
        float4 r;
        r.x = v.x * ct[0][c4+0] + ct[1][c4+0];
        r.y = v.y * ct[0][c4+1] + ct[1][c4+1];
        r.z = v.z * ct[0][c4+2] + ct[1][c4+2];
        r.w = v.w * ct[0][c4+3] + ct[1][c4+3];
        *(float4*)(ob + (size_t)n * CC + c4) = r;
    }
}

// =====================================================================
// TF32 tensor-core GEMM, cp.async double-buffered.
// Block tile 128x128, BK=32, 256 threads (8 warps, 64x32 warp tiles).
// =====================================================================
#define GAS 36
#define GBS 132
#define GEMM_SMEM_BYTES ((2 * 128 * GAS + 2 * 32 * GBS) * 4)

__global__ void __launch_bounds__(256, 2)
gemm512_tc(const float* __restrict__ A, const float* __restrict__ W,
           float* __restrict__ Out, const float* __restrict__ Res,
           int M, int rows_per_b, int out_rows_per_b, int out_off,
           float alpha)
{
    extern __shared__ unsigned smg[];
    unsigned* As = smg;                 // [2][128][GAS]
    unsigned* Bs = smg + 2 * 128 * GAS; // [2][32][GBS]

    int tid = threadIdx.x;
    int warp = tid >> 5, lane = tid & 31;
    int g = lane >> 2, tg = lane & 3;
    int wm = (warp >> 2) * 64, wn = (warp & 3) * 32;
    int m0 = blockIdx.x * 128, n0 = blockIdx.y * 128;

    float acc[4][4][4];
    #pragma unroll
    for (int i = 0; i < 4; i++)
        #pragma unroll
        for (int j = 0; j < 4; j++)
            #pragma unroll
            for (int q = 0; q < 4; q++) acc[i][j][q] = 0.f;

    // fill mapping
    int arow[4], ac4[4]; bool aok[4];
    int brow[4], bc4[4];
    #pragma unroll
    for (int i = 0; i < 4; i++) {
        int f = tid + i * 256;
        arow[i] = f >> 3;  ac4[i] = (f & 7) << 2;
        aok[i] = (m0 + arow[i]) < M;
        brow[i] = f >> 5;  bc4[i] = (f & 31) << 2;
    }

    auto loadTile = [&](int kt, int st) {
        int k0 = kt * 32;
        unsigned* Ad = As + st * 128 * GAS;
        unsigned* Bd = Bs + st * 32 * GBS;
        #pragma unroll
        for (int i = 0; i < 4; i++) {
            cpa16((unsigned)__cvta_generic_to_shared(Ad + arow[i] * GAS + ac4[i]),
                  A + (size_t)(m0 + arow[i]) * 512 + k0 + ac4[i], aok[i]);
            cpa16((unsigned)__cvta_generic_to_shared(Bd + brow[i] * GBS + bc4[i]),
                  W + (size_t)(k0 + brow[i]) * 512 + n0 + bc4[i], true);
        }
    };

    loadTile(0, 0);
    cpa_commit();

    for (int t = 0; t < 16; t++) {
        __syncthreads();                 // prev compute done before overwriting its stage
        if (t + 1 < 16) {
            loadTile(t + 1, (t + 1) & 1);
            cpa_commit();
            cpa_wait<1>();
        } else {
            cpa_wait<0>();
        }
        __syncthreads();

        const unsigned* Ac = As + (t & 1) * 128 * GAS;
        const unsigned* Bc = Bs + (t & 1) * 32 * GBS;
        #pragma unroll
        for (int ks = 0; ks < 32; ks += 8) {
            unsigned af[4][4], bf[4][2];
            #pragma unroll
            for (int i = 0; i < 4; i++) {
                int r = wm + i * 16 + g;
                af[i][0] = Ac[r * GAS + ks + tg];
                af[i][1] = Ac[(r + 8) * GAS + ks + tg];
                af[i][2] = Ac[r * GAS + ks + tg + 4];
                af[i][3] = Ac[(r + 8) * GAS + ks + tg + 4];
            }
            #pragma unroll
            for (int j = 0; j < 4; j++) {
                bf[j][0] = Bc[(ks + tg) * GBS + wn + j * 8 + g];
                bf[j][1] = Bc[(ks + tg + 4) * GBS + wn + j * 8 + g];
            }
            #pragma unroll
            for (int i = 0; i < 4; i++)
                #pragma unroll
                for (int j = 0; j < 4; j++)
                    mma8(acc[i][j], af[i], bf[j]);
        }
    }

    // epilogue
    #pragma unroll
    for (int i = 0; i < 4; i++) {
        #pragma unroll
        for (int rsel = 0; rsel < 2; rsel++) {
            int gm = m0 + wm + i * 16 + g + rsel * 8;
            if (gm >= M) continue;
            int bbi = gm / rows_per_b;
            int rr  = gm - bbi * rows_per_b;
            size_t orow = (size_t)bbi * out_rows_per_b + out_off + rr;
            #pragma unroll
            for (int j = 0; j < 4; j++) {
                int col = n0 + wn + j * 8 + 2 * tg;
                float v0 = acc[i][j][rsel * 2 + 0] * alpha;
                float v1 = acc[i][j][rsel * 2 + 1] * alpha;
                if (Res) {
                    float2 r = *(const float2*)(Res + orow * 512 + col);
                    v0 += r.x; v1 += r.y;
                }
                *(float2*)(Out + orow * 512 + col) = make_float2(v0, v1);
            }
        }
    }
}

// =====================================================================
// TF32 flash attention, cp.async double-buffered KV, 8 warps (16 q-rows each).
// Block = (128-q-tile, head, batch).
// =====================================================================
#define ATS 68
#define NKVT 18
#define ATT_SMEM_BYTES ((128 * ATS + 4 * 64 * ATS + 128 * ATS + 128) * 4)

__global__ void __launch_bounds__(256, 1)
attn_tc(const int* __restrict__ tmask,
        const float* __restrict__ Qg,
        const float* __restrict__ Kg,
        const float* __restrict__ Vg,
        float* __restrict__ Og)
{
    extern __shared__ unsigned smb[];
    unsigned* Qs = smb;                        // [128][ATS]
    unsigned* Ks = Qs + 128 * ATS;             // [2][64][ATS]
    unsigned* Vs = Ks + 2 * 64 * ATS;          // [2][64][ATS]
    unsigned* Ps = Vs + 2 * 64 * ATS;          // [128][ATS]
    float* kmaskf = (float*)(Ps + 128 * ATS);  // [2][64]

    int qt = blockIdx.x, h = blockIdx.y, b = blockIdx.z;
    int tid = threadIdx.x, warp = tid >> 5, lane = tid & 31;
    int g = lane >> 2, tg = lane & 3;
    int wm = warp * 16;

    const float* qb = Qg + (size_t)(b * NN + qt * 128) * CC + h * HDD;
    const float* kb = Kg + (size_t)b * KVLEN * CC + h * HDD;
    const float* vb = Vg + (size_t)b * KVLEN * CC + h * HDD;
    const int* tm = tmask + b * LL;

    // Q via cp.async (group 0)
    #pragma unroll
    for (int i = 0; i < 8; i++) {
        int f = tid + i * 256;
        int r = f >> 4, c4 = (f & 15) << 2;
        cpa16((unsigned)__cvta_generic_to_shared(Qs + r * ATS + c4),
              qb + (size_t)r * CC + c4, true);
    }
    cpa_commit();

    auto loadKV = [&](int t, int st) {
        unsigned* Kd = Ks + st * 64 * ATS;
        unsigned* Vd = Vs + st * 64 * ATS;
        int kv0 = t * 64;
        #pragma unroll
        for (int i = 0; i < 4; i++) {
            int f = tid + i * 256;
            int r = f >> 4, c4 = (f & 15) << 2;
            int kg = kv0 + r;
            bool ok = kg < KVLEN;
            cpa16((unsigned)__cvta_generic_to_shared(Kd + r * ATS + c4),
                  kb + (size_t)kg * CC + c4, ok);
            cpa16((unsigned)__cvta_generic_to_shared(Vd + r * ATS + c4),
                  vb + (size_t)kg * CC + c4, ok);
        }
        if (tid < 64) {
            int kg = kv0 + tid;
            float madd = 0.f;
            if (kg >= KVLEN) madd = NEGV;
            else if (kg >= NN && tm[kg - NN] == 0) madd = NEGV;
            kmaskf[st * 64 + tid] = madd;
        }
    };

    loadKV(0, 0);
    cpa_commit();

    float m_i[2], l_i[2], o[8][4];
    m_i[0] = m_i[1] = -1e30f;
    l_i[0] = l_i[1] = 0.f;
    #pragma unroll
    for (int j = 0; j < 8; j++)
        #pragma unroll
        for (int q = 0; q < 4; q++) o[j][q] = 0.f;

    for (int t = 0; t < NKVT; t++) {
        __syncthreads();
        if (t + 1 < NKVT) {
            loadKV(t + 1, (t + 1) & 1);
            cpa_commit();
            cpa_wait<1>();
        } else {
            cpa_wait<0>();
        }
        __syncthreads();

        int st = t & 1;
        const unsigned* Kc = Ks + st * 64 * ATS;
        const unsigned* Vc = Vs + st * 64 * ATS;
        const float* km = kmaskf + st * 64;

        // ---- S = Q K^T ----
        float s[8][4];
        #pragma unroll
        for (int j = 0; j < 8; j++)
            #pragma unroll
            for (int q = 0; q < 4; q++) s[j][q] = 0.f;

        #pragma unroll
        for (int d0 = 0; d0 < 64; d0 += 8) {
            unsigned aq[4];
            int r = wm + g;
            aq[0] = Qs[r * ATS + d0 + tg];
            aq[1] = Qs[(r + 8) * ATS + d0 + tg];
            aq[2] = Qs[r * ATS + d0 + tg + 4];
            aq[3] = Qs[(r + 8) * ATS + d0 + tg + 4];
            #pragma unroll
            for (int j = 0; j < 8; j++) {
                unsigned bk[2];
                bk[0] = Kc[(j * 8 + g) * ATS + d0 + tg];
                bk[1] = Kc[(j * 8 + g) * ATS + d0 + tg + 4];
                mma8(s[j], aq, bk);
            }
        }

        // ---- mask + online softmax ----
        #pragma unroll
        for (int j = 0; j < 8; j++) {
            float km0 = km[j * 8 + 2 * tg];
            float km1 = km[j * 8 + 2 * tg + 1];
            s[j][0] += km0; s[j][1] += km1;
            s[j][2] += km0; s[j][3] += km1;
        }
        float mx0 = -1e30f, mx1 = -1e30f;
        #pragma unroll
        for (int j = 0; j < 8; j++) {
            mx0 = fmaxf(mx0, fmaxf(s[j][0], s[j][1]));
            mx1 = fmaxf(mx1, fmaxf(s[j][2], s[j][3]));
        }
        mx0 = fmaxf(mx0, __shfl_xor_sync(0xffffffffu, mx0, 1));
        mx0 = fmaxf(mx0, __shfl_xor_sync(0xffffffffu, mx0, 2));
        mx1 = fmaxf(mx1, __shfl_xor_sync(0xffffffffu, mx1, 1));
        mx1 = fmaxf(mx1, __shfl_xor_sync(0xffffffffu, mx1, 2));
        float mn0 = fmaxf(m_i[0], mx0), mn1 = fmaxf(m_i[1], mx1);
        float al0 = __expf(m_i[0] - mn0), al1 = __expf(m_i[1] - mn1);
        m_i[0] = mn0; m_i[1] = mn1;
        float sum0 = 0.f, sum1 = 0.f;
        int pr = wm + g;
        #pragma unroll
        for (int j = 0; j < 8; j++) {
            float p0 = __expf(s[j][0] - mn0);
            float p1 = __expf(s[j][1] - mn0);
            float p2 = __expf(s[j][2] - mn1);
            float p3 = __expf(s[j][3] - mn1);
            sum0 += p0 + p1; sum1 += p2 + p3;
            uint2 u0; u0.x = __float_as_uint(p0); u0.y = __float_as_uint(p1);
            uint2 u1; u1.x = __float_as_uint(p2); u1.y = __float_as_uint(p3);
            *(uint2*)(Ps + pr * ATS + j * 8 + 2 * tg) = u0;
            *(uint2*)(Ps + (pr + 8) * ATS + j * 8 + 2 * tg) = u1;
        }
        sum0 += __shfl_xor_sync(0xffffffffu, sum0, 1);
        sum0 += __shfl_xor_sync(0xffffffffu, sum0, 2);
        sum1 += __shfl_xor_sync(0xffffffffu, sum1, 1);
        sum1 += __shfl_xor_sync(0xffffffffu, sum1, 2);
        l_i[0] = l_i[0] * al0 + sum0;
        l_i[1] = l_i[1] * al1 + sum1;
        #pragma unroll
        for (int j = 0; j < 8; j++) {
            o[j][0] *= al0; o[j][1] *= al0;
            o[j][2] *= al1; o[j][3] *= al1;
        }
        __syncwarp();

        // ---- O += P V ----
        #pragma unroll
        for (int k0 = 0; k0 < 64; k0 += 8) {
            unsigned ap[4];
            ap[0] = Ps[pr * ATS + k0 + tg];
            ap[1] = Ps[(pr + 8) * ATS + k0 + tg];
            ap[2] = Ps[pr * ATS + k0 + tg + 4];
            ap[3] = Ps[(pr + 8) * ATS + k0 + tg + 4];
            #pragma unroll
            for (int j = 0; j < 8; j++) {
                unsigned bv[2];
                bv[0] = Vc[(k0 + tg) * ATS + j * 8 + g];
                bv[1] = Vc[(k0 + tg + 4) * ATS + j * 8 + g];
                mma8(o[j], ap, bv);
            }
        }
        __syncwarp();
    }

    // ---- write O ----
    float* ob = Og + (size_t)(b * NN + qt * 128) * CC + h * HDD;
    #pragma unroll
    for (int rsel = 0; rsel < 2; rsel++) {
        int r = wm + g + rsel * 8;
        float inv = 1.f / l_i[rsel];
        #pragma unroll
        for (int j = 0; j < 8; j++) {
            int col = j * 8 + 2 * tg;
            float v0 = o[j][rsel * 2 + 0] * inv;
            float v1 = o[j][rsel * 2 + 1] * inv;
            *(float2*)(ob + (size_t)r * CC + col) = make_float2(v0, v1);
        }
    }
}

// =====================================================================
// launch
// =====================================================================
extern "C" void kernel_launch(void* const* d_in, const int* in_sizes, int n_in,
                              void* d_out, int out_size)
{
    const float* x    = (const float*)d_in[0];
    const float* te   = (const float*)d_in[1];
    const int*   tmk  = (const int*)  d_in[2];
    const float* gqs  = (const float*)d_in[3];
    const float* gqb  = (const float*)d_in[4];
    const float* gks  = (const float*)d_in[5];
    const float* gkb  = (const float*)d_in[6];
    const float* gts  = (const float*)d_in[7];
    const float* gtb  = (const float*)d_in[8];
    const float* Wq   = (const float*)d_in[9];
    const float* Wks  = (const float*)d_in[10];
    const float* Wvs  = (const float*)d_in[11];
    const float* Wkc  = (const float*)d_in[12];
    const float* Wvc  = (const float*)d_in[13];
    const float* Wout = (const float*)d_in[14];
    float* out = (float*)d_out;

    float* scratch = nullptr;
    cudaGetSymbolAddress((void**)&scratch, g_scratch);
    float* XQ   = scratch + OFF_XQ;
    float* XKV  = scratch + OFF_XKV;
    float* Qb   = scratch + OFF_Q;
    float* ATTb = scratch + OFF_ATTN;
    float* Tb   = scratch + OFF_T;
    float* Kb   = scratch + OFF_K;
    float* Vb   = scratch + OFF_V;

    cudaFuncSetAttribute(gemm512_tc, cudaFuncAttributeMaxDynamicSharedMemorySize,
                         GEMM_SMEM_BYTES);
    cudaFuncSetAttribute(attn_tc, cudaFuncAttributeMaxDynamicSharedMemorySize,
                         ATT_SMEM_BYTES);

    gn_img_kernel<<<512, 256>>>(x, gqs, gqb, gks, gkb, XQ, XKV);
    gn_txt_kernel<<<512, 128>>>(te, gts, gtb, Tb);

    gemm512_tc<<<dim3(128, 4), 256, GEMM_SMEM_BYTES>>>(XQ,  Wq,  Qb, nullptr, 16384, 1024, 1024,  0, 0.125f);
    gemm512_tc<<<dim3(128, 4), 256, GEMM_SMEM_BYTES>>>(XKV, Wks, Kb, nullptr, 16384, 1024, KVLEN, 0, 1.f);
    gemm512_tc<<<dim3(128, 4), 256, GEMM_SMEM_BYTES>>>(XKV, Wvs, Vb, nullptr, 16384, 1024, KVLEN, 0, 1.f);
    gemm512_tc<<<dim3(10, 4),  256, GEMM_SMEM_BYTES>>>(Tb,  Wkc, Kb, nullptr, 1232,  77,   KVLEN, 1024, 1.f);
    gemm512_tc<<<dim3(10, 4),  256, GEMM_SMEM_BYTES>>>(Tb,  Wvc, Vb, nullptr, 1232,  77,   KVLEN, 1024, 1.f);

    attn_tc<<<dim3(8, NHH, BB), 256, ATT_SMEM_BYTES>>>(tmk, Qb, Kb, Vb, ATTb);

    gemm512_tc<<<dim3(128, 4), 256, GEMM_SMEM_BYTES>>>(ATTb, Wout, out, x, 16384, 1024, 1024, 0, 1.f);
}

// round 4
// speedup vs baseline: 8.4633x; 2.2057x over previous
#include <cuda_runtime.h>
#include <cuda_bf16.h>
#include <math.h>

// ---------------- problem constants ----------------
#define BB    16
#define NN    1024
#define CC    512
#define LL    77
#define KVLEN 1101
#define NHH   8
#define HDD   64
#define CPG   16
#define EPSV  1e-6f
#define NEGV  -1e10f

// ---------------- scratch ----------------
__device__ float g_scratch[52224000];

// bf16-element offsets into scratch (viewed as __nv_bfloat16*)
#define BOFF_XQ   ((size_t)0)
#define BOFF_XKV  ((size_t)8388608)
#define BOFF_T    ((size_t)16777216)
#define BOFF_Q    ((size_t)17408000)
#define BOFF_K    ((size_t)25796608)
#define BOFF_V    ((size_t)34816000)
#define BOFF_ATT  ((size_t)43835392)
#define BOFF_W    ((size_t)52224000)   // 6 matrices x 262144

// ---------------- helpers ----------------
__device__ __forceinline__ unsigned pack_bf16x2(float lo, float hi) {
    unsigned r;
    asm("cvt.rn.bf16x2.f32 %0, %1, %2;" : "=r"(r) : "f"(hi), "f"(lo));
    return r;
}
__device__ __forceinline__ void mma16(float* c, const unsigned* a, const unsigned* b) {
    asm volatile(
        "mma.sync.aligned.m16n8k16.row.col.f32.bf16.bf16.f32 "
        "{%0,%1,%2,%3},{%4,%5,%6,%7},{%8,%9},{%0,%1,%2,%3};\n"
        : "+f"(c[0]), "+f"(c[1]), "+f"(c[2]), "+f"(c[3])
        : "r"(a[0]), "r"(a[1]), "r"(a[2]), "r"(a[3]), "r"(b[0]), "r"(b[1]));
}
__device__ __forceinline__ void ldsm4(unsigned& r0, unsigned& r1, unsigned& r2, unsigned& r3,
                                      unsigned addr) {
    asm volatile("ldmatrix.sync.aligned.m8n8.x4.shared.b16 {%0,%1,%2,%3}, [%4];"
                 : "=r"(r0), "=r"(r1), "=r"(r2), "=r"(r3) : "r"(addr));
}
__device__ __forceinline__ void ldsm4t(unsigned& r0, unsigned& r1, unsigned& r2, unsigned& r3,
                                       unsigned addr) {
    asm volatile("ldmatrix.sync.aligned.m8n8.x4.trans.shared.b16 {%0,%1,%2,%3}, [%4];"
                 : "=r"(r0), "=r"(r1), "=r"(r2), "=r"(r3) : "r"(addr));
}
__device__ __forceinline__ void cpa16(unsigned dst, const void* src, bool p) {
    int sz = p ? 16 : 0;
    asm volatile("cp.async.cg.shared.global [%0], [%1], 16, %2;\n"
                 :: "r"(dst), "l"(src), "r"(sz));
}
__device__ __forceinline__ void cpa_commit() { asm volatile("cp.async.commit_group;\n"); }
template<int N> __device__ __forceinline__ void cpa_wait() {
    asm volatile("cp.async.wait_group %0;\n" :: "n"(N));
}

// =====================================================================
// Weight conversion: fp32 -> bf16, 6 matrices of 512x512, kept [k][n].
// =====================================================================
__global__ void wconv_kernel(const float* __restrict__ w0, const float* __restrict__ w1,
                             const float* __restrict__ w2, const float* __restrict__ w3,
                             const float* __restrict__ w4, const float* __restrict__ w5,
                             __nv_bfloat16* __restrict__ out)
{
    int gid = blockIdx.x * 256 + threadIdx.x;      // 0..393215 (x4 elems)
    int mat = gid >> 16;
    int idx = (gid & 65535) << 2;
    const float* src = mat == 0 ? w0 : mat == 1 ? w1 : mat == 2 ? w2
                     : mat == 3 ? w3 : mat == 4 ? w4 : w5;
    float4 v = *(const float4*)(src + idx);
    uint2 p;
    p.x = pack_bf16x2(v.x, v.y);
    p.y = pack_bf16x2(v.z, v.w);
    *(uint2*)(out + (size_t)mat * 262144 + idx) = p;
}

// =====================================================================
// GroupNorm over image (fp32 stats, bf16 outputs x_q and x_kv)
// =====================================================================
__global__ void gn_img_kernel(const float* __restrict__ x,
                              const float* __restrict__ qsc, const float* __restrict__ qbi,
                              const float* __restrict__ ksc, const float* __restrict__ kbi,
                              __nv_bfloat16* __restrict__ oq, __nv_bfloat16* __restrict__ okv)
{
    int b = blockIdx.x >> 5, g = blockIdx.x & 31;
    const float* xb = x + (size_t)b * NN * CC + g * CPG;
    int tid = threadIdx.x;

    float s = 0.f, s2 = 0.f;
    for (int e = tid; e < NN * 4; e += 256) {
        int n = e >> 2, c4 = (e & 3) << 2;
        float4 v = *(const float4*)(xb + (size_t)n * CC + c4);
        s  += v.x + v.y + v.z + v.w;
        s2 += v.x * v.x + v.y * v.y + v.z * v.z + v.w * v.w;
    }
    #pragma unroll
    for (int o2 = 16; o2; o2 >>= 1) {
        s  += __shfl_xor_sync(0xffffffffu, s,  o2);
        s2 += __shfl_xor_sync(0xffffffffu, s2, o2);
    }
    __shared__ float sh[8], sh2[8];
    int w = tid >> 5, lane = tid & 31;
    if (lane == 0) { sh[w] = s; sh2[w] = s2; }
    __syncthreads();

    __shared__ float cq[2][CPG], ck[2][CPG];
    if (tid < CPG) {
        float ts = 0.f, ts2 = 0.f;
        #pragma unroll
        for (int i = 0; i < 8; i++) { ts += sh[i]; ts2 += sh2[i]; }
        const float cnt = (float)(NN * CPG);
        float mu  = ts / cnt;
        float var = ts2 / cnt - mu * mu;
        float inv = rsqrtf(var + EPSV);
        int c = g * CPG + tid;
        float aq = inv * qsc[c];
        cq[0][tid] = aq;  cq[1][tid] = qbi[c] - mu * aq;
        float ak = inv * ksc[c];
        ck[0][tid] = ak;  ck[1][tid] = kbi[c] - mu * ak;
    }
    __syncthreads();

    __nv_bfloat16* oqb  = oq  + (size_t)b * NN * CC + g * CPG;
    __nv_bfloat16* okvb = okv + (size_t)b * NN * CC + g * CPG;
    for (int e = tid; e < NN * 4; e += 256) {
        int n = e >> 2, c4 = (e & 3) << 2;
        float4 v = *(const float4*)(xb + (size_t)n * CC + c4);
        uint2 pq, pk;
        pq.x = pack_bf16x2(v.x * cq[0][c4+0] + cq[1][c4+0], v.y * cq[0][c4+1] + cq[1][c4+1]);
        pq.y = pack_bf16x2(v.z * cq[0][c4+2] + cq[1][c4+2], v.w * cq[0][c4+3] + cq[1][c4+3]);
        pk.x = pack_bf16x2(v.x * ck[0][c4+0] + ck[1][c4+0], v.y * ck[0][c4+1] + ck[1][c4+1]);
        pk.y = pack_bf16x2(v.z * ck[0][c4+2] + ck[1][c4+2], v.w * ck[0][c4+3] + ck[1][c4+3]);
        *(uint2*)(oqb  + (size_t)n * CC + c4) = pq;
        *(uint2*)(okvb + (size_t)n * CC + c4) = pk;
    }
}

// =====================================================================
// GroupNorm over text (bf16 output)
// =====================================================================
__global__ void gn_txt_kernel(const float* __restrict__ t,
                              const float* __restrict__ tsc, const float* __restrict__ tbi,
                              __nv_bfloat16* __restrict__ ot)
{
    int b = blockIdx.x >> 5, g = blockIdx.x & 31;
    const float* xb = t + (size_t)b * LL * CC + g * CPG;
    int tid = threadIdx.x;

    float s = 0.f, s2 = 0.f;
    for (int e = tid; e < LL * 4; e += 128) {
        int n = e >> 2, c4 = (e & 3) << 2;
        float4 v = *(const float4*)(xb + (size_t)n * CC + c4);
        s  += v.x + v.y + v.z + v.w;
        s2 += v.x * v.x + v.y * v.y + v.z * v.z + v.w * v.w;
    }
    #pragma unroll
    for (int o2 = 16; o2; o2 >>= 1) {
        s  += __shfl_xor_sync(0xffffffffu, s,  o2);
        s2 += __shfl_xor_sync(0xffffffffu, s2, o2);
    }
    __shared__ float sh[4], sh2[4];
    int w = tid >> 5, lane = tid & 31;
    if (lane == 0) { sh[w] = s; sh2[w] = s2; }
    __syncthreads();

    __shared__ float ct[2][CPG];
    if (tid < CPG) {
        float ts = 0.f, ts2 = 0.f;
        #pragma unroll
        for (int i = 0; i < 4; i++) { ts += sh[i]; ts2 += sh2[i]; }
        const float cnt = (float)(LL * CPG);
        float mu  = ts / cnt;
        float var = ts2 / cnt - mu * mu;
        float inv = rsqrtf(var + EPSV);
        int c = g * CPG + tid;
        float a = inv * tsc[c];
        ct[0][tid] = a;  ct[1][tid] = tbi[c] - mu * a;
    }
    __syncthreads();

    __nv_bfloat16* ob = ot + (size_t)b * LL * CC + g * CPG;
    for (int e = tid; e < LL * 4; e += 128) {
        int n = e >> 2, c4 = (e & 3) << 2;
        float4 v = *(const float4*)(xb + (size_t)n * CC + c4);
        uint2 p;
        p.x = pack_bf16x2(v.x * ct[0][c4+0] + ct[1][c4+0], v.y * ct[0][c4+1] + ct[1][c4+1]);
        p.y = pack_bf16x2(v.z * ct[0][c4+2] + ct[1][c4+2], v.w * ct[0][c4+3] + ct[1][c4+3]);
        *(uint2*)(ob + (size_t)n * CC + c4) = p;
    }
}

// =====================================================================
// BF16 tensor-core GEMM (m16n8k16 + ldmatrix), cp.async double-buffered.
// Block 128x128, BK=64, 256 threads (8 warps, 64x32 warp tiles).
// A [M][512] bf16 row-major; W [512][512] bf16 row-major [k][n] (ldsm trans).
// =====================================================================
#define GEMM_SMEM 65536

__global__ void __launch_bounds__(256, 2)
gemm_bf16(const __nv_bfloat16* __restrict__ A, const __nv_bfloat16* __restrict__ W,
          void* __restrict__ OutP, const float* __restrict__ Res,
          int M, int rows_per_b, int out_rows_per_b, int out_off,
          float alpha, int outBf16)
{
    extern __shared__ char smc[];
    unsigned aBase = (unsigned)__cvta_generic_to_shared(smc);   // [2][128 rows][128B]
    unsigned bBase = aBase + 32768;                             // [2][64 rows][256B]

    int tid = threadIdx.x, warp = tid >> 5, lane = tid & 31;
    int g = lane >> 2, tg = lane & 3;
    int wm = (warp >> 2) * 64, wn = (warp & 3) * 32;
    int m0 = blockIdx.x * 128, n0 = blockIdx.y * 128;

    float acc[4][4][4] = {};

    auto loadTile = [&](int kt, int st) {
        int k0 = kt * 64;
        unsigned aD = aBase + st * 16384;
        unsigned bD = bBase + st * 16384;
        #pragma unroll
        for (int i = 0; i < 4; i++) {
            int f = tid + i * 256;
            int r = f >> 3, c = f & 7;
            bool ok = (m0 + r) < M;
            cpa16(aD + r * 128 + (((c ^ (r & 7))) << 4),
                  A + (size_t)(m0 + r) * 512 + k0 + c * 8, ok);
        }
        #pragma unroll
        for (int i = 0; i < 4; i++) {
            int f = tid + i * 256;
            int r = f >> 4, c = f & 15;
            cpa16(bD + r * 256 + (((c ^ (r & 7))) << 4),
                  W + (size_t)(k0 + r) * 512 + n0 + c * 8, true);
        }
    };
    loadTile(0, 0);
    cpa_commit();

    for (int t = 0; t < 8; t++) {
        __syncthreads();
        if (t + 1 < 8) { loadTile(t + 1, (t + 1) & 1); cpa_commit(); cpa_wait<1>(); }
        else           { cpa_wait<0>(); }
        __syncthreads();

        unsigned aC = aBase + (t & 1) * 16384;
        unsigned bC = bBase + (t & 1) * 16384;
        #pragma unroll
        for (int kc = 0; kc < 8; kc += 2) {     // k16 steps (chunk pairs)
            unsigned af[4][4];
            #pragma unroll
            for (int i = 0; i < 4; i++) {
                int r = wm + i * 16 + (lane & 15);
                int c = kc + (lane >> 4);
                ldsm4(af[i][0], af[i][1], af[i][2], af[i][3],
                      aC + r * 128 + ((c ^ (r & 7)) << 4));
            }
            unsigned bfr[4][2];
            #pragma unroll
            for (int grp = 0; grp < 2; grp++) {
                int r = kc * 8 + (lane & 15);
                int c = (wn >> 3) + 2 * grp + (lane >> 4);
                unsigned r0, r1, r2, r3;
                ldsm4t(r0, r1, r2, r3, bC + r * 256 + ((c ^ (r & 7)) << 4));
                bfr[grp*2][0] = r0;  bfr[grp*2][1] = r1;
                bfr[grp*2+1][0] = r2; bfr[grp*2+1][1] = r3;
            }
            #pragma unroll
            for (int i = 0; i < 4; i++)
                #pragma unroll
                for (int j = 0; j < 4; j++)
                    mma16(acc[i][j], af[i], bfr[j]);
        }
    }

    // epilogue
    #pragma unroll
    for (int i = 0; i < 4; i++) {
        #pragma unroll
        for (int rs = 0; rs < 2; rs++) {
            int gm = m0 + wm + i * 16 + g + rs * 8;
            if (gm >= M) continue;
            int bbi = gm / rows_per_b;
            int rr  = gm - bbi * rows_per_b;
            size_t orow = (size_t)bbi * out_rows_per_b + out_off + rr;
            #pragma unroll
            for (int j = 0; j < 4; j++) {
                int col = n0 + wn + j * 8 + 2 * tg;
                float v0 = acc[i][j][rs * 2 + 0] * alpha;
                float v1 = acc[i][j][rs * 2 + 1] * alpha;
                if (outBf16) {
                    *(unsigned*)((__nv_bfloat16*)OutP + orow * 512 + col) =
                        pack_bf16x2(v0, v1);
                } else {
                    if (Res) {
                        float2 rv = *(const float2*)(Res + orow * 512 + col);
                        v0 += rv.x; v1 += rv.y;
                    }
                    *(float2*)((float*)OutP + orow * 512 + col) = make_float2(v0, v1);
                }
            }
        }
    }
}

// =====================================================================
// BF16 flash attention (m16n8k16 + ldmatrix), double-buffered KV,
// 8 warps x 16 q-rows, block = (128-q-tile, head, batch). smem 66KB -> 2/SM.
// =====================================================================
#define ATT_SMEM (65536 + 512)

__global__ void __launch_bounds__(256, 2)
attn_bf16(const int* __restrict__ tmask,
          const __nv_bfloat16* __restrict__ Qg,
          const __nv_bfloat16* __restrict__ Kg,
          const __nv_bfloat16* __restrict__ Vg,
          __nv_bfloat16* __restrict__ Og)
{
    extern __shared__ char smc[];
    unsigned qB = (unsigned)__cvta_generic_to_shared(smc);  // [128][128B]
    unsigned kB = qB + 16384;                               // [2][64][128B]
    unsigned vB = kB + 16384;                               // [2][64][128B]
    unsigned pB = vB + 16384;                               // [128][128B]
    char* psPtr = smc + 49152;
    float* kmaskf = (float*)(smc + 65536);                  // [2][64]

    int qt = blockIdx.x, h = blockIdx.y, b = blockIdx.z;
    int tid = threadIdx.x, warp = tid >> 5, lane = tid & 31;
    int g = lane >> 2, tg = lane & 3;
    int wm = warp * 16;

    const __nv_bfloat16* qb = Qg + (size_t)(b * NN + qt * 128) * 512 + h * 64;
    const __nv_bfloat16* kb = Kg + (size_t)b * KVLEN * 512 + h * 64;
    const __nv_bfloat16* vb = Vg + (size_t)b * KVLEN * 512 + h * 64;
    const int* tm = tmask + b * LL;

    #pragma unroll
    for (int i = 0; i < 4; i++) {
        int f = tid + i * 256;
        int r = f >> 3, c = f & 7;
        cpa16(qB + r * 128 + ((c ^ (r & 7)) << 4), qb + (size_t)r * 512 + c * 8, true);
    }
    cpa_commit();

    auto loadKV = [&](int t, int st) {
        int kv0 = t * 64;
        unsigned kD = kB + st * 8192, vD = vB + st * 8192;
        #pragma unroll
        for (int i = 0; i < 2; i++) {
            int f = tid + i * 256;
            int r = f >> 3, c = f & 7;
            int kg = kv0 + r;
            bool ok = kg < KVLEN;
            cpa16(kD + r * 128 + ((c ^ (r & 7)) << 4), kb + (size_t)kg * 512 + c * 8, ok);
            cpa16(vD + r * 128 + ((c ^ (r & 7)) << 4), vb + (size_t)kg * 512 + c * 8, ok);
        }
        if (tid < 64) {
            int kg = kv0 + tid;
            float m = 0.f;
            if (kg >= KVLEN) m = NEGV;
            else if (kg >= NN && tm[kg - NN] == 0) m = NEGV;
            kmaskf[st * 64 + tid] = m;
        }
    };
    loadKV(0, 0);
    cpa_commit();

    float m_i[2] = {-1e30f, -1e30f}, l_i[2] = {0.f, 0.f}, o[8][4] = {};

    for (int t = 0; t < 18; t++) {
        __syncthreads();
        if (t + 1 < 18) { loadKV(t + 1, (t + 1) & 1); cpa_commit(); cpa_wait<1>(); }
        else            { cpa_wait<0>(); }
        __syncthreads();

        unsigned kC = kB + (t & 1) * 8192;
        unsigned vC = vB + (t & 1) * 8192;
        const float* km = kmaskf + (t & 1) * 64;

        // ---- S = Q K^T ----
        float s[8][4] = {};
        #pragma unroll
        for (int kc = 0; kc < 8; kc += 2) {
            unsigned aq[4];
            {
                int r = wm + (lane & 15);
                int c = kc + (lane >> 4);
                ldsm4(aq[0], aq[1], aq[2], aq[3], qB + r * 128 + ((c ^ (r & 7)) << 4));
            }
            #pragma unroll
            for (int grp = 0; grp < 4; grp++) {
                int r = grp * 16 + (lane & 7) + ((lane >> 4) << 3);
                int c = kc + ((lane >> 3) & 1);
                unsigned r0, r1, r2, r3;
                ldsm4(r0, r1, r2, r3, kC + r * 128 + ((c ^ (r & 7)) << 4));
                unsigned bk0[2] = {r0, r1}, bk1[2] = {r2, r3};
                mma16(s[grp * 2], aq, bk0);
                mma16(s[grp * 2 + 1], aq, bk1);
            }
        }

        // ---- mask + online softmax ----
        #pragma unroll
        for (int j = 0; j < 8; j++) {
            float k0v = km[j * 8 + 2 * tg], k1v = km[j * 8 + 2 * tg + 1];
            s[j][0] += k0v; s[j][1] += k1v;
            s[j][2] += k0v; s[j][3] += k1v;
        }
        float mx0 = -1e30f, mx1 = -1e30f;
        #pragma unroll
        for (int j = 0; j < 8; j++) {
            mx0 = fmaxf(mx0, fmaxf(s[j][0], s[j][1]));
            mx1 = fmaxf(mx1, fmaxf(s[j][2], s[j][3]));
        }
        mx0 = fmaxf(mx0, __shfl_xor_sync(0xffffffffu, mx0, 1));
        mx0 = fmaxf(mx0, __shfl_xor_sync(0xffffffffu, mx0, 2));
        mx1 = fmaxf(mx1, __shfl_xor_sync(0xffffffffu, mx1, 1));
        mx1 = fmaxf(mx1, __shfl_xor_sync(0xffffffffu, mx1, 2));
        float mn0 = fmaxf(m_i[0], mx0), mn1 = fmaxf(m_i[1], mx1);
        float al0 = __expf(m_i[0] - mn0), al1 = __expf(m_i[1] - mn1);
        m_i[0] = mn0; m_i[1] = mn1;
        float sum0 = 0.f, sum1 = 0.f;
        int pr = wm + g;
        #pragma unroll
        for (int j = 0; j < 8; j++) {
            float p0 = __expf(s[j][0] - mn0);
            float p1 = __expf(s[j][1] - mn0);
            float p2 = __expf(s[j][2] - mn1);
            float p3 = __expf(s[j][3] - mn1);
            sum0 += p0 + p1; sum1 += p2 + p3;
            *(unsigned*)(psPtr + pr * 128 + ((j ^ (pr & 7)) << 4) + 4 * tg) =
                pack_bf16x2(p0, p1);
            *(unsigned*)(psPtr + (pr + 8) * 128 + ((j ^ (pr & 7)) << 4) + 4 * tg) =
                pack_bf16x2(p2, p3);
        }
        sum0 += __shfl_xor_sync(0xffffffffu, sum0, 1);
        sum0 += __shfl_xor_sync(0xffffffffu, sum0, 2);
        sum1 += __shfl_xor_sync(0xffffffffu, sum1, 1);
        sum1 += __shfl_xor_sync(0xffffffffu, sum1, 2);
        l_i[0] = l_i[0] * al0 + sum0;
        l_i[1] = l_i[1] * al1 + sum1;
        #pragma unroll
        for (int j = 0; j < 8; j++) {
            o[j][0] *= al0; o[j][1] *= al0;
            o[j][2] *= al1; o[j][3] *= al1;
        }
        __syncwarp();

        // ---- O += P V ----
        #pragma unroll
        for (int kc = 0; kc < 8; kc += 2) {     // kv16 steps
            unsigned ap[4];
            {
                int r = wm + (lane & 15);
                int c = kc + (lane >> 4);
                ldsm4(ap[0], ap[1], ap[2], ap[3], pB + r * 128 + ((c ^ (r & 7)) << 4));
            }
            #pragma unroll
            for (int grp = 0; grp < 4; grp++) {
                int r = kc * 8 + (lane & 15);
                int c = grp * 2 + (lane >> 4);
                unsigned r0, r1, r2, r3;
                ldsm4t(r0, r1, r2, r3, vC + r * 128 + ((c ^ (r & 7)) << 4));
                unsigned bv0[2] = {r0, r1}, bv1[2] = {r2, r3};
                mma16(o[grp * 2], ap, bv0);
                mma16(o[grp * 2 + 1], ap, bv1);
            }
        }
        __syncwarp();
    }

    // ---- write O (bf16) ----
    __nv_bfloat16* ob = Og + (size_t)(b * NN + qt * 128) * 512 + h * 64;
    #pragma unroll
    for (int rs = 0; rs < 2; rs++) {
        int r = wm + g + rs * 8;
        float inv = 1.f / l_i[rs];
        #pragma unroll
        for (int j = 0; j < 8; j++) {
            int col = j * 8 + 2 * tg;
            *(unsigned*)(ob + (size_t)r * 512 + col) =
                pack_bf16x2(o[j][rs * 2 + 0] * inv, o[j][rs * 2 + 1] * inv);
        }
    }
}

// =====================================================================
// launch
// =====================================================================
extern "C" void kernel_launch(void* const* d_in, const int* in_sizes, int n_in,
                              void* d_out, int out_size)
{
    const float* x    = (const float*)d_in[0];
    const float* te   = (const float*)d_in[1];
    const int*   tmk  = (const int*)  d_in[2];
    const float* gqs  = (const float*)d_in[3];
    const float* gqb  = (const float*)d_in[4];
    const float* gks  = (const float*)d_in[5];
    const float* gkb  = (const float*)d_in[6];
    const float* gts  = (const float*)d_in[7];
    const float* gtb  = (const float*)d_in[8];
    const float* Wq   = (const float*)d_in[9];
    const float* Wks  = (const float*)d_in[10];
    const float* Wvs  = (const float*)d_in[11];
    const float* Wkc  = (const float*)d_in[12];
    const float* Wvc  = (const float*)d_in[13];
    const float* Wout = (const float*)d_in[14];
    float* out = (float*)d_out;

    float* scratch = nullptr;
    cudaGetSymbolAddress((void**)&scratch, g_scratch);
    __nv_bfloat16* bs = (__nv_bfloat16*)scratch;
    __nv_bfloat16* XQ   = bs + BOFF_XQ;
    __nv_bfloat16* XKV  = bs + BOFF_XKV;
    __nv_bfloat16* Tb   = bs + BOFF_T;
    __nv_bfloat16* Qb   = bs + BOFF_Q;
    __nv_bfloat16* Kb   = bs + BOFF_K;
    __nv_bfloat16* Vb   = bs + BOFF_V;
    __nv_bfloat16* ATTb = bs + BOFF_ATT;
    __nv_bfloat16* Wb   = bs + BOFF_W;

    cudaFuncSetAttribute(gemm_bf16, cudaFuncAttributeMaxDynamicSharedMemorySize, GEMM_SMEM);
    cudaFuncSetAttribute(attn_bf16, cudaFuncAttributeMaxDynamicSharedMemorySize, ATT_SMEM);

    wconv_kernel<<<1536, 256>>>(Wq, Wks, Wvs, Wkc, Wvc, Wout, Wb);
    gn_img_kernel<<<512, 256>>>(x, gqs, gqb, gks, gkb, XQ, XKV);
    gn_txt_kernel<<<512, 128>>>(te, gts, gtb, Tb);

    __nv_bfloat16* WqB  = Wb;
    __nv_bfloat16* WksB = Wb + 262144;
    __nv_bfloat16* WvsB = Wb + 2 * 262144;
    __nv_bfloat16* WkcB = Wb + 3 * 262144;
    __nv_bfloat16* WvcB = Wb + 4 * 262144;
    __nv_bfloat16* WoB  = Wb + 5 * 262144;

    gemm_bf16<<<dim3(128, 4), 256, GEMM_SMEM>>>(XQ,  WqB,  Qb, nullptr, 16384, 1024, 1024,  0, 0.125f, 1);
    gemm_bf16<<<dim3(128, 4), 256, GEMM_SMEM>>>(XKV, WksB, Kb, nullptr, 16384, 1024, KVLEN, 0, 1.f, 1);
    gemm_bf16<<<dim3(128, 4), 256, GEMM_SMEM>>>(XKV, WvsB, Vb, nullptr, 16384, 1024, KVLEN, 0, 1.f, 1);
    gemm_bf16<<<dim3(10, 4),  256, GEMM_SMEM>>>(Tb,  WkcB, Kb, nullptr, 1232,  77,   KVLEN, 1024, 1.f, 1);
    gemm_bf16<<<dim3(10, 4),  256, GEMM_SMEM>>>(Tb,  WvcB, Vb, nullptr, 1232,  77,   KVLEN, 1024, 1.f, 1);

    attn_bf16<<<dim3(8, NHH, BB), 256, ATT_SMEM>>>(tmk, Qb, Kb, Vb, ATTb);

    gemm_bf16<<<dim3(128, 4), 256, GEMM_SMEM>>>(ATTb, WoB, out, x, 16384, 1024, 1024, 0, 1.f, 0);
}

// round 5
// speedup vs baseline: 9.0032x; 1.0638x over previous
#include <cuda_runtime.h>
#include <cuda_bf16.h>
#include <math.h>

// ---------------- problem constants ----------------
#define BB    16
#define NN    1024
#define CC    512
#define LL    77
#define KVLEN 1101
#define NHH   8
#define HDD   64
#define CPG   16
#define EPSV  1e-6f
#define NEGV  -1e10f
#define LOG2E 1.44269504089f

// ---------------- scratch ----------------
__device__ float g_scratch[52224000];

// bf16-element offsets into scratch
#define BOFF_XQ   ((size_t)0)
#define BOFF_XKV  ((size_t)8388608)
#define BOFF_T    ((size_t)16777216)
#define BOFF_Q    ((size_t)17408000)
#define BOFF_K    ((size_t)25796608)
#define BOFF_V    ((size_t)34816000)
#define BOFF_ATT  ((size_t)43835392)
#define BOFF_W    ((size_t)52224000)

// ---------------- helpers ----------------
__device__ __forceinline__ unsigned pack_bf16x2(float lo, float hi) {
    unsigned r;
    asm("cvt.rn.bf16x2.f32 %0, %1, %2;" : "=r"(r) : "f"(hi), "f"(lo));
    return r;
}
__device__ __forceinline__ float ex2f(float x) {
    float r; asm("ex2.approx.ftz.f32 %0, %1;" : "=f"(r) : "f"(x)); return r;
}
__device__ __forceinline__ void mma16(float* c, const unsigned* a, const unsigned* b) {
    asm volatile(
        "mma.sync.aligned.m16n8k16.row.col.f32.bf16.bf16.f32 "
        "{%0,%1,%2,%3},{%4,%5,%6,%7},{%8,%9},{%0,%1,%2,%3};\n"
        : "+f"(c[0]), "+f"(c[1]), "+f"(c[2]), "+f"(c[3])
        : "r"(a[0]), "r"(a[1]), "r"(a[2]), "r"(a[3]), "r"(b[0]), "r"(b[1]));
}
__device__ __forceinline__ void ldsm4(unsigned& r0, unsigned& r1, unsigned& r2, unsigned& r3,
                                      unsigned addr) {
    asm volatile("ldmatrix.sync.aligned.m8n8.x4.shared.b16 {%0,%1,%2,%3}, [%4];"
                 : "=r"(r0), "=r"(r1), "=r"(r2), "=r"(r3) : "r"(addr));
}
__device__ __forceinline__ void ldsm4t(unsigned& r0, unsigned& r1, unsigned& r2, unsigned& r3,
                                       unsigned addr) {
    asm volatile("ldmatrix.sync.aligned.m8n8.x4.trans.shared.b16 {%0,%1,%2,%3}, [%4];"
                 : "=r"(r0), "=r"(r1), "=r"(r2), "=r"(r3) : "r"(addr));
}
__device__ __forceinline__ void cpa16(unsigned dst, const void* src, bool p) {
    int sz = p ? 16 : 0;
    asm volatile("cp.async.cg.shared.global [%0], [%1], 16, %2;\n"
                 :: "r"(dst), "l"(src), "r"(sz));
}
__device__ __forceinline__ void cpa_commit() { asm volatile("cp.async.commit_group;\n"); }
template<int N> __device__ __forceinline__ void cpa_wait() {
    asm volatile("cp.async.wait_group %0;\n" :: "n"(N));
}

// =====================================================================
// Weight conversion fp32 -> bf16 (6 matrices of 512x512, [k][n])
// =====================================================================
__global__ void wconv_kernel(const float* __restrict__ w0, const float* __restrict__ w1,
                             const float* __restrict__ w2, const float* __restrict__ w3,
                             const float* __restrict__ w4, const float* __restrict__ w5,
                             __nv_bfloat16* __restrict__ out)
{
    int gid = blockIdx.x * 256 + threadIdx.x;
    int mat = gid >> 16;
    int idx = (gid & 65535) << 2;
    const float* src = mat == 0 ? w0 : mat == 1 ? w1 : mat == 2 ? w2
                     : mat == 3 ? w3 : mat == 4 ? w4 : w5;
    float4 v = *(const float4*)(src + idx);
    uint2 p;
    p.x = pack_bf16x2(v.x, v.y);
    p.y = pack_bf16x2(v.z, v.w);
    *(uint2*)(out + (size_t)mat * 262144 + idx) = p;
}

// =====================================================================
// GroupNorm over image: single gmem read via 64KB smem slice cache.
// =====================================================================
#define GN_SMEM (NN * CPG * 4)

__global__ void __launch_bounds__(256, 3)
gn_img_kernel(const float* __restrict__ x,
              const float* __restrict__ qsc, const float* __restrict__ qbi,
              const float* __restrict__ ksc, const float* __restrict__ kbi,
              __nv_bfloat16* __restrict__ oq, __nv_bfloat16* __restrict__ okv)
{
    extern __shared__ float xs[];   // [1024][16]
    int b = blockIdx.x >> 5, g = blockIdx.x & 31;
    const float* xb = x + (size_t)b * NN * CC + g * CPG;
    int tid = threadIdx.x;

    float s = 0.f, s2 = 0.f;
    for (int e = tid; e < NN * 4; e += 256) {
        int n = e >> 2, c4 = (e & 3) << 2;
        float4 v = *(const float4*)(xb + (size_t)n * CC + c4);
        *(float4*)(xs + n * CPG + c4) = v;
        s  += v.x + v.y + v.z + v.w;
        s2 += v.x * v.x + v.y * v.y + v.z * v.z + v.w * v.w;
    }
    #pragma unroll
    for (int o2 = 16; o2; o2 >>= 1) {
        s  += __shfl_xor_sync(0xffffffffu, s,  o2);
        s2 += __shfl_xor_sync(0xffffffffu, s2, o2);
    }
    __shared__ float sh[8], sh2[8];
    int w = tid >> 5, lane = tid & 31;
    if (lane == 0) { sh[w] = s; sh2[w] = s2; }
    __syncthreads();

    __shared__ float cq[2][CPG], ck[2][CPG];
    if (tid < CPG) {
        float ts = 0.f, ts2 = 0.f;
        #pragma unroll
        for (int i = 0; i < 8; i++) { ts += sh[i]; ts2 += sh2[i]; }
        const float cnt = (float)(NN * CPG);
        float mu  = ts / cnt;
        float var = ts2 / cnt - mu * mu;
        float inv = rsqrtf(var + EPSV);
        int c = g * CPG + tid;
        float aq = inv * qsc[c];
        cq[0][tid] = aq;  cq[1][tid] = qbi[c] - mu * aq;
        float ak = inv * ksc[c];
        ck[0][tid] = ak;  ck[1][tid] = kbi[c] - mu * ak;
    }
    __syncthreads();

    __nv_bfloat16* oqb  = oq  + (size_t)b * NN * CC + g * CPG;
    __nv_bfloat16* okvb = okv + (size_t)b * NN * CC + g * CPG;
    for (int e = tid; e < NN * 4; e += 256) {
        int n = e >> 2, c4 = (e & 3) << 2;
        float4 v = *(const float4*)(xs + n * CPG + c4);
        uint2 pq, pk;
        pq.x = pack_bf16x2(v.x * cq[0][c4+0] + cq[1][c4+0], v.y * cq[0][c4+1] + cq[1][c4+1]);
        pq.y = pack_bf16x2(v.z * cq[0][c4+2] + cq[1][c4+2], v.w * cq[0][c4+3] + cq[1][c4+3]);
        pk.x = pack_bf16x2(v.x * ck[0][c4+0] + ck[1][c4+0], v.y * ck[0][c4+1] + ck[1][c4+1]);
        pk.y = pack_bf16x2(v.z * ck[0][c4+2] + ck[1][c4+2], v.w * ck[0][c4+3] + ck[1][c4+3]);
        *(uint2*)(oqb  + (size_t)n * CC + c4) = pq;
        *(uint2*)(okvb + (size_t)n * CC + c4) = pk;
    }
}

// =====================================================================
// GroupNorm over text
// =====================================================================
__global__ void gn_txt_kernel(const float* __restrict__ t,
                              const float* __restrict__ tsc, const float* __restrict__ tbi,
                              __nv_bfloat16* __restrict__ ot)
{
    int b = blockIdx.x >> 5, g = blockIdx.x & 31;
    const float* xb = t + (size_t)b * LL * CC + g * CPG;
    int tid = threadIdx.x;

    float s = 0.f, s2 = 0.f;
    for (int e = tid; e < LL * 4; e += 128) {
        int n = e >> 2, c4 = (e & 3) << 2;
        float4 v = *(const float4*)(xb + (size_t)n * CC + c4);
        s  += v.x + v.y + v.z + v.w;
        s2 += v.x * v.x + v.y * v.y + v.z * v.z + v.w * v.w;
    }
    #pragma unroll
    for (int o2 = 16; o2; o2 >>= 1) {
        s  += __shfl_xor_sync(0xffffffffu, s,  o2);
        s2 += __shfl_xor_sync(0xffffffffu, s2, o2);
    }
    __shared__ float sh[4], sh2[4];
    int w = tid >> 5, lane = tid & 31;
    if (lane == 0) { sh[w] = s; sh2[w] = s2; }
    __syncthreads();

    __shared__ float ct[2][CPG];
    if (tid < CPG) {
        float ts = 0.f, ts2 = 0.f;
        #pragma unroll
        for (int i = 0; i < 4; i++) { ts += sh[i]; ts2 += sh2[i]; }
        const float cnt = (float)(LL * CPG);
        float mu  = ts / cnt;
        float var = ts2 / cnt - mu * mu;
        float inv = rsqrtf(var + EPSV);
        int c = g * CPG + tid;
        float a = inv * tsc[c];
        ct[0][tid] = a;  ct[1][tid] = tbi[c] - mu * a;
    }
    __syncthreads();

    __nv_bfloat16* ob = ot + (size_t)b * LL * CC + g * CPG;
    for (int e = tid; e < LL * 4; e += 128) {
        int n = e >> 2, c4 = (e & 3) << 2;
        float4 v = *(const float4*)(xb + (size_t)n * CC + c4);
        uint2 p;
        p.x = pack_bf16x2(v.x * ct[0][c4+0] + ct[1][c4+0], v.y * ct[0][c4+1] + ct[1][c4+1]);
        p.y = pack_bf16x2(v.z * ct[0][c4+2] + ct[1][c4+2], v.w * ct[0][c4+3] + ct[1][c4+3]);
        *(uint2*)(ob + (size_t)n * CC + c4) = p;
    }
}

// =====================================================================
// BF16 GEMM, 3-stage cp.async pipeline, BK=64, one sync per tile.
// Block 128x128, 256 threads (8 warps, 64x32 warp tiles).
// =====================================================================
#define GEMM_SMEM 98304

__global__ void __launch_bounds__(256, 2)
gemm_bf16(const __nv_bfloat16* __restrict__ A, const __nv_bfloat16* __restrict__ W,
          void* __restrict__ OutP, const float* __restrict__ Res,
          int M, int rows_per_b, int out_rows_per_b, int out_off,
          float alpha, int outBf16)
{
    extern __shared__ char smc[];
    unsigned aBase = (unsigned)__cvta_generic_to_shared(smc);   // [3][128][128B]
    unsigned bBase = aBase + 3 * 16384;                         // [3][64][256B]

    int tid = threadIdx.x, warp = tid >> 5, lane = tid & 31;
    int g = lane >> 2, tg = lane & 3;
    int wm = (warp >> 2) * 64, wn = (warp & 3) * 32;
    int m0 = blockIdx.x * 128, n0 = blockIdx.y * 128;

    float acc[4][4][4] = {};

    auto loadTile = [&](int kt, int st) {
        int k0 = kt * 64;
        unsigned aD = aBase + st * 16384;
        unsigned bD = bBase + st * 16384;
        #pragma unroll
        for (int i = 0; i < 4; i++) {
            int f = tid + i * 256;
            int r = f >> 3, c = f & 7;
            bool ok = (m0 + r) < M;
            cpa16(aD + r * 128 + ((c ^ (r & 7)) << 4),
                  A + (size_t)(m0 + r) * 512 + k0 + c * 8, ok);
        }
        #pragma unroll
        for (int i = 0; i < 4; i++) {
            int f = tid + i * 256;
            int r = f >> 4, c = f & 15;
            cpa16(bD + r * 256 + ((c ^ (r & 7)) << 4),
                  W + (size_t)(k0 + r) * 512 + n0 + c * 8, true);
        }
    };
    loadTile(0, 0); cpa_commit();
    loadTile(1, 1); cpa_commit();

    int st = 0;
    for (int t = 0; t < 8; t++) {
        cpa_wait<1>();
        __syncthreads();
        if (t + 2 < 8) {
            int ns = st + 2; if (ns >= 3) ns -= 3;
            loadTile(t + 2, ns);
            cpa_commit();
        }

        unsigned aC = aBase + st * 16384;
        unsigned bC = bBase + st * 16384;
        #pragma unroll
        for (int kc = 0; kc < 8; kc += 2) {
            unsigned af[4][4];
            #pragma unroll
            for (int i = 0; i < 4; i++) {
                int r = wm + i * 16 + (lane & 15);
                int c = kc + (lane >> 4);
                ldsm4(af[i][0], af[i][1], af[i][2], af[i][3],
                      aC + r * 128 + ((c ^ (r & 7)) << 4));
            }
            unsigned bfr[4][2];
            #pragma unroll
            for (int grp = 0; grp < 2; grp++) {
                int r = kc * 8 + (lane & 15);
                int c = (wn >> 3) + 2 * grp + (lane >> 4);
                unsigned r0, r1, r2, r3;
                ldsm4t(r0, r1, r2, r3, bC + r * 256 + ((c ^ (r & 7)) << 4));
                bfr[grp*2][0] = r0;   bfr[grp*2][1] = r1;
                bfr[grp*2+1][0] = r2; bfr[grp*2+1][1] = r3;
            }
            #pragma unroll
            for (int i = 0; i < 4; i++)
                #pragma unroll
                for (int j = 0; j < 4; j++)
                    mma16(acc[i][j], af[i], bfr[j]);
        }
        if (++st == 3) st = 0;
    }

    #pragma unroll
    for (int i = 0; i < 4; i++) {
        #pragma unroll
        for (int rs = 0; rs < 2; rs++) {
            int gm = m0 + wm + i * 16 + g + rs * 8;
            if (gm >= M) continue;
            int bbi = gm / rows_per_b;
            int rr  = gm - bbi * rows_per_b;
            size_t orow = (size_t)bbi * out_rows_per_b + out_off + rr;
            #pragma unroll
            for (int j = 0; j < 4; j++) {
                int col = n0 + wn + j * 8 + 2 * tg;
                float v0 = acc[i][j][rs * 2 + 0] * alpha;
                float v1 = acc[i][j][rs * 2 + 1] * alpha;
                if (outBf16) {
                    *(unsigned*)((__nv_bfloat16*)OutP + orow * 512 + col) =
                        pack_bf16x2(v0, v1);
                } else {
                    if (Res) {
                        float2 rv = *(const float2*)(Res + orow * 512 + col);
                        v0 += rv.x; v1 += rv.y;
                    }
                    *(float2*)((float*)OutP + orow * 512 + col) = make_float2(v0, v1);
                }
            }
        }
    }
}

// =====================================================================
// BF16 flash attention: 4 warps, 64 q-rows per block, KV tiles of 64,
// double-buffered cp.async, log2-domain softmax (single EX2 per element).
// smem 48.5KB -> 4 blocks/SM.
// =====================================================================
#define ATT_SMEM (49152 + 512)

__global__ void __launch_bounds__(128, 4)
attn_bf16(const int* __restrict__ tmask,
          const __nv_bfloat16* __restrict__ Qg,
          const __nv_bfloat16* __restrict__ Kg,
          const __nv_bfloat16* __restrict__ Vg,
          __nv_bfloat16* __restrict__ Og)
{
    extern __shared__ char smc[];
    unsigned qB = (unsigned)__cvta_generic_to_shared(smc);  // [64][128B]
    unsigned kB = qB + 8192;                                // [2][64][128B]
    unsigned vB = kB + 16384;                               // [2][64][128B]
    unsigned pB = vB + 16384;                               // [64][128B]
    char* psPtr = smc + 40960;
    float* kmaskf = (float*)(smc + 49152);                  // [2][64]

    int qt = blockIdx.x, h = blockIdx.y, b = blockIdx.z;
    int tid = threadIdx.x, warp = tid >> 5, lane = tid & 31;
    int g = lane >> 2, tg = lane & 3;
    int wm = warp * 16;

    const __nv_bfloat16* qb = Qg + (size_t)(b * NN + qt * 64) * 512 + h * 64;
    const __nv_bfloat16* kb = Kg + (size_t)b * KVLEN * 512 + h * 64;
    const __nv_bfloat16* vb = Vg + (size_t)b * KVLEN * 512 + h * 64;
    const int* tm = tmask + b * LL;

    #pragma unroll
    for (int i = 0; i < 4; i++) {
        int f = tid + i * 128;
        int r = f >> 3, c = f & 7;
        cpa16(qB + r * 128 + ((c ^ (r & 7)) << 4), qb + (size_t)r * 512 + c * 8, true);
    }
    cpa_commit();

    auto loadKV = [&](int t, int st) {
        int kv0 = t * 64;
        unsigned kD = kB + st * 8192, vD = vB + st * 8192;
        #pragma unroll
        for (int i = 0; i < 4; i++) {
            int f = tid + i * 128;
            int r = f >> 3, c = f & 7;
            int kg = kv0 + r;
            bool ok = kg < KVLEN;
            cpa16(kD + r * 128 + ((c ^ (r & 7)) << 4), kb + (size_t)kg * 512 + c * 8, ok);
            cpa16(vD + r * 128 + ((c ^ (r & 7)) << 4), vb + (size_t)kg * 512 + c * 8, ok);
        }
        if (tid < 64) {
            int kg = kv0 + tid;
            float m = 0.f;
            if (kg >= KVLEN) m = NEGV * LOG2E;
            else if (kg >= NN && tm[kg - NN] == 0) m = NEGV * LOG2E;
            kmaskf[st * 64 + tid] = m;
        }
    };
    loadKV(0, 0);
    cpa_commit();

    float m_i[2] = {-1e30f, -1e30f}, l_i[2] = {0.f, 0.f}, o[8][4] = {};

    for (int t = 0; t < 18; t++) {
        __syncthreads();
        if (t + 1 < 18) { loadKV(t + 1, (t + 1) & 1); cpa_commit(); cpa_wait<1>(); }
        else            { cpa_wait<0>(); }
        __syncthreads();

        unsigned kC = kB + (t & 1) * 8192;
        unsigned vC = vB + (t & 1) * 8192;
        const float* km = kmaskf + (t & 1) * 64;

        // ---- S = Q K^T (log2-domain logits: LOG2E folded into Q) ----
        float s[8][4] = {};
        #pragma unroll
        for (int kc = 0; kc < 8; kc += 2) {
            unsigned aq[4];
            {
                int r = wm + (lane & 15);
                int c = kc + (lane >> 4);
                ldsm4(aq[0], aq[1], aq[2], aq[3], qB + r * 128 + ((c ^ (r & 7)) << 4));
            }
            #pragma unroll
            for (int grp = 0; grp < 4; grp++) {
                int r = grp * 16 + (lane & 7) + ((lane >> 4) << 3);
                int c = kc + ((lane >> 3) & 1);
                unsigned r0, r1, r2, r3;
                ldsm4(r0, r1, r2, r3, kC + r * 128 + ((c ^ (r & 7)) << 4));
                unsigned bk0[2] = {r0, r1}, bk1[2] = {r2, r3};
                mma16(s[grp * 2], aq, bk0);
                mma16(s[grp * 2 + 1], aq, bk1);
            }
        }

        // ---- mask + online softmax (exp2) ----
        #pragma unroll
        for (int j = 0; j < 8; j++) {
            float k0v = km[j * 8 + 2 * tg], k1v = km[j * 8 + 2 * tg + 1];
            s[j][0] += k0v; s[j][1] += k1v;
            s[j][2] += k0v; s[j][3] += k1v;
        }
        float mx0 = -1e30f, mx1 = -1e30f;
        #pragma unroll
        for (int j = 0; j < 8; j++) {
            mx0 = fmaxf(mx0, fmaxf(s[j][0], s[j][1]));
            mx1 = fmaxf(mx1, fmaxf(s[j][2], s[j][3]));
        }
        mx0 = fmaxf(mx0, __shfl_xor_sync(0xffffffffu, mx0, 1));
        mx0 = fmaxf(mx0, __shfl_xor_sync(0xffffffffu, mx0, 2));
        mx1 = fmaxf(mx1, __shfl_xor_sync(0xffffffffu, mx1, 1));
        mx1 = fmaxf(mx1, __shfl_xor_sync(0xffffffffu, mx1, 2));
        float mn0 = fmaxf(m_i[0], mx0), mn1 = fmaxf(m_i[1], mx1);
        float al0 = ex2f(m_i[0] - mn0), al1 = ex2f(m_i[1] - mn1);
        m_i[0] = mn0; m_i[1] = mn1;
        float sum0 = 0.f, sum1 = 0.f;
        int pr = wm + g;
        #pragma unroll
        for (int j = 0; j < 8; j++) {
            float p0 = ex2f(s[j][0] - mn0);
            float p1 = ex2f(s[j][1] - mn0);
            float p2 = ex2f(s[j][2] - mn1);
            float p3 = ex2f(s[j][3] - mn1);
            sum0 += p0 + p1; sum1 += p2 + p3;
            *(unsigned*)(psPtr + pr * 128 + ((j ^ (pr & 7)) << 4) + 4 * tg) =
                pack_bf16x2(p0, p1);
            *(unsigned*)(psPtr + (pr + 8) * 128 + ((j ^ (pr & 7)) << 4) + 4 * tg) =
                pack_bf16x2(p2, p3);
        }
        sum0 += __shfl_xor_sync(0xffffffffu, sum0, 1);
        sum0 += __shfl_xor_sync(0xffffffffu, sum0, 2);
        sum1 += __shfl_xor_sync(0xffffffffu, sum1, 1);
        sum1 += __shfl_xor_sync(0xffffffffu, sum1, 2);
        l_i[0] = l_i[0] * al0 + sum0;
        l_i[1] = l_i[1] * al1 + sum1;
        #pragma unroll
        for (int j = 0; j < 8; j++) {
            o[j][0] *= al0; o[j][1] *= al0;
            o[j][2] *= al1; o[j][3] *= al1;
        }
        __syncwarp();

        // ---- O += P V ----
        #pragma unroll
        for (int kc = 0; kc < 8; kc += 2) {
            unsigned ap[4];
            {
                int r = wm + (lane & 15);
                int c = kc + (lane >> 4);
                ldsm4(ap[0], ap[1], ap[2], ap[3], pB + r * 128 + ((c ^ (r & 7)) << 4));
            }
            #pragma unroll
            for (int grp = 0; grp < 4; grp++) {
                int r = kc * 8 + (lane & 15);
                int c = grp * 2 + (lane >> 4);
                unsigned r0, r1, r2, r3;
                ldsm4t(r0, r1, r2, r3, vC + r * 128 + ((c ^ (r & 7)) << 4));
                unsigned bv0[2] = {r0, r1}, bv1[2] = {r2, r3};
                mma16(o[grp * 2], ap, bv0);
                mma16(o[grp * 2 + 1], ap, bv1);
            }
        }
        __syncwarp();
    }

    __nv_bfloat16* ob = Og + (size_t)(b * NN + qt * 64) * 512 + h * 64;
    #pragma unroll
    for (int rs = 0; rs < 2; rs++) {
        int r = wm + g + rs * 8;
        float inv = 1.f / l_i[rs];
        #pragma unroll
        for (int j = 0; j < 8; j++) {
            int col = j * 8 + 2 * tg;
            *(unsigned*)(ob + (size_t)r * 512 + col) =
                pack_bf16x2(o[j][rs * 2 + 0] * inv, o[j][rs * 2 + 1] * inv);
        }
    }
}

// =====================================================================
// launch
// =====================================================================
extern "C" void kernel_launch(void* const* d_in, const int* in_sizes, int n_in,
                              void* d_out, int out_size)
{
    const float* x    = (const float*)d_in[0];
    const float* te   = (const float*)d_in[1];
    const int*   tmk  = (const int*)  d_in[2];
    const float* gqs  = (const float*)d_in[3];
    const float* gqb  = (const float*)d_in[4];
    const float* gks  = (const float*)d_in[5];
    const float* gkb  = (const float*)d_in[6];
    const float* gts  = (const float*)d_in[7];
    const float* gtb  = (const float*)d_in[8];
    const float* Wq   = (const float*)d_in[9];
    const float* Wks  = (const float*)d_in[10];
    const float* Wvs  = (const float*)d_in[11];
    const float* Wkc  = (const float*)d_in[12];
    const float* Wvc  = (const float*)d_in[13];
    const float* Wout = (const float*)d_in[14];
    float* out = (float*)d_out;

    float* scratch = nullptr;
    cudaGetSymbolAddress((void**)&scratch, g_scratch);
    __nv_bfloat16* bs = (__nv_bfloat16*)scratch;
    __nv_bfloat16* XQ   = bs + BOFF_XQ;
    __nv_bfloat16* XKV  = bs + BOFF_XKV;
    __nv_bfloat16* Tb   = bs + BOFF_T;
    __nv_bfloat16* Qb   = bs + BOFF_Q;
    __nv_bfloat16* Kb   = bs + BOFF_K;
    __nv_bfloat16* Vb   = bs + BOFF_V;
    __nv_bfloat16* ATTb = bs + BOFF_ATT;
    __nv_bfloat16* Wb   = bs + BOFF_W;

    cudaFuncSetAttribute(gemm_bf16, cudaFuncAttributeMaxDynamicSharedMemorySize, GEMM_SMEM);
    cudaFuncSetAttribute(attn_bf16, cudaFuncAttributeMaxDynamicSharedMemorySize, ATT_SMEM);
    cudaFuncSetAttribute(gn_img_kernel, cudaFuncAttributeMaxDynamicSharedMemorySize, GN_SMEM);

    wconv_kernel<<<1536, 256>>>(Wq, Wks, Wvs, Wkc, Wvc, Wout, Wb);
    gn_img_kernel<<<512, 256, GN_SMEM>>>(x, gqs, gqb, gks, gkb, XQ, XKV);
    gn_txt_kernel<<<512, 128>>>(te, gts, gtb, Tb);

    __nv_bfloat16* WqB  = Wb;
    __nv_bfloat16* WksB = Wb + 262144;
    __nv_bfloat16* WvsB = Wb + 2 * 262144;
    __nv_bfloat16* WkcB = Wb + 3 * 262144;
    __nv_bfloat16* WvcB = Wb + 4 * 262144;
    __nv_bfloat16* WoB  = Wb + 5 * 262144;

    // Q projection: fold 1/sqrt(64) * log2(e) so attention softmax is exp2-only.
    gemm_bf16<<<dim3(128, 4), 256, GEMM_SMEM>>>(XQ,  WqB,  Qb, nullptr, 16384, 1024, 1024,  0, 0.125f * LOG2E, 1);
    gemm_bf16<<<dim3(128, 4), 256, GEMM_SMEM>>>(XKV, WksB, Kb, nullptr, 16384, 1024, KVLEN, 0, 1.f, 1);
    gemm_bf16<<<dim3(128, 4), 256, GEMM_SMEM>>>(XKV, WvsB, Vb, nullptr, 16384, 1024, KVLEN, 0, 1.f, 1);
    gemm_bf16<<<dim3(10, 4),  256, GEMM_SMEM>>>(Tb,  WkcB, Kb, nullptr, 1232,  77,   KVLEN, 1024, 1.f, 1);
    gemm_bf16<<<dim3(10, 4),  256, GEMM_SMEM>>>(Tb,  WvcB, Vb, nullptr, 1232,  77,   KVLEN, 1024, 1.f, 1);

    attn_bf16<<<dim3(16, NHH, BB), 128, ATT_SMEM>>>(tmk, Qb, Kb, Vb, ATTb);

    gemm_bf16<<<dim3(128, 4), 256, GEMM_SMEM>>>(ATTb, WoB, out, x, 16384, 1024, 1024, 0, 1.f, 0);
}

// round 7
// speedup vs baseline: 9.5807x; 1.0641x over previous
#include <cuda_runtime.h>
#include <cuda_bf16.h>
#include <math.h>

// ---------------- problem constants ----------------
#define BB    16
#define NN    1024
#define CC    512
#define LL    77
#define KVLEN 1101
#define NHH   8
#define HDD   64
#define CPG   16
#define EPSV  1e-6f
#define NEGV  -1e10f
#define LOG2E 1.44269504089f

// ---------------- scratch ----------------
__device__ float g_scratch[52224000];

#define BOFF_XQ   ((size_t)0)
#define BOFF_XKV  ((size_t)8388608)
#define BOFF_T    ((size_t)16777216)
#define BOFF_Q    ((size_t)17408000)
#define BOFF_K    ((size_t)25796608)
#define BOFF_V    ((size_t)34816000)
#define BOFF_ATT  ((size_t)43835392)
#define BOFF_W    ((size_t)52224000)

// ---------------- helpers ----------------
__device__ __forceinline__ unsigned pack_bf16x2(float lo, float hi) {
    unsigned r;
    asm("cvt.rn.bf16x2.f32 %0, %1, %2;" : "=r"(r) : "f"(hi), "f"(lo));
    return r;
}
__device__ __forceinline__ float ex2f(float x) {
    float r; asm("ex2.approx.ftz.f32 %0, %1;" : "=f"(r) : "f"(x)); return r;
}
__device__ __forceinline__ void mma16(float* c, const unsigned* a, const unsigned* b) {
    asm volatile(
        "mma.sync.aligned.m16n8k16.row.col.f32.bf16.bf16.f32 "
        "{%0,%1,%2,%3},{%4,%5,%6,%7},{%8,%9},{%0,%1,%2,%3};\n"
        : "+f"(c[0]), "+f"(c[1]), "+f"(c[2]), "+f"(c[3])
        : "r"(a[0]), "r"(a[1]), "r"(a[2]), "r"(a[3]), "r"(b[0]), "r"(b[1]));
}
__device__ __forceinline__ void ldsm4(unsigned& r0, unsigned& r1, unsigned& r2, unsigned& r3,
                                      unsigned addr) {
    asm volatile("ldmatrix.sync.aligned.m8n8.x4.shared.b16 {%0,%1,%2,%3}, [%4];"
                 : "=r"(r0), "=r"(r1), "=r"(r2), "=r"(r3) : "r"(addr));
}
__device__ __forceinline__ void ldsm4t(unsigned& r0, unsigned& r1, unsigned& r2, unsigned& r3,
                                       unsigned addr) {
    asm volatile("ldmatrix.sync.aligned.m8n8.x4.trans.shared.b16 {%0,%1,%2,%3}, [%4];"
                 : "=r"(r0), "=r"(r1), "=r"(r2), "=r"(r3) : "r"(addr));
}
__device__ __forceinline__ void cpa16(unsigned dst, const void* src, bool p) {
    int sz = p ? 16 : 0;
    asm volatile("cp.async.cg.shared.global [%0], [%1], 16, %2;\n"
                 :: "r"(dst), "l"(src), "r"(sz));
}
__device__ __forceinline__ void cpa_commit() { asm volatile("cp.async.commit_group;\n"); }
template<int N> __device__ __forceinline__ void cpa_wait() {
    asm volatile("cp.async.wait_group %0;\n" :: "n"(N));
}

// =====================================================================
// Weight conversion fp32 -> bf16 (6 matrices of 512x512, [k][n])
// =====================================================================
__global__ void wconv_kernel(const float* __restrict__ w0, const float* __restrict__ w1,
                             const float* __restrict__ w2, const float* __restrict__ w3,
                             const float* __restrict__ w4, const float* __restrict__ w5,
                             __nv_bfloat16* __restrict__ out)
{
    int gid = blockIdx.x * 256 + threadIdx.x;
    int mat = gid >> 16;
    int idx = (gid & 65535) << 2;
    const float* src = mat == 0 ? w0 : mat == 1 ? w1 : mat == 2 ? w2
                     : mat == 3 ? w3 : mat == 4 ? w4 : w5;
    float4 v = *(const float4*)(src + idx);
    uint2 p;
    p.x = pack_bf16x2(v.x, v.y);
    p.y = pack_bf16x2(v.z, v.w);
    *(uint2*)(out + (size_t)mat * 262144 + idx) = p;
}

// =====================================================================
// GroupNorm over image (smem slice cache; bf16 x_q / x_kv outputs)
// =====================================================================
#define GN_SMEM (NN * CPG * 4)

__global__ void __launch_bounds__(256, 3)
gn_img_kernel(const float* __restrict__ x,
              const float* __restrict__ qsc, const float* __restrict__ qbi,
              const float* __restrict__ ksc, const float* __restrict__ kbi,
              __nv_bfloat16* __restrict__ oq, __nv_bfloat16* __restrict__ okv)
{
    extern __shared__ float xs[];
    int b = blockIdx.x >> 5, g = blockIdx.x & 31;
    const float* xb = x + (size_t)b * NN * CC + g * CPG;
    int tid = threadIdx.x;

    float s = 0.f, s2 = 0.f;
    for (int e = tid; e < NN * 4; e += 256) {
        int n = e >> 2, c4 = (e & 3) << 2;
        float4 v = *(const float4*)(xb + (size_t)n * CC + c4);
        *(float4*)(xs + n * CPG + c4) = v;
        s  += v.x + v.y + v.z + v.w;
        s2 += v.x * v.x + v.y * v.y + v.z * v.z + v.w * v.w;
    }
    #pragma unroll
    for (int o2 = 16; o2; o2 >>= 1) {
        s  += __shfl_xor_sync(0xffffffffu, s,  o2);
        s2 += __shfl_xor_sync(0xffffffffu, s2, o2);
    }
    __shared__ float sh[8], sh2[8];
    int w = tid >> 5, lane = tid & 31;
    if (lane == 0) { sh[w] = s; sh2[w] = s2; }
    __syncthreads();

    __shared__ float cq[2][CPG], ck[2][CPG];
    if (tid < CPG) {
        float ts = 0.f, ts2 = 0.f;
        #pragma unroll
        for (int i = 0; i < 8; i++) { ts += sh[i]; ts2 += sh2[i]; }
        const float cnt = (float)(NN * CPG);
        float mu  = ts / cnt;
        float var = ts2 / cnt - mu * mu;
        float inv = rsqrtf(var + EPSV);
        int c = g * CPG + tid;
        float aq = inv * qsc[c];
        cq[0][tid] = aq;  cq[1][tid] = qbi[c] - mu * aq;
        float ak = inv * ksc[c];
        ck[0][tid] = ak;  ck[1][tid] = kbi[c] - mu * ak;
    }
    __syncthreads();

    __nv_bfloat16* oqb  = oq  + (size_t)b * NN * CC + g * CPG;
    __nv_bfloat16* okvb = okv + (size_t)b * NN * CC + g * CPG;
    for (int e = tid; e < NN * 4; e += 256) {
        int n = e >> 2, c4 = (e & 3) << 2;
        float4 v = *(const float4*)(xs + n * CPG + c4);
        uint2 pq, pk;
        pq.x = pack_bf16x2(v.x * cq[0][c4+0] + cq[1][c4+0], v.y * cq[0][c4+1] + cq[1][c4+1]);
        pq.y = pack_bf16x2(v.z * cq[0][c4+2] + cq[1][c4+2], v.w * cq[0][c4+3] + cq[1][c4+3]);
        pk.x = pack_bf16x2(v.x * ck[0][c4+0] + ck[1][c4+0], v.y * ck[0][c4+1] + ck[1][c4+1]);
        pk.y = pack_bf16x2(v.z * ck[0][c4+2] + ck[1][c4+2], v.w * ck[0][c4+3] + ck[1][c4+3]);
        *(uint2*)(oqb  + (size_t)n * CC + c4) = pq;
        *(uint2*)(okvb + (size_t)n * CC + c4) = pk;
    }
}

// =====================================================================
// GroupNorm over text
// =====================================================================
__global__ void gn_txt_kernel(const float* __restrict__ t,
                              const float* __restrict__ tsc, const float* __restrict__ tbi,
                              __nv_bfloat16* __restrict__ ot)
{
    int b = blockIdx.x >> 5, g = blockIdx.x & 31;
    const float* xb = t + (size_t)b * LL * CC + g * CPG;
    int tid = threadIdx.x;

    float s = 0.f, s2 = 0.f;
    for (int e = tid; e < LL * 4; e += 128) {
        int n = e >> 2, c4 = (e & 3) << 2;
        float4 v = *(const float4*)(xb + (size_t)n * CC + c4);
        s  += v.x + v.y + v.z + v.w;
        s2 += v.x * v.x + v.y * v.y + v.z * v.z + v.w * v.w;
    }
    #pragma unroll
    for (int o2 = 16; o2; o2 >>= 1) {
        s  += __shfl_xor_sync(0xffffffffu, s,  o2);
        s2 += __shfl_xor_sync(0xffffffffu, s2, o2);
    }
    __shared__ float sh[4], sh2[4];
    int w = tid >> 5, lane = tid & 31;
    if (lane == 0) { sh[w] = s; sh2[w] = s2; }
    __syncthreads();

    __shared__ float ct[2][CPG];
    if (tid < CPG) {
        float ts = 0.f, ts2 = 0.f;
        #pragma unroll
        for (int i = 0; i < 4; i++) { ts += sh[i]; ts2 += sh2[i]; }
        const float cnt = (float)(LL * CPG);
        float mu  = ts / cnt;
        float var = ts2 / cnt - mu * mu;
        float inv = rsqrtf(var + EPSV);
        int c = g * CPG + tid;
        float a = inv * tsc[c];
        ct[0][tid] = a;  ct[1][tid] = tbi[c] - mu * a;
    }
    __syncthreads();

    __nv_bfloat16* ob = ot + (size_t)b * LL * CC + g * CPG;
    for (int e = tid; e < LL * 4; e += 128) {
        int n = e >> 2, c4 = (e & 3) << 2;
        float4 v = *(const float4*)(xb + (size_t)n * CC + c4);
        uint2 p;
        p.x = pack_bf16x2(v.x * ct[0][c4+0] + ct[1][c4+0], v.y * ct[0][c4+1] + ct[1][c4+1]);
        p.y = pack_bf16x2(v.z * ct[0][c4+2] + ct[1][c4+2], v.w * ct[0][c4+3] + ct[1][c4+3]);
        *(uint2*)(ob + (size_t)n * CC + c4) = p;
    }
}

// =====================================================================
// BF16 GEMM, 3-stage cp.async pipeline, BK=64 (proven R5 version).
// =====================================================================
#define GEMM_SMEM 98304

__global__ void __launch_bounds__(256, 2)
gemm_bf16(const __nv_bfloat16* __restrict__ A, const __nv_bfloat16* __restrict__ W,
          void* __restrict__ OutP, const float* __restrict__ Res,
          int M, int rows_per_b, int out_rows_per_b, int out_off,
          float alpha, int outBf16)
{
    extern __shared__ char smc[];
    unsigned aBase = (unsigned)__cvta_generic_to_shared(smc);
    unsigned bBase = aBase + 3 * 16384;

    int tid = threadIdx.x, warp = tid >> 5, lane = tid & 31;
    int g = lane >> 2, tg = lane & 3;
    int wm = (warp >> 2) * 64, wn = (warp & 3) * 32;
    int m0 = blockIdx.x * 128, n0 = blockIdx.y * 128;

    float acc[4][4][4] = {};

    auto loadTile = [&](int kt, int st) {
        int k0 = kt * 64;
        unsigned aD = aBase + st * 16384;
        unsigned bD = bBase + st * 16384;
        #pragma unroll
        for (int i = 0; i < 4; i++) {
            int f = tid + i * 256;
            int r = f >> 3, c = f & 7;
            bool ok = (m0 + r) < M;
            cpa16(aD + r * 128 + ((c ^ (r & 7)) << 4),
                  A + (size_t)(m0 + r) * 512 + k0 + c * 8, ok);
        }
        #pragma unroll
        for (int i = 0; i < 4; i++) {
            int f = tid + i * 256;
            int r = f >> 4, c = f & 15;
            cpa16(bD + r * 256 + ((c ^ (r & 7)) << 4),
                  W + (size_t)(k0 + r) * 512 + n0 + c * 8, true);
        }
    };
    loadTile(0, 0); cpa_commit();
    loadTile(1, 1); cpa_commit();

    int st = 0;
    for (int t = 0; t < 8; t++) {
        cpa_wait<1>();
        __syncthreads();
        if (t + 2 < 8) {
            int ns = st + 2; if (ns >= 3) ns -= 3;
            loadTile(t + 2, ns);
            cpa_commit();
        }

        unsigned aC = aBase + st * 16384;
        unsigned bC = bBase + st * 16384;
        #pragma unroll
        for (int kc = 0; kc < 8; kc += 2) {
            unsigned af[4][4];
            #pragma unroll
            for (int i = 0; i < 4; i++) {
                int r = wm + i * 16 + (lane & 15);
                int c = kc + (lane >> 4);
                ldsm4(af[i][0], af[i][1], af[i][2], af[i][3],
                      aC + r * 128 + ((c ^ (r & 7)) << 4));
            }
            unsigned bfr[4][2];
            #pragma unroll
            for (int grp = 0; grp < 2; grp++) {
                int r = kc * 8 + (lane & 15);
                int c = (wn >> 3) + 2 * grp + (lane >> 4);
                unsigned r0, r1, r2, r3;
                ldsm4t(r0, r1, r2, r3, bC + r * 256 + ((c ^ (r & 7)) << 4));
                bfr[grp*2][0] = r0;   bfr[grp*2][1] = r1;
                bfr[grp*2+1][0] = r2; bfr[grp*2+1][1] = r3;
            }
            #pragma unroll
            for (int i = 0; i < 4; i++)
                #pragma unroll
                for (int j = 0; j < 4; j++)
                    mma16(acc[i][j], af[i], bfr[j]);
        }
        if (++st == 3) st = 0;
    }

    #pragma unroll
    for (int i = 0; i < 4; i++) {
        #pragma unroll
        for (int rs = 0; rs < 2; rs++) {
            int gm = m0 + wm + i * 16 + g + rs * 8;
            if (gm >= M) continue;
            int bbi = gm / rows_per_b;
            int rr  = gm - bbi * rows_per_b;
            size_t orow = (size_t)bbi * out_rows_per_b + out_off + rr;
            #pragma unroll
            for (int j = 0; j < 4; j++) {
                int col = n0 + wn + j * 8 + 2 * tg;
                float v0 = acc[i][j][rs * 2 + 0] * alpha;
                float v1 = acc[i][j][rs * 2 + 1] * alpha;
                if (outBf16) {
                    *(unsigned*)((__nv_bfloat16*)OutP + orow * 512 + col) =
                        pack_bf16x2(v0, v1);
                } else {
                    if (Res) {
                        float2 rv = *(const float2*)(Res + orow * 512 + col);
                        v0 += rv.x; v1 += rv.y;
                    }
                    *(float2*)((float*)OutP + orow * 512 + col) = make_float2(v0, v1);
                }
            }
        }
    }
}

// =====================================================================
// BF16 flash attention: register-resident P (no smem round trip),
// 4 warps x 16 q-rows, KV tiles of 64, double-buffered cp.async,
// log2-domain softmax, mask fast path. smem 40.5KB -> 4 blocks/SM.
// =====================================================================
#define ATT_SMEM (40960 + 512)

__global__ void __launch_bounds__(128, 4)
attn_bf16(const int* __restrict__ tmask,
          const __nv_bfloat16* __restrict__ Qg,
          const __nv_bfloat16* __restrict__ Kg,
          const __nv_bfloat16* __restrict__ Vg,
          __nv_bfloat16* __restrict__ Og)
{
    extern __shared__ char smc[];
    unsigned qB = (unsigned)__cvta_generic_to_shared(smc);  // [64][128B]
    unsigned kB = qB + 8192;                                // [2][64][128B]
    unsigned vB = kB + 16384;                               // [2][64][128B]
    float* kmaskf = (float*)(smc + 40960);                  // [2][64]

    int qt = blockIdx.x, h = blockIdx.y, b = blockIdx.z;
    int tid = threadIdx.x, warp = tid >> 5, lane = tid & 31;
    int g = lane >> 2, tg = lane & 3;
    int wm = warp * 16;

    const __nv_bfloat16* qb = Qg + (size_t)(b * NN + qt * 64) * 512 + h * 64;
    const __nv_bfloat16* kb = Kg + (size_t)b * KVLEN * 512 + h * 64;
    const __nv_bfloat16* vb = Vg + (size_t)b * KVLEN * 512 + h * 64;
    const int* tm = tmask + b * LL;

    #pragma unroll
    for (int i = 0; i < 4; i++) {
        int f = tid + i * 128;
        int r = f >> 3, c = f & 7;
        cpa16(qB + r * 128 + ((c ^ (r & 7)) << 4), qb + (size_t)r * 512 + c * 8, true);
    }
    cpa_commit();

    auto loadKV = [&](int t, int stg) {
        int kv0 = t * 64;
        unsigned kD = kB + stg * 8192, vD = vB + stg * 8192;
        #pragma unroll
        for (int i = 0; i < 4; i++) {
            int f = tid + i * 128;
            int r = f >> 3, c = f & 7;
            int kg = kv0 + r;
            bool ok = kg < KVLEN;
            cpa16(kD + r * 128 + ((c ^ (r & 7)) << 4), kb + (size_t)kg * 512 + c * 8, ok);
            cpa16(vD + r * 128 + ((c ^ (r & 7)) << 4), vb + (size_t)kg * 512 + c * 8, ok);
        }
        if (kv0 + 64 > NN && tid < 64) {
            int kg = kv0 + tid;
            float m = 0.f;
            if (kg >= KVLEN) m = NEGV * LOG2E;
            else if (kg >= NN && tm[kg - NN] == 0) m = NEGV * LOG2E;
            kmaskf[stg * 64 + tid] = m;
        }
    };
    loadKV(0, 0);
    cpa_commit();

    float m_i[2] = {-1e30f, -1e30f}, l_i[2] = {0.f, 0.f}, o[8][4] = {};

    for (int t = 0; t < 18; t++) {
        __syncthreads();
        if (t + 1 < 18) { loadKV(t + 1, (t + 1) & 1); cpa_commit(); cpa_wait<1>(); }
        else            { cpa_wait<0>(); }
        __syncthreads();

        unsigned kC = kB + (t & 1) * 8192;
        unsigned vC = vB + (t & 1) * 8192;
        const float* km = kmaskf + (t & 1) * 64;
        bool masked = (t * 64 + 64 > NN);   // only tiles 16,17

        // ---- S = Q K^T (log2-domain: LOG2E folded into Q projection) ----
        float s[8][4] = {};
        #pragma unroll
        for (int kc = 0; kc < 8; kc += 2) {
            unsigned aq[4];
            {
                int r = wm + (lane & 15);
                int c = kc + (lane >> 4);
                ldsm4(aq[0], aq[1], aq[2], aq[3], qB + r * 128 + ((c ^ (r & 7)) << 4));
            }
            #pragma unroll
            for (int grp = 0; grp < 4; grp++) {
                int r = grp * 16 + (lane & 7) + ((lane >> 4) << 3);
                int c = kc + ((lane >> 3) & 1);
                unsigned r0, r1, r2, r3;
                ldsm4(r0, r1, r2, r3, kC + r * 128 + ((c ^ (r & 7)) << 4));
                unsigned bk0[2] = {r0, r1}, bk1[2] = {r2, r3};
                mma16(s[grp * 2], aq, bk0);
                mma16(s[grp * 2 + 1], aq, bk1);
            }
        }

        // ---- mask (only final tiles) + online softmax (exp2) ----
        if (masked) {
            #pragma unroll
            for (int j = 0; j < 8; j++) {
                float k0v = km[j * 8 + 2 * tg], k1v = km[j * 8 + 2 * tg + 1];
                s[j][0] += k0v; s[j][1] += k1v;
                s[j][2] += k0v; s[j][3] += k1v;
            }
        }
        float mx0 = -1e30f, mx1 = -1e30f;
        #pragma unroll
        for (int j = 0; j < 8; j++) {
            mx0 = fmaxf(mx0, fmaxf(s[j][0], s[j][1]));
            mx1 = fmaxf(mx1, fmaxf(s[j][2], s[j][3]));
        }
        mx0 = fmaxf(mx0, __shfl_xor_sync(0xffffffffu, mx0, 1));
        mx0 = fmaxf(mx0, __shfl_xor_sync(0xffffffffu, mx0, 2));
        mx1 = fmaxf(mx1, __shfl_xor_sync(0xffffffffu, mx1, 1));
        mx1 = fmaxf(mx1, __shfl_xor_sync(0xffffffffu, mx1, 2));
        float mn0 = fmaxf(m_i[0], mx0), mn1 = fmaxf(m_i[1], mx1);
        float al0 = ex2f(m_i[0] - mn0), al1 = ex2f(m_i[1] - mn1);
        m_i[0] = mn0; m_i[1] = mn1;

        // exp2 + pack P directly into A-fragment registers (no smem!)
        // k16 chunk kc2 pairs S tiles j=2kc2 (k-lo) and j=2kc2+1 (k-hi):
        //   a0 = (row g, k-lo), a1 = (row g+8, k-lo), a2 = (row g, k-hi), a3 = (row g+8, k-hi)
        unsigned pp[4][4];
        float sum0 = 0.f, sum1 = 0.f;
        #pragma unroll
        for (int kc2 = 0; kc2 < 4; kc2++) {
            float p00 = ex2f(s[2*kc2][0]   - mn0);
            float p01 = ex2f(s[2*kc2][1]   - mn0);
            float p02 = ex2f(s[2*kc2][2]   - mn1);
            float p03 = ex2f(s[2*kc2][3]   - mn1);
            float p10 = ex2f(s[2*kc2+1][0] - mn0);
            float p11 = ex2f(s[2*kc2+1][1] - mn0);
            float p12 = ex2f(s[2*kc2+1][2] - mn1);
            float p13 = ex2f(s[2*kc2+1][3] - mn1);
            sum0 += p00 + p01 + p10 + p11;
            sum1 += p02 + p03 + p12 + p13;
            pp[kc2][0] = pack_bf16x2(p00, p01);
            pp[kc2][1] = pack_bf16x2(p02, p03);
            pp[kc2][2] = pack_bf16x2(p10, p11);
            pp[kc2][3] = pack_bf16x2(p12, p13);
        }
        sum0 += __shfl_xor_sync(0xffffffffu, sum0, 1);
        sum0 += __shfl_xor_sync(0xffffffffu, sum0, 2);
        sum1 += __shfl_xor_sync(0xffffffffu, sum1, 1);
        sum1 += __shfl_xor_sync(0xffffffffu, sum1, 2);
        l_i[0] = l_i[0] * al0 + sum0;
        l_i[1] = l_i[1] * al1 + sum1;
        #pragma unroll
        for (int j = 0; j < 8; j++) {
            o[j][0] *= al0; o[j][1] *= al0;
            o[j][2] *= al1; o[j][3] *= al1;
        }

        // ---- O += P V (P from registers) ----
        #pragma unroll
        for (int kc2 = 0; kc2 < 4; kc2++) {
            #pragma unroll
            for (int grp = 0; grp < 4; grp++) {
                int r = kc2 * 16 + (lane & 15);
                int c = grp * 2 + (lane >> 4);
                unsigned r0, r1, r2, r3;
                ldsm4t(r0, r1, r2, r3, vC + r * 128 + ((c ^ (r & 7)) << 4));
                unsigned bv0[2] = {r0, r1}, bv1[2] = {r2, r3};
                mma16(o[grp * 2], pp[kc2], bv0);
                mma16(o[grp * 2 + 1], pp[kc2], bv1);
            }
        }
    }

    __nv_bfloat16* ob = Og + (size_t)(b * NN + qt * 64) * 512 + h * 64;
    #pragma unroll
    for (int rs = 0; rs < 2; rs++) {
        int r = wm + g + rs * 8;
        float inv = 1.f / l_i[rs];
        #pragma unroll
        for (int j = 0; j < 8; j++) {
            int col = j * 8 + 2 * tg;
            *(unsigned*)(ob + (size_t)r * 512 + col) =
                pack_bf16x2(o[j][rs * 2 + 0] * inv, o[j][rs * 2 + 1] * inv);
        }
    }
}

// =====================================================================
// launch
// =====================================================================
extern "C" void kernel_launch(void* const* d_in, const int* in_sizes, int n_in,
                              void* d_out, int out_size)
{
    const float* x    = (const float*)d_in[0];
    const float* te   = (const float*)d_in[1];
    const int*   tmk  = (const int*)  d_in[2];
    const float* gqs  = (const float*)d_in[3];
    const float* gqb  = (const float*)d_in[4];
    const float* gks  = (const float*)d_in[5];
    const float* gkb  = (const float*)d_in[6];
    const float* gts  = (const float*)d_in[7];
    const float* gtb  = (const float*)d_in[8];
    const float* Wq   = (const float*)d_in[9];
    const float* Wks  = (const float*)d_in[10];
    const float* Wvs  = (const float*)d_in[11];
    const float* Wkc  = (const float*)d_in[12];
    const float* Wvc  = (const float*)d_in[13];
    const float* Wout = (const float*)d_in[14];
    float* out = (float*)d_out;

    float* scratch = nullptr;
    cudaGetSymbolAddress((void**)&scratch, g_scratch);
    __nv_bfloat16* bs = (__nv_bfloat16*)scratch;
    __nv_bfloat16* XQ   = bs + BOFF_XQ;
    __nv_bfloat16* XKV  = bs + BOFF_XKV;
    __nv_bfloat16* Tb   = bs + BOFF_T;
    __nv_bfloat16* Qb   = bs + BOFF_Q;
    __nv_bfloat16* Kb   = bs + BOFF_K;
    __nv_bfloat16* Vb   = bs + BOFF_V;
    __nv_bfloat16* ATTb = bs + BOFF_ATT;
    __nv_bfloat16* Wb   = bs + BOFF_W;

    cudaFuncSetAttribute(gemm_bf16, cudaFuncAttributeMaxDynamicSharedMemorySize, GEMM_SMEM);
    cudaFuncSetAttribute(attn_bf16, cudaFuncAttributeMaxDynamicSharedMemorySize, ATT_SMEM);
    cudaFuncSetAttribute(gn_img_kernel, cudaFuncAttributeMaxDynamicSharedMemorySize, GN_SMEM);

    wconv_kernel<<<1536, 256>>>(Wq, Wks, Wvs, Wkc, Wvc, Wout, Wb);
    gn_img_kernel<<<512, 256, GN_SMEM>>>(x, gqs, gqb, gks, gkb, XQ, XKV);
    gn_txt_kernel<<<512, 128>>>(te, gts, gtb, Tb);

    __nv_bfloat16* WqB  = Wb;
    __nv_bfloat16* WksB = Wb + 262144;
    __nv_bfloat16* WvsB = Wb + 2 * 262144;
    __nv_bfloat16* WkcB = Wb + 3 * 262144;
    __nv_bfloat16* WvcB = Wb + 4 * 262144;
    __nv_bfloat16* WoB  = Wb + 5 * 262144;

    // Q projection folds 1/sqrt(64) * log2(e) (exp2-domain softmax).
    gemm_bf16<<<dim3(128, 4), 256, GEMM_SMEM>>>(XQ,  WqB,  Qb, nullptr, 16384, 1024, 1024,  0, 0.125f * LOG2E, 1);
    gemm_bf16<<<dim3(128, 4), 256, GEMM_SMEM>>>(XKV, WksB, Kb, nullptr, 16384, 1024, KVLEN, 0, 1.f, 1);
    gemm_bf16<<<dim3(128, 4), 256, GEMM_SMEM>>>(XKV, WvsB, Vb, nullptr, 16384, 1024, KVLEN, 0, 1.f, 1);
    gemm_bf16<<<dim3(10, 4),  256, GEMM_SMEM>>>(Tb,  WkcB, Kb, nullptr, 1232,  77,   KVLEN, 1024, 1.f, 1);
    gemm_bf16<<<dim3(10, 4),  256, GEMM_SMEM>>>(Tb,  WvcB, Vb, nullptr, 1232,  77,   KVLEN, 1024, 1.f, 1);

    attn_bf16<<<dim3(16, NHH, BB), 128, ATT_SMEM>>>(tmk, Qb, Kb, Vb, ATTb);

    gemm_bf16<<<dim3(128, 4), 256, GEMM_SMEM>>>(ATTb, WoB, out, x, 16384, 1024, 1024, 0, 1.f, 0);
}

// round 8
// speedup vs baseline: 10.4010x; 1.0856x over previous
#include <cuda_runtime.h>
#include <cuda_bf16.h>
#include <math.h>

// ---------------- problem constants ----------------
#define BB    16
#define NN    1024
#define CC    512
#define LL    77
#define KVLEN 1101
#define NHH   8
#define HDD   64
#define CPG   16
#define EPSV  1e-6f
#define NEGV  -1e10f
#define LOG2E 1.44269504089f

// ---------------- scratch ----------------
__device__ float g_scratch[52224000];

#define BOFF_XQ   ((size_t)0)
#define BOFF_XKV  ((size_t)8388608)
#define BOFF_T    ((size_t)16777216)
#define BOFF_Q    ((size_t)17408000)
#define BOFF_K    ((size_t)25796608)
#define BOFF_V    ((size_t)34816000)
#define BOFF_ATT  ((size_t)43835392)
#define BOFF_W    ((size_t)52224000)

// ---------------- helpers ----------------
__device__ __forceinline__ unsigned pack_bf16x2(float lo, float hi) {
    unsigned r;
    asm("cvt.rn.bf16x2.f32 %0, %1, %2;" : "=r"(r) : "f"(hi), "f"(lo));
    return r;
}
__device__ __forceinline__ float ex2f(float x) {
    float r; asm("ex2.approx.ftz.f32 %0, %1;" : "=f"(r) : "f"(x)); return r;
}
__device__ __forceinline__ void mma16(float* c, const unsigned* a, const unsigned* b) {
    asm volatile(
        "mma.sync.aligned.m16n8k16.row.col.f32.bf16.bf16.f32 "
        "{%0,%1,%2,%3},{%4,%5,%6,%7},{%8,%9},{%0,%1,%2,%3};\n"
        : "+f"(c[0]), "+f"(c[1]), "+f"(c[2]), "+f"(c[3])
        : "r"(a[0]), "r"(a[1]), "r"(a[2]), "r"(a[3]), "r"(b[0]), "r"(b[1]));
}
__device__ __forceinline__ void ldsm4(unsigned& r0, unsigned& r1, unsigned& r2, unsigned& r3,
                                      unsigned addr) {
    asm volatile("ldmatrix.sync.aligned.m8n8.x4.shared.b16 {%0,%1,%2,%3}, [%4];"
                 : "=r"(r0), "=r"(r1), "=r"(r2), "=r"(r3) : "r"(addr));
}
__device__ __forceinline__ void ldsm4t(unsigned& r0, unsigned& r1, unsigned& r2, unsigned& r3,
                                       unsigned addr) {
    asm volatile("ldmatrix.sync.aligned.m8n8.x4.trans.shared.b16 {%0,%1,%2,%3}, [%4];"
                 : "=r"(r0), "=r"(r1), "=r"(r2), "=r"(r3) : "r"(addr));
}
__device__ __forceinline__ void cpa16(unsigned dst, const void* src, bool p) {
    int sz = p ? 16 : 0;
    asm volatile("cp.async.cg.shared.global [%0], [%1], 16, %2;\n"
                 :: "r"(dst), "l"(src), "r"(sz));
}
__device__ __forceinline__ void cpa_commit() { asm volatile("cp.async.commit_group;\n"); }
template<int N> __device__ __forceinline__ void cpa_wait() {
    asm volatile("cp.async.wait_group %0;\n" :: "n"(N));
}

struct GemmJob {
    const __nv_bfloat16* A;
    const __nv_bfloat16* W;
    __nv_bfloat16* Out;
    float alpha;
    int out_rows_per_b;
    int out_off;
};

// =====================================================================
// Weight conversion fp32 -> bf16 (6 matrices of 512x512, [k][n])
// =====================================================================
__global__ void wconv_kernel(const float* __restrict__ w0, const float* __restrict__ w1,
                             const float* __restrict__ w2, const float* __restrict__ w3,
                             const float* __restrict__ w4, const float* __restrict__ w5,
                             __nv_bfloat16* __restrict__ out)
{
    int gid = blockIdx.x * 256 + threadIdx.x;
    int mat = gid >> 16;
    int idx = (gid & 65535) << 2;
    const float* src = mat == 0 ? w0 : mat == 1 ? w1 : mat == 2 ? w2
                     : mat == 3 ? w3 : mat == 4 ? w4 : w5;
    float4 v = *(const float4*)(src + idx);
    uint2 p;
    p.x = pack_bf16x2(v.x, v.y);
    p.y = pack_bf16x2(v.z, v.w);
    *(uint2*)(out + (size_t)mat * 262144 + idx) = p;
}

// =====================================================================
// GroupNorm over image (smem slice cache; bf16 x_q / x_kv outputs)
// =====================================================================
#define GN_SMEM (NN * CPG * 4)

__global__ void __launch_bounds__(256, 3)
gn_img_kernel(const float* __restrict__ x,
              const float* __restrict__ qsc, const float* __restrict__ qbi,
              const float* __restrict__ ksc, const float* __restrict__ kbi,
              __nv_bfloat16* __restrict__ oq, __nv_bfloat16* __restrict__ okv)
{
    extern __shared__ float xs[];
    int b = blockIdx.x >> 5, g = blockIdx.x & 31;
    const float* xb = x + (size_t)b * NN * CC + g * CPG;
    int tid = threadIdx.x;

    float s = 0.f, s2 = 0.f;
    for (int e = tid; e < NN * 4; e += 256) {
        int n = e >> 2, c4 = (e & 3) << 2;
        float4 v = *(const float4*)(xb + (size_t)n * CC + c4);
        *(float4*)(xs + n * CPG + c4) = v;
        s  += v.x + v.y + v.z + v.w;
        s2 += v.x * v.x + v.y * v.y + v.z * v.z + v.w * v.w;
    }
    #pragma unroll
    for (int o2 = 16; o2; o2 >>= 1) {
        s  += __shfl_xor_sync(0xffffffffu, s,  o2);
        s2 += __shfl_xor_sync(0xffffffffu, s2, o2);
    }
    __shared__ float sh[8], sh2[8];
    int w = tid >> 5, lane = tid & 31;
    if (lane == 0) { sh[w] = s; sh2[w] = s2; }
    __syncthreads();

    __shared__ float cq[2][CPG], ck[2][CPG];
    if (tid < CPG) {
        float ts = 0.f, ts2 = 0.f;
        #pragma unroll
        for (int i = 0; i < 8; i++) { ts += sh[i]; ts2 += sh2[i]; }
        const float cnt = (float)(NN * CPG);
        float mu  = ts / cnt;
        float var = ts2 / cnt - mu * mu;
        float inv = rsqrtf(var + EPSV);
        int c = g * CPG + tid;
        float aq = inv * qsc[c];
        cq[0][tid] = aq;  cq[1][tid] = qbi[c] - mu * aq;
        float ak = inv * ksc[c];
        ck[0][tid] = ak;  ck[1][tid] = kbi[c] - mu * ak;
    }
    __syncthreads();

    __nv_bfloat16* oqb  = oq  + (size_t)b * NN * CC + g * CPG;
    __nv_bfloat16* okvb = okv + (size_t)b * NN * CC + g * CPG;
    for (int e = tid; e < NN * 4; e += 256) {
        int n = e >> 2, c4 = (e & 3) << 2;
        float4 v = *(const float4*)(xs + n * CPG + c4);
        uint2 pq, pk;
        pq.x = pack_bf16x2(v.x * cq[0][c4+0] + cq[1][c4+0], v.y * cq[0][c4+1] + cq[1][c4+1]);
        pq.y = pack_bf16x2(v.z * cq[0][c4+2] + cq[1][c4+2], v.w * cq[0][c4+3] + cq[1][c4+3]);
        pk.x = pack_bf16x2(v.x * ck[0][c4+0] + ck[1][c4+0], v.y * ck[0][c4+1] + ck[1][c4+1]);
        pk.y = pack_bf16x2(v.z * ck[0][c4+2] + ck[1][c4+2], v.w * ck[0][c4+3] + ck[1][c4+3]);
        *(uint2*)(oqb  + (size_t)n * CC + c4) = pq;
        *(uint2*)(okvb + (size_t)n * CC + c4) = pk;
    }
}

// =====================================================================
// GroupNorm over text
// =====================================================================
__global__ void gn_txt_kernel(const float* __restrict__ t,
                              const float* __restrict__ tsc, const float* __restrict__ tbi,
                              __nv_bfloat16* __restrict__ ot)
{
    int b = blockIdx.x >> 5, g = blockIdx.x & 31;
    const float* xb = t + (size_t)b * LL * CC + g * CPG;
    int tid = threadIdx.x;

    float s = 0.f, s2 = 0.f;
    for (int e = tid; e < LL * 4; e += 128) {
        int n = e >> 2, c4 = (e & 3) << 2;
        float4 v = *(const float4*)(xb + (size_t)n * CC + c4);
        s  += v.x + v.y + v.z + v.w;
        s2 += v.x * v.x + v.y * v.y + v.z * v.z + v.w * v.w;
    }
    #pragma unroll
    for (int o2 = 16; o2; o2 >>= 1) {
        s  += __shfl_xor_sync(0xffffffffu, s,  o2);
        s2 += __shfl_xor_sync(0xffffffffu, s2, o2);
    }
    __shared__ float sh[4], sh2[4];
    int w = tid >> 5, lane = tid & 31;
    if (lane == 0) { sh[w] = s; sh2[w] = s2; }
    __syncthreads();

    __shared__ float ct[2][CPG];
    if (tid < CPG) {
        float ts = 0.f, ts2 = 0.f;
        #pragma unroll
        for (int i = 0; i < 4; i++) { ts += sh[i]; ts2 += sh2[i]; }
        const float cnt = (float)(LL * CPG);
        float mu  = ts / cnt;
        float var = ts2 / cnt - mu * mu;
        float inv = rsqrtf(var + EPSV);
        int c = g * CPG + tid;
        float a = inv * tsc[c];
        ct[0][tid] = a;  ct[1][tid] = tbi[c] - mu * a;
    }
    __syncthreads();

    __nv_bfloat16* ob = ot + (size_t)b * LL * CC + g * CPG;
    for (int e = tid; e < LL * 4; e += 128) {
        int n = e >> 2, c4 = (e & 3) << 2;
        float4 v = *(const float4*)(xb + (size_t)n * CC + c4);
        uint2 p;
        p.x = pack_bf16x2(v.x * ct[0][c4+0] + ct[1][c4+0], v.y * ct[0][c4+1] + ct[1][c4+1]);
        p.y = pack_bf16x2(v.z * ct[0][c4+2] + ct[1][c4+2], v.w * ct[0][c4+3] + ct[1][c4+3]);
        *(uint2*)(ob + (size_t)n * CC + c4) = p;
    }
}

// =====================================================================
// BF16 GEMM core (3-stage cp.async pipeline, BK=64, block 128x128).
// =====================================================================
__device__ __forceinline__ void gemm_core(
    const __nv_bfloat16* __restrict__ A, const __nv_bfloat16* __restrict__ W,
    int M, int m0, int n0, unsigned aBase, unsigned bBase, float acc[4][4][4],
    int tid, int lane, int wm, int wn)
{
    auto loadTile = [&](int kt, int st) {
        int k0 = kt * 64;
        unsigned aD = aBase + st * 16384;
        unsigned bD = bBase + st * 16384;
        #pragma unroll
        for (int i = 0; i < 4; i++) {
            int f = tid + i * 256;
            int r = f >> 3, c = f & 7;
            bool ok = (m0 + r) < M;
            cpa16(aD + r * 128 + ((c ^ (r & 7)) << 4),
                  A + (size_t)(m0 + r) * 512 + k0 + c * 8, ok);
        }
        #pragma unroll
        for (int i = 0; i < 4; i++) {
            int f = tid + i * 256;
            int r = f >> 4, c = f & 15;
            cpa16(bD + r * 256 + ((c ^ (r & 7)) << 4),
                  W + (size_t)(k0 + r) * 512 + n0 + c * 8, true);
        }
    };
    loadTile(0, 0); cpa_commit();
    loadTile(1, 1); cpa_commit();

    int st = 0;
    for (int t = 0; t < 8; t++) {
        cpa_wait<1>();
        __syncthreads();
        if (t + 2 < 8) {
            int ns = st + 2; if (ns >= 3) ns -= 3;
            loadTile(t + 2, ns);
            cpa_commit();
        }
        unsigned aC = aBase + st * 16384;
        unsigned bC = bBase + st * 16384;
        #pragma unroll
        for (int kc = 0; kc < 8; kc += 2) {
            unsigned af[4][4];
            #pragma unroll
            for (int i = 0; i < 4; i++) {
                int r = wm + i * 16 + (lane & 15);
                int c = kc + (lane >> 4);
                ldsm4(af[i][0], af[i][1], af[i][2], af[i][3],
                      aC + r * 128 + ((c ^ (r & 7)) << 4));
            }
            unsigned bfr[4][2];
            #pragma unroll
            for (int grp = 0; grp < 2; grp++) {
                int r = kc * 8 + (lane & 15);
                int c = (wn >> 3) + 2 * grp + (lane >> 4);
                unsigned r0, r1, r2, r3;
                ldsm4t(r0, r1, r2, r3, bC + r * 256 + ((c ^ (r & 7)) << 4));
                bfr[grp*2][0] = r0;   bfr[grp*2][1] = r1;
                bfr[grp*2+1][0] = r2; bfr[grp*2+1][1] = r3;
            }
            #pragma unroll
            for (int i = 0; i < 4; i++)
                #pragma unroll
                for (int j = 0; j < 4; j++)
                    mma16(acc[i][j], af[i], bfr[j]);
        }
        if (++st == 3) st = 0;
    }
}

#define GEMM_SMEM 98304

// Multi-job projection GEMM: blockIdx.z selects job (bf16 output).
__global__ void __launch_bounds__(256, 2)
gemm_multi(GemmJob j0, GemmJob j1, GemmJob j2, int M, int rows_per_b)
{
    extern __shared__ char smc[];
    unsigned aBase = (unsigned)__cvta_generic_to_shared(smc);
    unsigned bBase = aBase + 3 * 16384;

    GemmJob jb = blockIdx.z == 0 ? j0 : blockIdx.z == 1 ? j1 : j2;

    int tid = threadIdx.x, warp = tid >> 5, lane = tid & 31;
    int g = lane >> 2, tg = lane & 3;
    int wm = (warp >> 2) * 64, wn = (warp & 3) * 32;
    int m0 = blockIdx.x * 128, n0 = blockIdx.y * 128;

    float acc[4][4][4] = {};
    gemm_core(jb.A, jb.W, M, m0, n0, aBase, bBase, acc, tid, lane, wm, wn);

    #pragma unroll
    for (int i = 0; i < 4; i++) {
        #pragma unroll
        for (int rs = 0; rs < 2; rs++) {
            int gm = m0 + wm + i * 16 + g + rs * 8;
            if (gm >= M) continue;
            int bbi = gm / rows_per_b;
            int rr  = gm - bbi * rows_per_b;
            size_t orow = (size_t)bbi * jb.out_rows_per_b + jb.out_off + rr;
            #pragma unroll
            for (int j = 0; j < 4; j++) {
                int col = n0 + wn + j * 8 + 2 * tg;
                *(unsigned*)(jb.Out + orow * 512 + col) =
                    pack_bf16x2(acc[i][j][rs * 2 + 0] * jb.alpha,
                                acc[i][j][rs * 2 + 1] * jb.alpha);
            }
        }
    }
}

// Final projection GEMM: fp32 out + residual.
__global__ void __launch_bounds__(256, 2)
gemm_final(const __nv_bfloat16* __restrict__ A, const __nv_bfloat16* __restrict__ W,
           float* __restrict__ Out, const float* __restrict__ Res)
{
    extern __shared__ char smc[];
    unsigned aBase = (unsigned)__cvta_generic_to_shared(smc);
    unsigned bBase = aBase + 3 * 16384;

    int tid = threadIdx.x, warp = tid >> 5, lane = tid & 31;
    int g = lane >> 2, tg = lane & 3;
    int wm = (warp >> 2) * 64, wn = (warp & 3) * 32;
    int m0 = blockIdx.x * 128, n0 = blockIdx.y * 128;

    float acc[4][4][4] = {};
    gemm_core(A, W, 16384, m0, n0, aBase, bBase, acc, tid, lane, wm, wn);

    #pragma unroll
    for (int i = 0; i < 4; i++) {
        #pragma unroll
        for (int rs = 0; rs < 2; rs++) {
            size_t orow = (size_t)(m0 + wm + i * 16 + g + rs * 8);
            #pragma unroll
            for (int j = 0; j < 4; j++) {
                int col = n0 + wn + j * 8 + 2 * tg;
                float2 rv = *(const float2*)(Res + orow * 512 + col);
                *(float2*)(Out + orow * 512 + col) =
                    make_float2(acc[i][j][rs * 2 + 0] + rv.x,
                                acc[i][j][rs * 2 + 1] + rv.y);
            }
        }
    }
}

// =====================================================================
// BF16 flash attention: 128-q-row blocks (8 warps x 16 rows),
// register-resident P, double-buffered KV tiles of 64, exp2 softmax.
// smem 48.5KB, 256 threads, 2 blocks/SM.
// =====================================================================
#define ATT_SMEM (49152 + 512)

__global__ void __launch_bounds__(256, 2)
attn_bf16(const int* __restrict__ tmask,
          const __nv_bfloat16* __restrict__ Qg,
          const __nv_bfloat16* __restrict__ Kg,
          const __nv_bfloat16* __restrict__ Vg,
          __nv_bfloat16* __restrict__ Og)
{
    extern __shared__ char smc[];
    unsigned qB = (unsigned)__cvta_generic_to_shared(smc);  // [128][128B]
    unsigned kB = qB + 16384;                               // [2][64][128B]
    unsigned vB = kB + 16384;                               // [2][64][128B]
    float* kmaskf = (float*)(smc + 49152);                  // [2][64]

    int qt = blockIdx.x, h = blockIdx.y, b = blockIdx.z;
    int tid = threadIdx.x, warp = tid >> 5, lane = tid & 31;
    int g = lane >> 2, tg = lane & 3;
    int wm = warp * 16;

    const __nv_bfloat16* qb = Qg + (size_t)(b * NN + qt * 128) * 512 + h * 64;
    const __nv_bfloat16* kb = Kg + (size_t)b * KVLEN * 512 + h * 64;
    const __nv_bfloat16* vb = Vg + (size_t)b * KVLEN * 512 + h * 64;
    const int* tm = tmask + b * LL;

    #pragma unroll
    for (int i = 0; i < 4; i++) {
        int f = tid + i * 256;
        int r = f >> 3, c = f & 7;
        cpa16(qB + r * 128 + ((c ^ (r & 7)) << 4), qb + (size_t)r * 512 + c * 8, true);
    }
    cpa_commit();

    auto loadKV = [&](int t, int stg) {
        int kv0 = t * 64;
        unsigned kD = kB + stg * 8192, vD = vB + stg * 8192;
        #pragma unroll
        for (int i = 0; i < 2; i++) {
            int f = tid + i * 256;
            int r = f >> 3, c = f & 7;
            int kg = kv0 + r;
            bool ok = kg < KVLEN;
            cpa16(kD + r * 128 + ((c ^ (r & 7)) << 4), kb + (size_t)kg * 512 + c * 8, ok);
            cpa16(vD + r * 128 + ((c ^ (r & 7)) << 4), vb + (size_t)kg * 512 + c * 8, ok);
        }
        if (kv0 + 64 > NN && tid < 64) {
            int kg = kv0 + tid;
            float m = 0.f;
            if (kg >= KVLEN) m = NEGV * LOG2E;
            else if (kg >= NN && tm[kg - NN] == 0) m = NEGV * LOG2E;
            kmaskf[stg * 64 + tid] = m;
        }
    };
    loadKV(0, 0);
    cpa_commit();

    float m_i[2] = {-1e30f, -1e30f}, l_i[2] = {0.f, 0.f}, o[8][4] = {};

    for (int t = 0; t < 18; t++) {
        __syncthreads();
        if (t + 1 < 18) { loadKV(t + 1, (t + 1) & 1); cpa_commit(); cpa_wait<1>(); }
        else            { cpa_wait<0>(); }
        __syncthreads();

        unsigned kC = kB + (t & 1) * 8192;
        unsigned vC = vB + (t & 1) * 8192;
        const float* km = kmaskf + (t & 1) * 64;
        bool masked = (t * 64 + 64 > NN);

        // ---- S = Q K^T ----
        float s[8][4] = {};
        #pragma unroll
        for (int kc = 0; kc < 8; kc += 2) {
            unsigned aq[4];
            {
                int r = wm + (lane & 15);
                int c = kc + (lane >> 4);
                ldsm4(aq[0], aq[1], aq[2], aq[3], qB + r * 128 + ((c ^ (r & 7)) << 4));
            }
            #pragma unroll
            for (int grp = 0; grp < 4; grp++) {
                int r = grp * 16 + (lane & 7) + ((lane >> 4) << 3);
                int c = kc + ((lane >> 3) & 1);
                unsigned r0, r1, r2, r3;
                ldsm4(r0, r1, r2, r3, kC + r * 128 + ((c ^ (r & 7)) << 4));
                unsigned bk0[2] = {r0, r1}, bk1[2] = {r2, r3};
                mma16(s[grp * 2], aq, bk0);
                mma16(s[grp * 2 + 1], aq, bk1);
            }
        }

        // ---- mask + online softmax (exp2) ----
        if (masked) {
            #pragma unroll
            for (int j = 0; j < 8; j++) {
                float k0v = km[j * 8 + 2 * tg], k1v = km[j * 8 + 2 * tg + 1];
                s[j][0] += k0v; s[j][1] += k1v;
                s[j][2] += k0v; s[j][3] += k1v;
            }
        }
        float mx0 = -1e30f, mx1 = -1e30f;
        #pragma unroll
        for (int j = 0; j < 8; j++) {
            mx0 = fmaxf(mx0, fmaxf(s[j][0], s[j][1]));
            mx1 = fmaxf(mx1, fmaxf(s[j][2], s[j][3]));
        }
        mx0 = fmaxf(mx0, __shfl_xor_sync(0xffffffffu, mx0, 1));
        mx0 = fmaxf(mx0, __shfl_xor_sync(0xffffffffu, mx0, 2));
        mx1 = fmaxf(mx1, __shfl_xor_sync(0xffffffffu, mx1, 1));
        mx1 = fmaxf(mx1, __shfl_xor_sync(0xffffffffu, mx1, 2));
        float mn0 = fmaxf(m_i[0], mx0), mn1 = fmaxf(m_i[1], mx1);
        float al0 = ex2f(m_i[0] - mn0), al1 = ex2f(m_i[1] - mn1);
        m_i[0] = mn0; m_i[1] = mn1;

        unsigned pp[4][4];
        float sum0 = 0.f, sum1 = 0.f;
        #pragma unroll
        for (int kc2 = 0; kc2 < 4; kc2++) {
            float p00 = ex2f(s[2*kc2][0]   - mn0);
            float p01 = ex2f(s[2*kc2][1]   - mn0);
            float p02 = ex2f(s[2*kc2][2]   - mn1);
            float p03 = ex2f(s[2*kc2][3]   - mn1);
            float p10 = ex2f(s[2*kc2+1][0] - mn0);
            float p11 = ex2f(s[2*kc2+1][1] - mn0);
            float p12 = ex2f(s[2*kc2+1][2] - mn1);
            float p13 = ex2f(s[2*kc2+1][3] - mn1);
            sum0 += p00 + p01 + p10 + p11;
            sum1 += p02 + p03 + p12 + p13;
            pp[kc2][0] = pack_bf16x2(p00, p01);
            pp[kc2][1] = pack_bf16x2(p02, p03);
            pp[kc2][2] = pack_bf16x2(p10, p11);
            pp[kc2][3] = pack_bf16x2(p12, p13);
        }
        sum0 += __shfl_xor_sync(0xffffffffu, sum0, 1);
        sum0 += __shfl_xor_sync(0xffffffffu, sum0, 2);
        sum1 += __shfl_xor_sync(0xffffffffu, sum1, 1);
        sum1 += __shfl_xor_sync(0xffffffffu, sum1, 2);
        l_i[0] = l_i[0] * al0 + sum0;
        l_i[1] = l_i[1] * al1 + sum1;
        #pragma unroll
        for (int j = 0; j < 8; j++) {
            o[j][0] *= al0; o[j][1] *= al0;
            o[j][2] *= al1; o[j][3] *= al1;
        }

        // ---- O += P V (P in registers) ----
        #pragma unroll
        for (int kc2 = 0; kc2 < 4; kc2++) {
            #pragma unroll
            for (int grp = 0; grp < 4; grp++) {
                int r = kc2 * 16 + (lane & 15);
                int c = grp * 2 + (lane >> 4);
                unsigned r0, r1, r2, r3;
                ldsm4t(r0, r1, r2, r3, vC + r * 128 + ((c ^ (r & 7)) << 4));
                unsigned bv0[2] = {r0, r1}, bv1[2] = {r2, r3};
                mma16(o[grp * 2], pp[kc2], bv0);
                mma16(o[grp * 2 + 1], pp[kc2], bv1);
            }
        }
    }

    __nv_bfloat16* ob = Og + (size_t)(b * NN + qt * 128) * 512 + h * 64;
    #pragma unroll
    for (int rs = 0; rs < 2; rs++) {
        int r = wm + g + rs * 8;
        float inv = 1.f / l_i[rs];
        #pragma unroll
        for (int j = 0; j < 8; j++) {
            int col = j * 8 + 2 * tg;
            *(unsigned*)(ob + (size_t)r * 512 + col) =
                pack_bf16x2(o[j][rs * 2 + 0] * inv, o[j][rs * 2 + 1] * inv);
        }
    }
}

// =====================================================================
// launch
// =====================================================================
extern "C" void kernel_launch(void* const* d_in, const int* in_sizes, int n_in,
                              void* d_out, int out_size)
{
    const float* x    = (const float*)d_in[0];
    const float* te   = (const float*)d_in[1];
    const int*   tmk  = (const int*)  d_in[2];
    const float* gqs  = (const float*)d_in[3];
    const float* gqb  = (const float*)d_in[4];
    const float* gks  = (const float*)d_in[5];
    const float* gkb  = (const float*)d_in[6];
    const float* gts  = (const float*)d_in[7];
    const float* gtb  = (const float*)d_in[8];
    const float* Wq   = (const float*)d_in[9];
    const float* Wks  = (const float*)d_in[10];
    const float* Wvs  = (const float*)d_in[11];
    const float* Wkc  = (const float*)d_in[12];
    const float* Wvc  = (const float*)d_in[13];
    const float* Wout = (const float*)d_in[14];
    float* out = (float*)d_out;

    float* scratch = nullptr;
    cudaGetSymbolAddress((void**)&scratch, g_scratch);
    __nv_bfloat16* bs = (__nv_bfloat16*)scratch;
    __nv_bfloat16* XQ   = bs + BOFF_XQ;
    __nv_bfloat16* XKV  = bs + BOFF_XKV;
    __nv_bfloat16* Tb   = bs + BOFF_T;
    __nv_bfloat16* Qb   = bs + BOFF_Q;
    __nv_bfloat16* Kb   = bs + BOFF_K;
    __nv_bfloat16* Vb   = bs + BOFF_V;
    __nv_bfloat16* ATTb = bs + BOFF_ATT;
    __nv_bfloat16* Wb   = bs + BOFF_W;

    cudaFuncSetAttribute(gemm_multi, cudaFuncAttributeMaxDynamicSharedMemorySize, GEMM_SMEM);
    cudaFuncSetAttribute(gemm_final, cudaFuncAttributeMaxDynamicSharedMemorySize, GEMM_SMEM);
    cudaFuncSetAttribute(attn_bf16, cudaFuncAttributeMaxDynamicSharedMemorySize, ATT_SMEM);
    cudaFuncSetAttribute(gn_img_kernel, cudaFuncAttributeMaxDynamicSharedMemorySize, GN_SMEM);

    wconv_kernel<<<1536, 256>>>(Wq, Wks, Wvs, Wkc, Wvc, Wout, Wb);
    gn_img_kernel<<<512, 256, GN_SMEM>>>(x, gqs, gqb, gks, gkb, XQ, XKV);
    gn_txt_kernel<<<512, 128>>>(te, gts, gtb, Tb);

    __nv_bfloat16* WqB  = Wb;
    __nv_bfloat16* WksB = Wb + 262144;
    __nv_bfloat16* WvsB = Wb + 2 * 262144;
    __nv_bfloat16* WkcB = Wb + 3 * 262144;
    __nv_bfloat16* WvcB = Wb + 4 * 262144;
    __nv_bfloat16* WoB  = Wb + 5 * 262144;

    // Self projections (Q folds 1/sqrt(64)*log2(e)) — one launch, z selects job.
    GemmJob jq  = { XQ,  WqB,  Qb, 0.125f * LOG2E, 1024,  0 };
    GemmJob jk  = { XKV, WksB, Kb, 1.f,            KVLEN, 0 };
    GemmJob jv  = { XKV, WvsB, Vb, 1.f,            KVLEN, 0 };
    gemm_multi<<<dim3(128, 4, 3), 256, GEMM_SMEM>>>(jq, jk, jv, 16384, 1024);

    // Cross projections — one launch, z selects job.
    GemmJob jkc = { Tb, WkcB, Kb, 1.f, KVLEN, 1024 };
    GemmJob jvc = { Tb, WvcB, Vb, 1.f, KVLEN, 1024 };
    gemm_multi<<<dim3(10, 4, 2), 256, GEMM_SMEM>>>(jkc, jvc, jvc, 1232, 77);

    attn_bf16<<<dim3(8, NHH, BB), 256, ATT_SMEM>>>(tmk, Qb, Kb, Vb, ATTb);

    gemm_final<<<dim3(128, 4), 256, GEMM_SMEM>>>(ATTb, WoB, out, x);
}

// round 9
// speedup vs baseline: 11.2969x; 1.0861x over previous
#include <cuda_runtime.h>
#include <cuda_bf16.h>
#include <math.h>

// ---------------- problem constants ----------------
#define BB    16
#define NN    1024
#define CC    512
#define LL    77
#define KVLEN 1101
#define NHH   8
#define HDD   64
#define CPG   16
#define EPSV  1e-6f
#define NEGV  -1e10f
#define LOG2E 1.44269504089f

// ---------------- scratch ----------------
__device__ float g_scratch[52224000];

#define BOFF_XQ   ((size_t)0)
#define BOFF_XKV  ((size_t)8388608)
#define BOFF_T    ((size_t)16777216)
#define BOFF_Q    ((size_t)17408000)
#define BOFF_K    ((size_t)25796608)
#define BOFF_V    ((size_t)34816000)
#define BOFF_ATT  ((size_t)43835392)
#define BOFF_W    ((size_t)52224000)

// ---------------- helpers ----------------
__device__ __forceinline__ unsigned pack_bf16x2(float lo, float hi) {
    unsigned r;
    asm("cvt.rn.bf16x2.f32 %0, %1, %2;" : "=r"(r) : "f"(hi), "f"(lo));
    return r;
}
__device__ __forceinline__ float ex2f(float x) {
    float r; asm("ex2.approx.ftz.f32 %0, %1;" : "=f"(r) : "f"(x)); return r;
}
__device__ __forceinline__ void mma16(float* c, const unsigned* a, const unsigned* b) {
    asm volatile(
        "mma.sync.aligned.m16n8k16.row.col.f32.bf16.bf16.f32 "
        "{%0,%1,%2,%3},{%4,%5,%6,%7},{%8,%9},{%0,%1,%2,%3};\n"
        : "+f"(c[0]), "+f"(c[1]), "+f"(c[2]), "+f"(c[3])
        : "r"(a[0]), "r"(a[1]), "r"(a[2]), "r"(a[3]), "r"(b[0]), "r"(b[1]));
}
__device__ __forceinline__ void ldsm4(unsigned& r0, unsigned& r1, unsigned& r2, unsigned& r3,
                                      unsigned addr) {
    asm volatile("ldmatrix.sync.aligned.m8n8.x4.shared.b16 {%0,%1,%2,%3}, [%4];"
                 : "=r"(r0), "=r"(r1), "=r"(r2), "=r"(r3) : "r"(addr));
}
__device__ __forceinline__ void ldsm4t(unsigned& r0, unsigned& r1, unsigned& r2, unsigned& r3,
                                       unsigned addr) {
    asm volatile("ldmatrix.sync.aligned.m8n8.x4.trans.shared.b16 {%0,%1,%2,%3}, [%4];"
                 : "=r"(r0), "=r"(r1), "=r"(r2), "=r"(r3) : "r"(addr));
}
__device__ __forceinline__ void cpa16(unsigned dst, const void* src, bool p) {
    int sz = p ? 16 : 0;
    asm volatile("cp.async.cg.shared.global [%0], [%1], 16, %2;\n"
                 :: "r"(dst), "l"(src), "r"(sz));
}
__device__ __forceinline__ void cpa_commit() { asm volatile("cp.async.commit_group;\n"); }
template<int N> __device__ __forceinline__ void cpa_wait() {
    asm volatile("cp.async.wait_group %0;\n" :: "n"(N));
}

struct GemmJob {
    const __nv_bfloat16* A;
    const __nv_bfloat16* W;
    __nv_bfloat16* Out;
    float alpha;
    int out_rows_per_b;
    int out_off;
};

// =====================================================================
// Fused prologue: gn_img (blocks 0..511), gn_txt (512..1023),
// wconv fp32->bf16 (1024..1407). One launch -> natural overlap.
// =====================================================================
#define PREP_SMEM (NN * CPG * 4)

__global__ void __launch_bounds__(256, 3)
prep_kernel(const float* __restrict__ x,
            const float* __restrict__ qsc, const float* __restrict__ qbi,
            const float* __restrict__ ksc, const float* __restrict__ kbi,
            const float* __restrict__ te,
            const float* __restrict__ tsc, const float* __restrict__ tbi,
            const float* __restrict__ w0, const float* __restrict__ w1,
            const float* __restrict__ w2, const float* __restrict__ w3,
            const float* __restrict__ w4, const float* __restrict__ w5,
            __nv_bfloat16* __restrict__ oq, __nv_bfloat16* __restrict__ okv,
            __nv_bfloat16* __restrict__ ot, __nv_bfloat16* __restrict__ wout)
{
    extern __shared__ float xs[];
    int bid = blockIdx.x;
    int tid = threadIdx.x;

    if (bid < 512) {
        // ---------- GroupNorm image ----------
        int b = bid >> 5, g = bid & 31;
        const float* xb = x + (size_t)b * NN * CC + g * CPG;

        float s = 0.f, s2 = 0.f;
        for (int e = tid; e < NN * 4; e += 256) {
            int n = e >> 2, c4 = (e & 3) << 2;
            float4 v = *(const float4*)(xb + (size_t)n * CC + c4);
            *(float4*)(xs + n * CPG + c4) = v;
            s  += v.x + v.y + v.z + v.w;
            s2 += v.x * v.x + v.y * v.y + v.z * v.z + v.w * v.w;
        }
        #pragma unroll
        for (int o2 = 16; o2; o2 >>= 1) {
            s  += __shfl_xor_sync(0xffffffffu, s,  o2);
            s2 += __shfl_xor_sync(0xffffffffu, s2, o2);
        }
        __shared__ float sh[8], sh2[8];
        int w = tid >> 5, lane = tid & 31;
        if (lane == 0) { sh[w] = s; sh2[w] = s2; }
        __syncthreads();

        __shared__ float cq[2][CPG], ck[2][CPG];
        if (tid < CPG) {
            float ts = 0.f, ts2 = 0.f;
            #pragma unroll
            for (int i = 0; i < 8; i++) { ts += sh[i]; ts2 += sh2[i]; }
            const float cnt = (float)(NN * CPG);
            float mu  = ts / cnt;
            float var = ts2 / cnt - mu * mu;
            float inv = rsqrtf(var + EPSV);
            int c = g * CPG + tid;
            float aq = inv * qsc[c];
            cq[0][tid] = aq;  cq[1][tid] = qbi[c] - mu * aq;
            float ak = inv * ksc[c];
            ck[0][tid] = ak;  ck[1][tid] = kbi[c] - mu * ak;
        }
        __syncthreads();

        __nv_bfloat16* oqb  = oq  + (size_t)b * NN * CC + g * CPG;
        __nv_bfloat16* okvb = okv + (size_t)b * NN * CC + g * CPG;
        for (int e = tid; e < NN * 4; e += 256) {
            int n = e >> 2, c4 = (e & 3) << 2;
            float4 v = *(const float4*)(xs + n * CPG + c4);
            uint2 pq, pk;
            pq.x = pack_bf16x2(v.x * cq[0][c4+0] + cq[1][c4+0], v.y * cq[0][c4+1] + cq[1][c4+1]);
            pq.y = pack_bf16x2(v.z * cq[0][c4+2] + cq[1][c4+2], v.w * cq[0][c4+3] + cq[1][c4+3]);
            pk.x = pack_bf16x2(v.x * ck[0][c4+0] + ck[1][c4+0], v.y * ck[0][c4+1] + ck[1][c4+1]);
            pk.y = pack_bf16x2(v.z * ck[0][c4+2] + ck[1][c4+2], v.w * ck[0][c4+3] + ck[1][c4+3]);
            *(uint2*)(oqb  + (size_t)n * CC + c4) = pq;
            *(uint2*)(okvb + (size_t)n * CC + c4) = pk;
        }
    } else if (bid < 1024) {
        // ---------- GroupNorm text ----------
        int b = (bid - 512) >> 5, g = (bid - 512) & 31;
        const float* xb = te + (size_t)b * LL * CC + g * CPG;

        float s = 0.f, s2 = 0.f;
        for (int e = tid; e < LL * 4; e += 256) {
            int n = e >> 2, c4 = (e & 3) << 2;
            float4 v = *(const float4*)(xb + (size_t)n * CC + c4);
            s  += v.x + v.y + v.z + v.w;
            s2 += v.x * v.x + v.y * v.y + v.z * v.z + v.w * v.w;
        }
        #pragma unroll
        for (int o2 = 16; o2; o2 >>= 1) {
            s  += __shfl_xor_sync(0xffffffffu, s,  o2);
            s2 += __shfl_xor_sync(0xffffffffu, s2, o2);
        }
        __shared__ float th[8], th2[8];
        int w = tid >> 5, lane = tid & 31;
        if (lane == 0) { th[w] = s; th2[w] = s2; }
        __syncthreads();

        __shared__ float ct[2][CPG];
        if (tid < CPG) {
            float ts = 0.f, ts2 = 0.f;
            #pragma unroll
            for (int i = 0; i < 8; i++) { ts += th[i]; ts2 += th2[i]; }
            const float cnt = (float)(LL * CPG);
            float mu  = ts / cnt;
            float var = ts2 / cnt - mu * mu;
            float inv = rsqrtf(var + EPSV);
            int c = g * CPG + tid;
            float a = inv * tsc[c];
            ct[0][tid] = a;  ct[1][tid] = tbi[c] - mu * a;
        }
        __syncthreads();

        __nv_bfloat16* ob = ot + (size_t)b * LL * CC + g * CPG;
        for (int e = tid; e < LL * 4; e += 256) {
            int n = e >> 2, c4 = (e & 3) << 2;
            float4 v = *(const float4*)(xb + (size_t)n * CC + c4);
            uint2 p;
            p.x = pack_bf16x2(v.x * ct[0][c4+0] + ct[1][c4+0], v.y * ct[0][c4+1] + ct[1][c4+1]);
            p.y = pack_bf16x2(v.z * ct[0][c4+2] + ct[1][c4+2], v.w * ct[0][c4+3] + ct[1][c4+3]);
            *(uint2*)(ob + (size_t)n * CC + c4) = p;
        }
    } else {
        // ---------- weight conversion (6 x 512x512, fp32 -> bf16) ----------
        int gid = (bid - 1024) * 256 + tid;    // 0..98303, 4 float4s each
        #pragma unroll
        for (int i = 0; i < 4; i++) {
            int f4 = gid * 4 + i;              // 0..393215
            int mat = f4 >> 16;
            int idx = (f4 & 65535) << 2;
            const float* src = mat == 0 ? w0 : mat == 1 ? w1 : mat == 2 ? w2
                             : mat == 3 ? w3 : mat == 4 ? w4 : w5;
            float4 v = *(const float4*)(src + idx);
            uint2 p;
            p.x = pack_bf16x2(v.x, v.y);
            p.y = pack_bf16x2(v.z, v.w);
            *(uint2*)(wout + (size_t)mat * 262144 + idx) = p;
        }
    }
}

// =====================================================================
// BF16 GEMM core (3-stage cp.async pipeline, BK=64, block 128x128).
// =====================================================================
__device__ __forceinline__ void gemm_core(
    const __nv_bfloat16* __restrict__ A, const __nv_bfloat16* __restrict__ W,
    int M, int m0, int n0, unsigned aBase, unsigned bBase, float acc[4][4][4],
    int tid, int lane, int wm, int wn)
{
    auto loadTile = [&](int kt, int st) {
        int k0 = kt * 64;
        unsigned aD = aBase + st * 16384;
        unsigned bD = bBase + st * 16384;
        #pragma unroll
        for (int i = 0; i < 4; i++) {
            int f = tid + i * 256;
            int r = f >> 3, c = f & 7;
            bool ok = (m0 + r) < M;
            cpa16(aD + r * 128 + ((c ^ (r & 7)) << 4),
                  A + (size_t)(m0 + r) * 512 + k0 + c * 8, ok);
        }
        #pragma unroll
        for (int i = 0; i < 4; i++) {
            int f = tid + i * 256;
            int r = f >> 4, c = f & 15;
            cpa16(bD + r * 256 + ((c ^ (r & 7)) << 4),
                  W + (size_t)(k0 + r) * 512 + n0 + c * 8, true);
        }
    };
    loadTile(0, 0); cpa_commit();
    loadTile(1, 1); cpa_commit();

    int st = 0;
    for (int t = 0; t < 8; t++) {
        cpa_wait<1>();
        __syncthreads();
        if (t + 2 < 8) {
            int ns = st + 2; if (ns >= 3) ns -= 3;
            loadTile(t + 2, ns);
            cpa_commit();
        }
        unsigned aC = aBase + st * 16384;
        unsigned bC = bBase + st * 16384;
        #pragma unroll
        for (int kc = 0; kc < 8; kc += 2) {
            unsigned af[4][4];
            #pragma unroll
            for (int i = 0; i < 4; i++) {
                int r = wm + i * 16 + (lane & 15);
                int c = kc + (lane >> 4);
                ldsm4(af[i][0], af[i][1], af[i][2], af[i][3],
                      aC + r * 128 + ((c ^ (r & 7)) << 4));
            }
            unsigned bfr[4][2];
            #pragma unroll
            for (int grp = 0; grp < 2; grp++) {
                int r = kc * 8 + (lane & 15);
                int c = (wn >> 3) + 2 * grp + (lane >> 4);
                unsigned r0, r1, r2, r3;
                ldsm4t(r0, r1, r2, r3, bC + r * 256 + ((c ^ (r & 7)) << 4));
                bfr[grp*2][0] = r0;   bfr[grp*2][1] = r1;
                bfr[grp*2+1][0] = r2; bfr[grp*2+1][1] = r3;
            }
            #pragma unroll
            for (int i = 0; i < 4; i++)
                #pragma unroll
                for (int j = 0; j < 4; j++)
                    mma16(acc[i][j], af[i], bfr[j]);
        }
        if (++st == 3) st = 0;
    }
}

#define GEMM_SMEM 98304

// All 5 projection jobs in one launch. z<3: self (M=16384); z=3: cross jobs.
__global__ void __launch_bounds__(256, 2)
gemm_all(GemmJob j0, GemmJob j1, GemmJob j2, GemmJob j3, GemmJob j4)
{
    extern __shared__ char smc[];
    unsigned aBase = (unsigned)__cvta_generic_to_shared(smc);
    unsigned bBase = aBase + 3 * 16384;

    int z = blockIdx.z;
    GemmJob jb;
    int M, rows_per_b, m0;
    if (z < 3) {
        jb = z == 0 ? j0 : z == 1 ? j1 : j2;
        M = 16384; rows_per_b = 1024; m0 = blockIdx.x * 128;
    } else {
        int xx = blockIdx.x;
        if (xx >= 20) return;
        if (xx < 10) { jb = j3; }
        else         { jb = j4; xx -= 10; }
        M = 1232; rows_per_b = 77; m0 = xx * 128;
    }

    int tid = threadIdx.x, warp = tid >> 5, lane = tid & 31;
    int g = lane >> 2, tg = lane & 3;
    int wm = (warp >> 2) * 64, wn = (warp & 3) * 32;
    int n0 = blockIdx.y * 128;

    float acc[4][4][4] = {};
    gemm_core(jb.A, jb.W, M, m0, n0, aBase, bBase, acc, tid, lane, wm, wn);

    #pragma unroll
    for (int i = 0; i < 4; i++) {
        #pragma unroll
        for (int rs = 0; rs < 2; rs++) {
            int gm = m0 + wm + i * 16 + g + rs * 8;
            if (gm >= M) continue;
            int bbi = gm / rows_per_b;
            int rr  = gm - bbi * rows_per_b;
            size_t orow = (size_t)bbi * jb.out_rows_per_b + jb.out_off + rr;
            #pragma unroll
            for (int j = 0; j < 4; j++) {
                int col = n0 + wn + j * 8 + 2 * tg;
                *(unsigned*)(jb.Out + orow * 512 + col) =
                    pack_bf16x2(acc[i][j][rs * 2 + 0] * jb.alpha,
                                acc[i][j][rs * 2 + 1] * jb.alpha);
            }
        }
    }
}

// Final projection GEMM: fp32 out + residual.
__global__ void __launch_bounds__(256, 2)
gemm_final(const __nv_bfloat16* __restrict__ A, const __nv_bfloat16* __restrict__ W,
           float* __restrict__ Out, const float* __restrict__ Res)
{
    extern __shared__ char smc[];
    unsigned aBase = (unsigned)__cvta_generic_to_shared(smc);
    unsigned bBase = aBase + 3 * 16384;

    int tid = threadIdx.x, warp = tid >> 5, lane = tid & 31;
    int g = lane >> 2, tg = lane & 3;
    int wm = (warp >> 2) * 64, wn = (warp & 3) * 32;
    int m0 = blockIdx.x * 128, n0 = blockIdx.y * 128;

    float acc[4][4][4] = {};
    gemm_core(A, W, 16384, m0, n0, aBase, bBase, acc, tid, lane, wm, wn);

    #pragma unroll
    for (int i = 0; i < 4; i++) {
        #pragma unroll
        for (int rs = 0; rs < 2; rs++) {
            size_t orow = (size_t)(m0 + wm + i * 16 + g + rs * 8);
            #pragma unroll
            for (int j = 0; j < 4; j++) {
                int col = n0 + wn + j * 8 + 2 * tg;
                float2 rv = *(const float2*)(Res + orow * 512 + col);
                *(float2*)(Out + orow * 512 + col) =
                    make_float2(acc[i][j][rs * 2 + 0] + rv.x,
                                acc[i][j][rs * 2 + 1] + rv.y);
            }
        }
    }
}

// =====================================================================
// BF16 flash attention: 128-q-row blocks (8 warps x 16 rows),
// register-resident P, 3-stage KV ring (1 sync/tile), exp2 softmax.
// smem 64.8KB, 256 threads, 2 blocks/SM.
// =====================================================================
#define ATT_SMEM (65536 + 768)

__global__ void __launch_bounds__(256, 2)
attn_bf16(const int* __restrict__ tmask,
          const __nv_bfloat16* __restrict__ Qg,
          const __nv_bfloat16* __restrict__ Kg,
          const __nv_bfloat16* __restrict__ Vg,
          __nv_bfloat16* __restrict__ Og)
{
    extern __shared__ char smc[];
    unsigned qB  = (unsigned)__cvta_generic_to_shared(smc);  // [128][128B]
    unsigned kvB = qB + 16384;                               // [3 stages][K 8K | V 8K]
    float* kmaskf = (float*)(smc + 65536);                   // [3][64]

    int qt = blockIdx.x, h = blockIdx.y, b = blockIdx.z;
    int tid = threadIdx.x, warp = tid >> 5, lane = tid & 31;
    int g = lane >> 2, tg = lane & 3;
    int wm = warp * 16;

    const __nv_bfloat16* qb = Qg + (size_t)(b * NN + qt * 128) * 512 + h * 64;
    const __nv_bfloat16* kb = Kg + (size_t)b * KVLEN * 512 + h * 64;
    const __nv_bfloat16* vb = Vg + (size_t)b * KVLEN * 512 + h * 64;
    const int* tm = tmask + b * LL;

    // Q load folded into first stage's group
    #pragma unroll
    for (int i = 0; i < 4; i++) {
        int f = tid + i * 256;
        int r = f >> 3, c = f & 7;
        cpa16(qB + r * 128 + ((c ^ (r & 7)) << 4), qb + (size_t)r * 512 + c * 8, true);
    }

    auto loadKV = [&](int t, int stg) {
        int kv0 = t * 64;
        unsigned kD = kvB + stg * 16384, vD = kD + 8192;
        #pragma unroll
        for (int i = 0; i < 2; i++) {
            int f = tid + i * 256;
            int r = f >> 3, c = f & 7;
            int kg = kv0 + r;
            bool ok = kg < KVLEN;
            cpa16(kD + r * 128 + ((c ^ (r & 7)) << 4), kb + (size_t)kg * 512 + c * 8, ok);
            cpa16(vD + r * 128 + ((c ^ (r & 7)) << 4), vb + (size_t)kg * 512 + c * 8, ok);
        }
        if (kv0 + 64 > NN && tid < 64) {
            int kg = kv0 + tid;
            float m = 0.f;
            if (kg >= KVLEN) m = NEGV * LOG2E;
            else if (kg >= NN && tm[kg - NN] == 0) m = NEGV * LOG2E;
            kmaskf[stg * 64 + tid] = m;
        }
    };
    loadKV(0, 0); cpa_commit();
    loadKV(1, 1); cpa_commit();

    float m_i[2] = {-1e30f, -1e30f}, l_i[2] = {0.f, 0.f}, o[8][4] = {};

    int st = 0;
    for (int t = 0; t < 18; t++) {
        if (t < 17) cpa_wait<1>(); else cpa_wait<0>();
        __syncthreads();
        if (t + 2 < 18) {
            int ns = st + 2; if (ns >= 3) ns -= 3;
            loadKV(t + 2, ns);
            cpa_commit();
        }

        unsigned kC = kvB + st * 16384;
        unsigned vC = kC + 8192;
        const float* km = kmaskf + st * 64;
        bool masked = (t * 64 + 64 > NN);

        // ---- S = Q K^T ----
        float s[8][4] = {};
        #pragma unroll
        for (int kc = 0; kc < 8; kc += 2) {
            unsigned aq[4];
            {
                int r = wm + (lane & 15);
                int c = kc + (lane >> 4);
                ldsm4(aq[0], aq[1], aq[2], aq[3], qB + r * 128 + ((c ^ (r & 7)) << 4));
            }
            #pragma unroll
            for (int grp = 0; grp < 4; grp++) {
                int r = grp * 16 + (lane & 7) + ((lane >> 4) << 3);
                int c = kc + ((lane >> 3) & 1);
                unsigned r0, r1, r2, r3;
                ldsm4(r0, r1, r2, r3, kC + r * 128 + ((c ^ (r & 7)) << 4));
                unsigned bk0[2] = {r0, r1}, bk1[2] = {r2, r3};
                mma16(s[grp * 2], aq, bk0);
                mma16(s[grp * 2 + 1], aq, bk1);
            }
        }

        // ---- mask + online softmax (exp2) ----
        if (masked) {
            #pragma unroll
            for (int j = 0; j < 8; j++) {
                float k0v = km[j * 8 + 2 * tg], k1v = km[j * 8 + 2 * tg + 1];
                s[j][0] += k0v; s[j][1] += k1v;
                s[j][2] += k0v; s[j][3] += k1v;
            }
        }
        float mx0 = -1e30f, mx1 = -1e30f;
        #pragma unroll
        for (int j = 0; j < 8; j++) {
            mx0 = fmaxf(mx0, fmaxf(s[j][0], s[j][1]));
            mx1 = fmaxf(mx1, fmaxf(s[j][2], s[j][3]));
        }
        mx0 = fmaxf(mx0, __shfl_xor_sync(0xffffffffu, mx0, 1));
        mx0 = fmaxf(mx0, __shfl_xor_sync(0xffffffffu, mx0, 2));
        mx1 = fmaxf(mx1, __shfl_xor_sync(0xffffffffu, mx1, 1));
        mx1 = fmaxf(mx1, __shfl_xor_sync(0xffffffffu, mx1, 2));
        float mn0 = fmaxf(m_i[0], mx0), mn1 = fmaxf(m_i[1], mx1);
        float al0 = ex2f(m_i[0] - mn0), al1 = ex2f(m_i[1] - mn1);
        m_i[0] = mn0; m_i[1] = mn1;

        unsigned pp[4][4];
        float sum0 = 0.f, sum1 = 0.f;
        #pragma unroll
        for (int kc2 = 0; kc2 < 4; kc2++) {
            float p00 = ex2f(s[2*kc2][0]   - mn0);
            float p01 = ex2f(s[2*kc2][1]   - mn0);
            float p02 = ex2f(s[2*kc2][2]   - mn1);
            float p03 = ex2f(s[2*kc2][3]   - mn1);
            float p10 = ex2f(s[2*kc2+1][0] - mn0);
            float p11 = ex2f(s[2*kc2+1][1] - mn0);
            float p12 = ex2f(s[2*kc2+1][2] - mn1);
            float p13 = ex2f(s[2*kc2+1][3] - mn1);
            sum0 += p00 + p01 + p10 + p11;
            sum1 += p02 + p03 + p12 + p13;
            pp[kc2][0] = pack_bf16x2(p00, p01);
            pp[kc2][1] = pack_bf16x2(p02, p03);
            pp[kc2][2] = pack_bf16x2(p10, p11);
            pp[kc2][3] = pack_bf16x2(p12, p13);
        }
        sum0 += __shfl_xor_sync(0xffffffffu, sum0, 1);
        sum0 += __shfl_xor_sync(0xffffffffu, sum0, 2);
        sum1 += __shfl_xor_sync(0xffffffffu, sum1, 1);
        sum1 += __shfl_xor_sync(0xffffffffu, sum1, 2);
        l_i[0] = l_i[0] * al0 + sum0;
        l_i[1] = l_i[1] * al1 + sum1;
        #pragma unroll
        for (int j = 0; j < 8; j++) {
            o[j][0] *= al0; o[j][1] *= al0;
            o[j][2] *= al1; o[j][3] *= al1;
        }

        // ---- O += P V (P in registers) ----
        #pragma unroll
        for (int kc2 = 0; kc2 < 4; kc2++) {
            #pragma unroll
            for (int grp = 0; grp < 4; grp++) {
                int r = kc2 * 16 + (lane & 15);
                int c = grp * 2 + (lane >> 4);
                unsigned r0, r1, r2, r3;
                ldsm4t(r0, r1, r2, r3, vC + r * 128 + ((c ^ (r & 7)) << 4));
                unsigned bv0[2] = {r0, r1}, bv1[2] = {r2, r3};
                mma16(o[grp * 2], pp[kc2], bv0);
                mma16(o[grp * 2 + 1], pp[kc2], bv1);
            }
        }
        if (++st == 3) st = 0;
    }

    __nv_bfloat16* ob = Og + (size_t)(b * NN + qt * 128) * 512 + h * 64;
    #pragma unroll
    for (int rs = 0; rs < 2; rs++) {
        int r = wm + g + rs * 8;
        float inv = 1.f / l_i[rs];
        #pragma unroll
        for (int j = 0; j < 8; j++) {
            int col = j * 8 + 2 * tg;
            *(unsigned*)(ob + (size_t)r * 512 + col) =
                pack_bf16x2(o[j][rs * 2 + 0] * inv, o[j][rs * 2 + 1] * inv);
        }
    }
}

// =====================================================================
// launch
// =====================================================================
extern "C" void kernel_launch(void* const* d_in, const int* in_sizes, int n_in,
                              void* d_out, int out_size)
{
    const float* x    = (const float*)d_in[0];
    const float* te   = (const float*)d_in[1];
    const int*   tmk  = (const int*)  d_in[2];
    const float* gqs  = (const float*)d_in[3];
    const float* gqb  = (const float*)d_in[4];
    const float* gks  = (const float*)d_in[5];
    const float* gkb  = (const float*)d_in[6];
    const float* gts  = (const float*)d_in[7];
    const float* gtb  = (const float*)d_in[8];
    const float* Wq   = (const float*)d_in[9];
    const float* Wks  = (const float*)d_in[10];
    const float* Wvs  = (const float*)d_in[11];
    const float* Wkc  = (const float*)d_in[12];
    const float* Wvc  = (const float*)d_in[13];
    const float* Wout = (const float*)d_in[14];
    float* out = (float*)d_out;

    float* scratch = nullptr;
    cudaGetSymbolAddress((void**)&scratch, g_scratch);
    __nv_bfloat16* bs = (__nv_bfloat16*)scratch;
    __nv_bfloat16* XQ   = bs + BOFF_XQ;
    __nv_bfloat16* XKV  = bs + BOFF_XKV;
    __nv_bfloat16* Tb   = bs + BOFF_T;
    __nv_bfloat16* Qb   = bs + BOFF_Q;
    __nv_bfloat16* Kb   = bs + BOFF_K;
    __nv_bfloat16* Vb   = bs + BOFF_V;
    __nv_bfloat16* ATTb = bs + BOFF_ATT;
    __nv_bfloat16* Wb   = bs + BOFF_W;

    cudaFuncSetAttribute(prep_kernel, cudaFuncAttributeMaxDynamicSharedMemorySize, PREP_SMEM);
    cudaFuncSetAttribute(gemm_all, cudaFuncAttributeMaxDynamicSharedMemorySize, GEMM_SMEM);
    cudaFuncSetAttribute(gemm_final, cudaFuncAttributeMaxDynamicSharedMemorySize, GEMM_SMEM);
    cudaFuncSetAttribute(attn_bf16, cudaFuncAttributeMaxDynamicSharedMemorySize, ATT_SMEM);

    prep_kernel<<<1408, 256, PREP_SMEM>>>(x, gqs, gqb, gks, gkb,
                                          te, gts, gtb,
                                          Wq, Wks, Wvs, Wkc, Wvc, Wout,
                                          XQ, XKV, Tb, Wb);

    __nv_bfloat16* WqB  = Wb;
    __nv_bfloat16* WksB = Wb + 262144;
    __nv_bfloat16* WvsB = Wb + 2 * 262144;
    __nv_bfloat16* WkcB = Wb + 3 * 262144;
    __nv_bfloat16* WvcB = Wb + 4 * 262144;
    __nv_bfloat16* WoB  = Wb + 5 * 262144;

    // All 5 projections in one launch (Q folds 1/sqrt(64)*log2(e)).
    GemmJob jq  = { XQ,  WqB,  Qb, 0.125f * LOG2E, 1024,  0 };
    GemmJob jk  = { XKV, WksB, Kb, 1.f,            KVLEN, 0 };
    GemmJob jv  = { XKV, WvsB, Vb, 1.f,            KVLEN, 0 };
    GemmJob jkc = { Tb,  WkcB, Kb, 1.f,            KVLEN, 1024 };
    GemmJob jvc = { Tb,  WvcB, Vb, 1.f,            KVLEN, 1024 };
    gemm_all<<<dim3(128, 4, 4), 256, GEMM_SMEM>>>(jq, jk, jv, jkc, jvc);

    attn_bf16<<<dim3(8, NHH, BB), 256, ATT_SMEM>>>(tmk, Qb, Kb, Vb, ATTb);

    gemm_final<<<dim3(128, 4), 256, GEMM_SMEM>>>(ATTb, WoB, out, x);
}